// round 5
// baseline (speedup 1.0000x reference)
#include <cuda_runtime.h>

#define D_MODEL  1024
#define N_HEADS  16
#define HEAD_DIM 64
#define BATCH    2
#define SEQ      2048
#define LMEM     8
#define M_TOT    (BATCH * SEQ)            // 4096
#define OUT_ELEMS (M_TOT * D_MODEL)       // 4194304
#define KV_ELEMS  (BATCH * N_HEADS * SEQ * HEAD_DIM)  // 4194304 each

// scratch (no cudaMalloc allowed). NOTE: these symbols must NEVER be passed
// directly as kernel arguments from host code — host sees a stub address
// (and GB300 ATS makes the bad dereference silently read host memory).
// Use cudaGetSymbolAddress on the host, or reference them in device code.
__device__ float g_q[M_TOT * D_MODEL];       // 16.8 MB
__device__ float g_ctx[M_TOT * D_MODEL];     // 16.8 MB

// ---------------------------------------------------------------------------
// Tiled fp32 GEMM: C = A(MxK) @ B(KxN) + bias(N)
// MODE 0: QKV — n<1024 -> g_q (device symbol); n in [1024,3072) -> C=kvbuf
//         (split-head layout)
// MODE 1: plain row-major store to C
// ---------------------------------------------------------------------------
#define BM 128
#define BN 128
#define BK 16

template <int MODE>
__global__ __launch_bounds__(256)
void sgemm_kernel(const float* __restrict__ A,
                  const float* __restrict__ B,
                  const float* __restrict__ bias,
                  float* __restrict__ C,        // MODE1: out ; MODE0: kvbuf
                  int M, int N, int K)
{
    __shared__ float As[BK][BM + 4];
    __shared__ float Bs[BK][BN];

    const int tid = threadIdx.x;            // 0..255
    const int row0 = blockIdx.y * BM;
    const int col0 = blockIdx.x * BN;
    const int tx = tid & 15;
    const int ty = tid >> 4;

    float acc[8][8];
#pragma unroll
    for (int i = 0; i < 8; i++)
#pragma unroll
        for (int j = 0; j < 8; j++) acc[i][j] = 0.0f;

    for (int kt = 0; kt < K; kt += BK) {
#pragma unroll
        for (int i = 0; i < 2; i++) {
            int e  = tid + i * 256;          // 0..511
            int r  = e >> 2;                 // 0..127
            int c4 = (e & 3) * 4;            // 0,4,8,12
            float4 v = *(const float4*)(A + (size_t)(row0 + r) * K + kt + c4);
            As[c4 + 0][r] = v.x;
            As[c4 + 1][r] = v.y;
            As[c4 + 2][r] = v.z;
            As[c4 + 3][r] = v.w;
        }
#pragma unroll
        for (int i = 0; i < 2; i++) {
            int e  = tid + i * 256;
            int r  = e >> 5;                 // 0..15
            int c4 = (e & 31) * 4;           // 0..124
            *(float4*)&Bs[r][c4] =
                *(const float4*)(B + (size_t)(kt + r) * N + col0 + c4);
        }
        __syncthreads();

#pragma unroll
        for (int k = 0; k < BK; k++) {
            float a[8], bb[8];
            *(float4*)&a[0]  = *(float4*)&As[k][ty * 8];
            *(float4*)&a[4]  = *(float4*)&As[k][ty * 8 + 4];
            *(float4*)&bb[0] = *(float4*)&Bs[k][tx * 8];
            *(float4*)&bb[4] = *(float4*)&Bs[k][tx * 8 + 4];
#pragma unroll
            for (int i = 0; i < 8; i++)
#pragma unroll
                for (int j = 0; j < 8; j++)
                    acc[i][j] += a[i] * bb[j];
        }
        __syncthreads();
    }

#pragma unroll
    for (int i = 0; i < 8; i++) {
        int m = row0 + ty * 8 + i;
#pragma unroll
        for (int j = 0; j < 8; j++) {
            int n = col0 + tx * 8 + j;
            float val = acc[i][j] + bias[n];
            if (MODE == 1) {
                C[(size_t)m * N + n] = val;
            } else {
                int b = m >> 11;
                int s = m & 2047;
                if (n < D_MODEL) {
                    g_q[(size_t)m * D_MODEL + n] = val;   // device-side symbol: OK
                } else {
                    int c = n - D_MODEL;
                    int which = c >> 10;     // 0 = k, 1 = v
                    c &= 1023;
                    int h = c >> 6;
                    int d = c & 63;
                    size_t off = (size_t)which * KV_ELEMS
                               + (((size_t)(b * N_HEADS + h) * SEQ + s) * HEAD_DIM + d);
                    C[off] = val;
                }
            }
        }
    }
}

// ---------------------------------------------------------------------------
// Attention: one block = (b, h, 128-query tile); one query per thread.
// ---------------------------------------------------------------------------
__global__ __launch_bounds__(128)
void attn_kernel(const float* __restrict__ kvbuf,
                 const float* __restrict__ pk,
                 const float* __restrict__ pv)
{
    __shared__ float sk[64][64];
    __shared__ float sv[64][64];

    const int tid = threadIdx.x;             // 0..127
    const int qt  = blockIdx.x;              // 0..15
    const int bh  = blockIdx.y;              // 0..31
    const int qrow = qt * 128 + tid;

    const float scale = 0.125f;

    float4 q[16];
    {
        const int b = bh >> 4, h = bh & 15;
        const float* qp = g_q + ((size_t)(b * SEQ + qrow) * D_MODEL + h * HEAD_DIM);
#pragma unroll
        for (int i = 0; i < 16; i++) q[i] = *(const float4*)(qp + 4 * i);
    }

    float4 acc[16];
#pragma unroll
    for (int i = 0; i < 16; i++) acc[i] = make_float4(0.f, 0.f, 0.f, 0.f);
    float mval = -1e30f;
    float lsum = 0.0f;

    // ---- 8 per-token memory keys seed the online softmax ----
    {
        const size_t mbase = ((size_t)bh * SEQ + qrow) * (LMEM * HEAD_DIM);
        const float* pkp = pk + mbase;
        const float* pvp = pv + mbase;
        float ms[LMEM];
#pragma unroll
        for (int l = 0; l < LMEM; l++) {
            float dot = 0.0f;
#pragma unroll
            for (int i = 0; i < 16; i++) {
                float4 kk = *(const float4*)(pkp + l * HEAD_DIM + 4 * i);
                dot += q[i].x * kk.x + q[i].y * kk.y + q[i].z * kk.z + q[i].w * kk.w;
            }
            ms[l] = dot * scale;
            mval = fmaxf(mval, ms[l]);
        }
#pragma unroll
        for (int l = 0; l < LMEM; l++) {
            float p = __expf(ms[l] - mval);
            lsum += p;
#pragma unroll
            for (int i = 0; i < 16; i++) {
                float4 vv = *(const float4*)(pvp + l * HEAD_DIM + 4 * i);
                acc[i].x += p * vv.x;
                acc[i].y += p * vv.y;
                acc[i].z += p * vv.z;
                acc[i].w += p * vv.w;
            }
        }
    }

    // ---- causal token keys ----
    const float* kb = kvbuf + (size_t)bh * SEQ * HEAD_DIM;
    const float* vb = kvbuf + (size_t)KV_ELEMS + (size_t)bh * SEQ * HEAD_DIM;
    const int nkeys = qt * 128 + 128;

    for (int kt0 = 0; kt0 < nkeys; kt0 += 64) {
#pragma unroll
        for (int i = 0; i < 8; i++) {
            int e = tid + i * 128;
            ((float4*)sk)[e] = ((const float4*)(kb + (size_t)kt0 * HEAD_DIM))[e];
            ((float4*)sv)[e] = ((const float4*)(vb + (size_t)kt0 * HEAD_DIM))[e];
        }
        __syncthreads();

#pragma unroll 1
        for (int c0 = 0; c0 < 64; c0 += 16) {
            float s[16];
            float cmax = -1e30f;
#pragma unroll
            for (int j = 0; j < 16; j++) {
                int kj = kt0 + c0 + j;
                float dot = 0.0f;
                const float4* kr = (const float4*)&sk[c0 + j][0];
#pragma unroll
                for (int i = 0; i < 16; i++) {
                    float4 kk = kr[i];
                    dot += q[i].x * kk.x + q[i].y * kk.y + q[i].z * kk.z + q[i].w * kk.w;
                }
                s[j] = (kj <= qrow) ? dot * scale : -1e30f;
                cmax = fmaxf(cmax, s[j]);
            }
            float newm = fmaxf(mval, cmax);
            float corr = __expf(mval - newm);
            mval = newm;
            lsum *= corr;
#pragma unroll
            for (int i = 0; i < 16; i++) {
                acc[i].x *= corr; acc[i].y *= corr;
                acc[i].z *= corr; acc[i].w *= corr;
            }
#pragma unroll
            for (int j = 0; j < 16; j++) {
                float p = __expf(s[j] - mval);
                lsum += p;
                const float4* vr = (const float4*)&sv[c0 + j][0];
#pragma unroll
                for (int i = 0; i < 16; i++) {
                    float4 vv = vr[i];
                    acc[i].x += p * vv.x;
                    acc[i].y += p * vv.y;
                    acc[i].z += p * vv.z;
                    acc[i].w += p * vv.w;
                }
            }
        }
        __syncthreads();
    }

    {
        const int b = bh >> 4, h = bh & 15;
        float inv = 1.0f / lsum;
        float* cp = g_ctx + ((size_t)(b * SEQ + qrow) * D_MODEL + h * HEAD_DIM);
#pragma unroll
        for (int i = 0; i < 16; i++) {
            float4 o;
            o.x = acc[i].x * inv;
            o.y = acc[i].y * inv;
            o.z = acc[i].z * inv;
            o.w = acc[i].w * inv;
            *(float4*)(cp + 4 * i) = o;   // device-side symbol: OK
        }
    }
}

// ---------------------------------------------------------------------------
extern "C" void kernel_launch(void* const* d_in, const int* in_sizes, int n_in,
                              void* d_out, int out_size)
{
    // Identify inputs by element count; fall back to positional.
    const float* x = 0; const float* pk = 0; const float* pv = 0;
    const float* W_qkv = 0; const float* b_qkv = 0;
    const float* W_out = 0; const float* b_out = 0;
    for (int i = 0; i < n_in; i++) {
        const float* p = (const float*)d_in[i];
        switch (in_sizes[i]) {
            case 4194304:  x = p;      break;
            case 33554432: if (!pk) pk = p; else pv = p; break;
            case 3145728:  W_qkv = p;  break;
            case 3072:     b_qkv = p;  break;
            case 1048576:  W_out = p;  break;
            case 1024:     b_out = p;  break;
            default: break;
        }
    }
    if (!(x && pk && pv && W_qkv && b_qkv && W_out && b_out)) {
        if (n_in < 7) return;
        x     = (const float*)d_in[0];
        pk    = (const float*)d_in[1];
        pv    = (const float*)d_in[2];
        W_qkv = (const float*)d_in[3];
        b_qkv = (const float*)d_in[4];
        W_out = (const float*)d_in[5];
        b_out = (const float*)d_in[6];
    }

    float* out = (float*)d_out;

    // THE FIX: real device addresses of __device__ scratch symbols.
    // (cudaGetSymbolAddress is a host query — no allocation, capture-safe.)
    static float* s_ctx = nullptr;
    if (!s_ctx) {
        void* p = 0;
        cudaGetSymbolAddress(&p, g_ctx);
        s_ctx = (float*)p;
    }

    // k/v destination directly inside d_out ([out | k | v] element layout).
    float* kvbuf = out + OUT_ELEMS;

    // 1) QKV GEMM: (4096 x 1024) @ (1024 x 3072) -> q (g_q) / k,v (d_out)
    {
        dim3 grid(3 * D_MODEL / BN, M_TOT / BM);   // (24, 32)
        sgemm_kernel<0><<<grid, 256>>>(x, W_qkv, b_qkv, kvbuf,
                                       M_TOT, 3 * D_MODEL, D_MODEL);
    }

    // 2) attention (reads g_q + kvbuf, writes g_ctx)
    {
        dim3 grid(SEQ / 128, BATCH * N_HEADS);     // (16, 32)
        attn_kernel<<<grid, 128>>>(kvbuf, pk, pv);
    }

    // 3) output GEMM: (4096 x 1024) @ (1024 x 1024) + bias -> out
    {
        dim3 grid(D_MODEL / BN, M_TOT / BM);       // (8, 32)
        sgemm_kernel<1><<<grid, 256>>>(s_ctx, W_out, b_out, out,
                                       M_TOT, D_MODEL, D_MODEL);
    }
}

// round 6
// speedup vs baseline: 1.0376x; 1.0376x over previous
#include <cuda_runtime.h>

#define D_MODEL  1024
#define N_HEADS  16
#define HEAD_DIM 64
#define BATCH    2
#define SEQ      2048
#define LMEM     8
#define M_TOT    (BATCH * SEQ)            // 4096
#define OUT_ELEMS (M_TOT * D_MODEL)       // 4194304
#define KV_ELEMS  (BATCH * N_HEADS * SEQ * HEAD_DIM)  // 4194304 each

typedef unsigned long long ull;

// scratch (no cudaMalloc allowed). NEVER pass these directly as kernel args
// from host code (host stub address + GB300 ATS = silent host reads).
__device__ float g_q[M_TOT * D_MODEL];       // 16.8 MB
__device__ float g_ctx[M_TOT * D_MODEL];     // 16.8 MB

// ---- packed fp32x2 helpers (sm_100+ PTX; 2 FMAs per issue) ----------------
__device__ __forceinline__ ull ffma2(ull a, ull b, ull c) {   // a*b + c (per lane)
    ull d;
    asm("fma.rn.f32x2 %0, %1, %2, %3;" : "=l"(d) : "l"(a), "l"(b), "l"(c));
    return d;
}
__device__ __forceinline__ ull fmul2(ull a, ull b) {
    ull d;
    asm("mul.rn.f32x2 %0, %1, %2;" : "=l"(d) : "l"(a), "l"(b));
    return d;
}
__device__ __forceinline__ ull pack2(float lo, float hi) {
    ull r;
    asm("mov.b64 %0, {%1, %2};" : "=l"(r) : "f"(lo), "f"(hi));
    return r;
}
__device__ __forceinline__ void unpack2(ull v, float& lo, float& hi) {
    asm("mov.b64 {%0, %1}, %2;" : "=f"(lo), "=f"(hi) : "l"(v));
}

// ---------------------------------------------------------------------------
// Tiled fp32 GEMM (FFMA2 mainloop): C = A(MxK) @ B(KxN) + bias(N)
// MODE 0: QKV — n<1024 -> g_q; n in [1024,3072) -> C=kvbuf (split-head)
// MODE 1: plain row-major store to C
// ---------------------------------------------------------------------------
#define BM 128
#define BN 128
#define BK 16

template <int MODE>
__global__ __launch_bounds__(256)
void sgemm_kernel(const float* __restrict__ A,
                  const float* __restrict__ B,
                  const float* __restrict__ bias,
                  float* __restrict__ C,
                  int M, int N, int K)
{
    __shared__ float As[BK][BM + 4];
    __shared__ float Bs[BK][BN];

    const int tid = threadIdx.x;            // 0..255
    const int row0 = blockIdx.y * BM;
    const int col0 = blockIdx.x * BN;
    const int tx = tid & 15;
    const int ty = tid >> 4;

    // acc2[i][j] = packed pair (row i, cols 2j / 2j+1)
    ull acc2[8][4];
#pragma unroll
    for (int i = 0; i < 8; i++)
#pragma unroll
        for (int j = 0; j < 4; j++) acc2[i][j] = 0ull;   // {0.0f, 0.0f}

    for (int kt = 0; kt < K; kt += BK) {
#pragma unroll
        for (int i = 0; i < 2; i++) {
            int e  = tid + i * 256;          // 0..511
            int r  = e >> 2;                 // 0..127
            int c4 = (e & 3) * 4;            // 0,4,8,12
            float4 v = *(const float4*)(A + (size_t)(row0 + r) * K + kt + c4);
            As[c4 + 0][r] = v.x;
            As[c4 + 1][r] = v.y;
            As[c4 + 2][r] = v.z;
            As[c4 + 3][r] = v.w;
        }
#pragma unroll
        for (int i = 0; i < 2; i++) {
            int e  = tid + i * 256;
            int r  = e >> 5;                 // 0..15
            int c4 = (e & 31) * 4;           // 0..124
            *(float4*)&Bs[r][c4] =
                *(const float4*)(B + (size_t)(kt + r) * N + col0 + c4);
        }
        __syncthreads();

#pragma unroll
        for (int k = 0; k < BK; k++) {
            float a[8];
            *(float4*)&a[0] = *(float4*)&As[k][ty * 8];
            *(float4*)&a[4] = *(float4*)&As[k][ty * 8 + 4];

            ulonglong2 bb0 = *(const ulonglong2*)&Bs[k][tx * 8];
            ulonglong2 bb1 = *(const ulonglong2*)&Bs[k][tx * 8 + 4];
            ull b2[4] = { bb0.x, bb0.y, bb1.x, bb1.y };

            ull a2[8];
#pragma unroll
            for (int i = 0; i < 8; i++) a2[i] = pack2(a[i], a[i]);

#pragma unroll
            for (int i = 0; i < 8; i++)
#pragma unroll
                for (int j = 0; j < 4; j++)
                    acc2[i][j] = ffma2(a2[i], b2[j], acc2[i][j]);
        }
        __syncthreads();
    }

    // epilogue
#pragma unroll
    for (int i = 0; i < 8; i++) {
        int m = row0 + ty * 8 + i;
#pragma unroll
        for (int j = 0; j < 4; j++) {
            float v0, v1;
            unpack2(acc2[i][j], v0, v1);
#pragma unroll
            for (int t = 0; t < 2; t++) {
                int n = col0 + tx * 8 + 2 * j + t;
                float val = (t ? v1 : v0) + bias[n];
                if (MODE == 1) {
                    C[(size_t)m * N + n] = val;
                } else {
                    int b = m >> 11;
                    int s = m & 2047;
                    if (n < D_MODEL) {
                        g_q[(size_t)m * D_MODEL + n] = val;
                    } else {
                        int c = n - D_MODEL;
                        int which = c >> 10;     // 0 = k, 1 = v
                        c &= 1023;
                        int h = c >> 6;
                        int d = c & 63;
                        size_t off = (size_t)which * KV_ELEMS
                                   + (((size_t)(b * N_HEADS + h) * SEQ + s) * HEAD_DIM + d);
                        C[off] = val;
                    }
                }
            }
        }
    }
}

// ---------------------------------------------------------------------------
// Attention: one block = (b, h, 128-query tile); one query per thread.
// All inner products / accumulations in packed f32x2.
// ---------------------------------------------------------------------------
__global__ __launch_bounds__(128)
void attn_kernel(const float* __restrict__ kvbuf,
                 const float* __restrict__ pk,
                 const float* __restrict__ pv)
{
    __shared__ float sk[64][64];
    __shared__ float sv[64][64];

    const int tid = threadIdx.x;             // 0..127
    const int qt  = blockIdx.x;              // 0..15
    const int bh  = blockIdx.y;              // 0..31
    const int qrow = qt * 128 + tid;

    const float scale = 0.125f;

    // q in packed pairs: q2[2i], q2[2i+1] = dims 4i..4i+3
    ull q2[32];
    {
        const int b = bh >> 4, h = bh & 15;
        const ulonglong2* qp = (const ulonglong2*)
            (g_q + ((size_t)(b * SEQ + qrow) * D_MODEL + h * HEAD_DIM));
#pragma unroll
        for (int i = 0; i < 16; i++) {
            ulonglong2 t = qp[i];
            q2[2 * i] = t.x;
            q2[2 * i + 1] = t.y;
        }
    }

    ull acc2[32];
#pragma unroll
    for (int i = 0; i < 32; i++) acc2[i] = 0ull;
    float mval = -1e30f;
    float lsum = 0.0f;

    // ---- 8 per-token memory keys seed the online softmax ----
    {
        const size_t mbase = ((size_t)bh * SEQ + qrow) * (LMEM * HEAD_DIM);
        const ulonglong2* pkp = (const ulonglong2*)(pk + mbase);
        const ulonglong2* pvp = (const ulonglong2*)(pv + mbase);
        float ms[LMEM];
#pragma unroll
        for (int l = 0; l < LMEM; l++) {
            ull dot2 = 0ull;
#pragma unroll
            for (int i = 0; i < 16; i++) {
                ulonglong2 kk = pkp[l * 16 + i];
                dot2 = ffma2(q2[2 * i], kk.x, dot2);
                dot2 = ffma2(q2[2 * i + 1], kk.y, dot2);
            }
            float dlo, dhi;
            unpack2(dot2, dlo, dhi);
            ms[l] = (dlo + dhi) * scale;
            mval = fmaxf(mval, ms[l]);
        }
#pragma unroll
        for (int l = 0; l < LMEM; l++) {
            float p = __expf(ms[l] - mval);
            lsum += p;
            ull p2 = pack2(p, p);
#pragma unroll
            for (int i = 0; i < 16; i++) {
                ulonglong2 vv = pvp[l * 16 + i];
                acc2[2 * i]     = ffma2(p2, vv.x, acc2[2 * i]);
                acc2[2 * i + 1] = ffma2(p2, vv.y, acc2[2 * i + 1]);
            }
        }
    }

    // ---- causal token keys ----
    const float* kb = kvbuf + (size_t)bh * SEQ * HEAD_DIM;
    const float* vb = kvbuf + (size_t)KV_ELEMS + (size_t)bh * SEQ * HEAD_DIM;
    const int nkeys = qt * 128 + 128;

    for (int kt0 = 0; kt0 < nkeys; kt0 += 64) {
#pragma unroll
        for (int i = 0; i < 8; i++) {
            int e = tid + i * 128;
            ((float4*)sk)[e] = ((const float4*)(kb + (size_t)kt0 * HEAD_DIM))[e];
            ((float4*)sv)[e] = ((const float4*)(vb + (size_t)kt0 * HEAD_DIM))[e];
        }
        __syncthreads();

#pragma unroll 1
        for (int c0 = 0; c0 < 64; c0 += 16) {
            float s[16];
            float cmax = -1e30f;
#pragma unroll
            for (int j = 0; j < 16; j++) {
                int kj = kt0 + c0 + j;
                const ulonglong2* kr = (const ulonglong2*)&sk[c0 + j][0];
                ull dot2 = 0ull;
#pragma unroll
                for (int i = 0; i < 16; i++) {
                    ulonglong2 kk = kr[i];
                    dot2 = ffma2(q2[2 * i], kk.x, dot2);
                    dot2 = ffma2(q2[2 * i + 1], kk.y, dot2);
                }
                float dlo, dhi;
                unpack2(dot2, dlo, dhi);
                s[j] = (kj <= qrow) ? (dlo + dhi) * scale : -1e30f;
                cmax = fmaxf(cmax, s[j]);
            }
            float newm = fmaxf(mval, cmax);
            float corr = __expf(mval - newm);
            mval = newm;
            lsum *= corr;
            ull corr2 = pack2(corr, corr);
#pragma unroll
            for (int i = 0; i < 32; i++) acc2[i] = fmul2(acc2[i], corr2);
#pragma unroll
            for (int j = 0; j < 16; j++) {
                float p = __expf(s[j] - mval);
                lsum += p;
                ull p2 = pack2(p, p);
                const ulonglong2* vr = (const ulonglong2*)&sv[c0 + j][0];
#pragma unroll
                for (int i = 0; i < 16; i++) {
                    ulonglong2 vv = vr[i];
                    acc2[2 * i]     = ffma2(p2, vv.x, acc2[2 * i]);
                    acc2[2 * i + 1] = ffma2(p2, vv.y, acc2[2 * i + 1]);
                }
            }
        }
        __syncthreads();
    }

    // normalize + store ctx (device-side symbol: OK)
    {
        const int b = bh >> 4, h = bh & 15;
        float inv = 1.0f / lsum;
        ull inv2 = pack2(inv, inv);
        ulonglong2* cp = (ulonglong2*)
            (g_ctx + ((size_t)(b * SEQ + qrow) * D_MODEL + h * HEAD_DIM));
#pragma unroll
        for (int i = 0; i < 16; i++) {
            ulonglong2 o;
            o.x = fmul2(acc2[2 * i], inv2);
            o.y = fmul2(acc2[2 * i + 1], inv2);
            cp[i] = o;
        }
    }
}

// ---------------------------------------------------------------------------
extern "C" void kernel_launch(void* const* d_in, const int* in_sizes, int n_in,
                              void* d_out, int out_size)
{
    const float* x = 0; const float* pk = 0; const float* pv = 0;
    const float* W_qkv = 0; const float* b_qkv = 0;
    const float* W_out = 0; const float* b_out = 0;
    for (int i = 0; i < n_in; i++) {
        const float* p = (const float*)d_in[i];
        switch (in_sizes[i]) {
            case 4194304:  x = p;      break;
            case 33554432: if (!pk) pk = p; else pv = p; break;
            case 3145728:  W_qkv = p;  break;
            case 3072:     b_qkv = p;  break;
            case 1048576:  W_out = p;  break;
            case 1024:     b_out = p;  break;
            default: break;
        }
    }
    if (!(x && pk && pv && W_qkv && b_qkv && W_out && b_out)) {
        if (n_in < 7) return;
        x     = (const float*)d_in[0];
        pk    = (const float*)d_in[1];
        pv    = (const float*)d_in[2];
        W_qkv = (const float*)d_in[3];
        b_qkv = (const float*)d_in[4];
        W_out = (const float*)d_in[5];
        b_out = (const float*)d_in[6];
    }

    float* out = (float*)d_out;

    // real device address of g_ctx (host query; capture-safe, no alloc)
    static float* s_ctx = nullptr;
    if (!s_ctx) {
        void* p = 0;
        cudaGetSymbolAddress(&p, g_ctx);
        s_ctx = (float*)p;
    }

    float* kvbuf = out + OUT_ELEMS;   // [out | k | v] element layout

    // 1) QKV GEMM
    {
        dim3 grid(3 * D_MODEL / BN, M_TOT / BM);   // (24, 32)
        sgemm_kernel<0><<<grid, 256>>>(x, W_qkv, b_qkv, kvbuf,
                                       M_TOT, 3 * D_MODEL, D_MODEL);
    }
    // 2) attention
    {
        dim3 grid(SEQ / 128, BATCH * N_HEADS);     // (16, 32)
        attn_kernel<<<grid, 128>>>(kvbuf, pk, pv);
    }
    // 3) output GEMM
    {
        dim3 grid(D_MODEL / BN, M_TOT / BM);       // (8, 32)
        sgemm_kernel<1><<<grid, 256>>>(s_ctx, W_out, b_out, out,
                                       M_TOT, D_MODEL, D_MODEL);
    }
}

// round 7
// speedup vs baseline: 1.1960x; 1.1526x over previous
#include <cuda_runtime.h>

#define D_MODEL  1024
#define N_HEADS  16
#define HEAD_DIM 64
#define BATCH    2
#define SEQ      2048
#define LMEM     8
#define M_TOT    (BATCH * SEQ)            // 4096
#define OUT_ELEMS (M_TOT * D_MODEL)       // 4194304
#define KV_ELEMS  (BATCH * N_HEADS * SEQ * HEAD_DIM)  // 4194304 each

typedef unsigned long long ull;

// scratch (no cudaMalloc allowed). NEVER pass these directly as kernel args
// from host code (host stub address + GB300 ATS = silent host reads).
__device__ float g_q[M_TOT * D_MODEL];       // 16.8 MB
__device__ float g_ctx[M_TOT * D_MODEL];     // 16.8 MB

// ---- packed fp32x2 helpers (sm_100+ PTX; 2 FMAs per issue) ----------------
__device__ __forceinline__ ull ffma2(ull a, ull b, ull c) {
    ull d;
    asm("fma.rn.f32x2 %0, %1, %2, %3;" : "=l"(d) : "l"(a), "l"(b), "l"(c));
    return d;
}
__device__ __forceinline__ ull fmul2(ull a, ull b) {
    ull d;
    asm("mul.rn.f32x2 %0, %1, %2;" : "=l"(d) : "l"(a), "l"(b));
    return d;
}
__device__ __forceinline__ ull pack2(float lo, float hi) {
    ull r;
    asm("mov.b64 %0, {%1, %2};" : "=l"(r) : "f"(lo), "f"(hi));
    return r;
}
__device__ __forceinline__ void unpack2(ull v, float& lo, float& hi) {
    asm("mov.b64 {%0, %1}, %2;" : "=f"(lo), "=f"(hi) : "l"(v));
}

// ---------------------------------------------------------------------------
// Tiled fp32 GEMM (FFMA2 mainloop): C = A(MxK) @ B(KxN) + bias(N)
// MODE 0: QKV — n<1024 -> g_q; n in [1024,3072) -> C=kvbuf (split-head)
// MODE 1: plain row-major store to C
// ---------------------------------------------------------------------------
#define BM 128
#define BN 128
#define BK 16

template <int MODE>
__global__ __launch_bounds__(256)
void sgemm_kernel(const float* __restrict__ A,
                  const float* __restrict__ B,
                  const float* __restrict__ bias,
                  float* __restrict__ C,
                  int M, int N, int K)
{
    __shared__ float As[BK][BM + 4];
    __shared__ float Bs[BK][BN];

    const int tid = threadIdx.x;            // 0..255
    const int row0 = blockIdx.y * BM;
    const int col0 = blockIdx.x * BN;
    const int tx = tid & 15;
    const int ty = tid >> 4;

    ull acc2[8][4];
#pragma unroll
    for (int i = 0; i < 8; i++)
#pragma unroll
        for (int j = 0; j < 4; j++) acc2[i][j] = 0ull;

    for (int kt = 0; kt < K; kt += BK) {
#pragma unroll
        for (int i = 0; i < 2; i++) {
            int e  = tid + i * 256;
            int r  = e >> 2;
            int c4 = (e & 3) * 4;
            float4 v = *(const float4*)(A + (size_t)(row0 + r) * K + kt + c4);
            As[c4 + 0][r] = v.x;
            As[c4 + 1][r] = v.y;
            As[c4 + 2][r] = v.z;
            As[c4 + 3][r] = v.w;
        }
#pragma unroll
        for (int i = 0; i < 2; i++) {
            int e  = tid + i * 256;
            int r  = e >> 5;
            int c4 = (e & 31) * 4;
            *(float4*)&Bs[r][c4] =
                *(const float4*)(B + (size_t)(kt + r) * N + col0 + c4);
        }
        __syncthreads();

#pragma unroll
        for (int k = 0; k < BK; k++) {
            float a[8];
            *(float4*)&a[0] = *(float4*)&As[k][ty * 8];
            *(float4*)&a[4] = *(float4*)&As[k][ty * 8 + 4];

            ulonglong2 bb0 = *(const ulonglong2*)&Bs[k][tx * 8];
            ulonglong2 bb1 = *(const ulonglong2*)&Bs[k][tx * 8 + 4];
            ull b2[4] = { bb0.x, bb0.y, bb1.x, bb1.y };

            ull a2[8];
#pragma unroll
            for (int i = 0; i < 8; i++) a2[i] = pack2(a[i], a[i]);

#pragma unroll
            for (int i = 0; i < 8; i++)
#pragma unroll
                for (int j = 0; j < 4; j++)
                    acc2[i][j] = ffma2(a2[i], b2[j], acc2[i][j]);
        }
        __syncthreads();
    }

#pragma unroll
    for (int i = 0; i < 8; i++) {
        int m = row0 + ty * 8 + i;
#pragma unroll
        for (int j = 0; j < 4; j++) {
            float v0, v1;
            unpack2(acc2[i][j], v0, v1);
#pragma unroll
            for (int t = 0; t < 2; t++) {
                int n = col0 + tx * 8 + 2 * j + t;
                float val = (t ? v1 : v0) + bias[n];
                if (MODE == 1) {
                    C[(size_t)m * N + n] = val;
                } else {
                    int b = m >> 11;
                    int s = m & 2047;
                    if (n < D_MODEL) {
                        g_q[(size_t)m * D_MODEL + n] = val;
                    } else {
                        int c = n - D_MODEL;
                        int which = c >> 10;
                        c &= 1023;
                        int h = c >> 6;
                        int d = c & 63;
                        size_t off = (size_t)which * KV_ELEMS
                                   + (((size_t)(b * N_HEADS + h) * SEQ + s) * HEAD_DIM + d);
                        C[off] = val;
                    }
                }
            }
        }
    }
}

// ---------------------------------------------------------------------------
// Attention v2: one CTA = (b, h, 128-query tile), 256 threads.
// Thread pair (lane, lane^16) splits HEAD_DIM: each owns 32 dims.
// Static softmax base (exp(s - 20)) — no online max, no rescaling.
// ---------------------------------------------------------------------------
__global__ __launch_bounds__(256)
void attn_kernel(const float* __restrict__ kvbuf,
                 const float* __restrict__ pk,
                 const float* __restrict__ pv)
{
    __shared__ float sk[64][64];
    __shared__ float sv[64][64];

    const int tid  = threadIdx.x;             // 0..255
    const int warp = tid >> 5;                // 0..7
    const int lane = tid & 31;
    const int half = lane >> 4;               // 0 or 1 (dim half)
    const int qi   = (warp << 4) | (lane & 15);  // 0..127
    const int qt   = blockIdx.x;               // 0..15
    const int bh   = blockIdx.y;               // 0..31
    const int qrow = qt * 128 + qi;
    const int b = bh >> 4, h = bh & 15;
    const float MX = 20.0f;                    // static softmax base

    // q half (32 dims), pre-scaled by 1/sqrt(64)
    ull q2[16];
    {
        const ulonglong2* qp = (const ulonglong2*)
            (g_q + ((size_t)(b * SEQ + qrow) * D_MODEL + h * HEAD_DIM + half * 32));
        ull sc2 = pack2(0.125f, 0.125f);
#pragma unroll
        for (int i = 0; i < 8; i++) {
            ulonglong2 t = qp[i];
            q2[2 * i]     = fmul2(t.x, sc2);
            q2[2 * i + 1] = fmul2(t.y, sc2);
        }
    }

    ull acc2[16];
#pragma unroll
    for (int i = 0; i < 16; i++) acc2[i] = 0ull;
    float lsum = 0.0f;

    // ---- 8 per-token memory keys ----
    {
        const size_t mbase = ((size_t)bh * SEQ + qrow) * (LMEM * HEAD_DIM) + half * 32;
#pragma unroll
        for (int l = 0; l < LMEM; l++) {
            const ulonglong2* kp = (const ulonglong2*)(pk + mbase + l * HEAD_DIM);
            ull dot2 = 0ull;
#pragma unroll
            for (int i = 0; i < 8; i++) {
                ulonglong2 kk = kp[i];
                dot2 = ffma2(q2[2 * i], kk.x, dot2);
                dot2 = ffma2(q2[2 * i + 1], kk.y, dot2);
            }
            float dlo, dhi;
            unpack2(dot2, dlo, dhi);
            float d = dlo + dhi;
            d += __shfl_xor_sync(0xFFFFFFFFu, d, 16);
            float p = __expf(d - MX);
            lsum += p;
            ull p2 = pack2(p, p);
            const ulonglong2* vp = (const ulonglong2*)(pv + mbase + l * HEAD_DIM);
#pragma unroll
            for (int i = 0; i < 8; i++) {
                ulonglong2 vv = vp[i];
                acc2[2 * i]     = ffma2(p2, vv.x, acc2[2 * i]);
                acc2[2 * i + 1] = ffma2(p2, vv.y, acc2[2 * i + 1]);
            }
        }
    }

    // ---- causal token keys ----
    const float* kb = kvbuf + (size_t)bh * SEQ * HEAD_DIM;
    const float* vb = kvbuf + (size_t)KV_ELEMS + (size_t)bh * SEQ * HEAD_DIM;
    const int nkeys = qt * 128 + 128;
    const int wmax  = qt * 128 + (warp << 4) + 15;   // max qrow in this warp

    for (int kt0 = 0; kt0 < nkeys; kt0 += 64) {
        // stage 64 keys + values: 1024 float4 each, 4 per thread
#pragma unroll
        for (int i = 0; i < 4; i++) {
            int e = tid + i * 256;
            ((float4*)sk)[e] = ((const float4*)(kb + (size_t)kt0 * HEAD_DIM))[e];
            ((float4*)sv)[e] = ((const float4*)(vb + (size_t)kt0 * HEAD_DIM))[e];
        }
        __syncthreads();

#pragma unroll 1
        for (int c0 = 0; c0 < 64; c0 += 8) {
            if (kt0 + c0 <= wmax) {      // warp-uniform: skip fully-masked chunks
                float p[8];
                // phase 1+2: 8 scaled dots -> masked exp
#pragma unroll
                for (int j = 0; j < 8; j++) {
                    const ulonglong2* kr = (const ulonglong2*)&sk[c0 + j][half * 32];
                    ull dot2 = 0ull;
#pragma unroll
                    for (int i = 0; i < 8; i++) {
                        ulonglong2 kk = kr[i];
                        dot2 = ffma2(q2[2 * i], kk.x, dot2);
                        dot2 = ffma2(q2[2 * i + 1], kk.y, dot2);
                    }
                    float dlo, dhi;
                    unpack2(dot2, dlo, dhi);
                    float d = dlo + dhi;
                    d += __shfl_xor_sync(0xFFFFFFFFu, d, 16);
                    int kj = kt0 + c0 + j;
                    p[j] = (kj <= qrow) ? __expf(d - MX) : 0.0f;
                }
                // phase 3: accumulate V
#pragma unroll
                for (int j = 0; j < 8; j++) {
                    lsum += p[j];
                    ull p2 = pack2(p[j], p[j]);
                    const ulonglong2* vr = (const ulonglong2*)&sv[c0 + j][half * 32];
#pragma unroll
                    for (int i = 0; i < 8; i++) {
                        ulonglong2 vv = vr[i];
                        acc2[2 * i]     = ffma2(p2, vv.x, acc2[2 * i]);
                        acc2[2 * i + 1] = ffma2(p2, vv.y, acc2[2 * i + 1]);
                    }
                }
            }
        }
        __syncthreads();
    }

    // normalize + store this thread's 32 dims of ctx
    {
        float inv = 1.0f / lsum;
        ull inv2 = pack2(inv, inv);
        ulonglong2* cp = (ulonglong2*)
            (g_ctx + ((size_t)(b * SEQ + qrow) * D_MODEL + h * HEAD_DIM + half * 32));
#pragma unroll
        for (int i = 0; i < 8; i++) {
            ulonglong2 o;
            o.x = fmul2(acc2[2 * i], inv2);
            o.y = fmul2(acc2[2 * i + 1], inv2);
            cp[i] = o;
        }
    }
}

// ---------------------------------------------------------------------------
extern "C" void kernel_launch(void* const* d_in, const int* in_sizes, int n_in,
                              void* d_out, int out_size)
{
    const float* x = 0; const float* pk = 0; const float* pv = 0;
    const float* W_qkv = 0; const float* b_qkv = 0;
    const float* W_out = 0; const float* b_out = 0;
    for (int i = 0; i < n_in; i++) {
        const float* p = (const float*)d_in[i];
        switch (in_sizes[i]) {
            case 4194304:  x = p;      break;
            case 33554432: if (!pk) pk = p; else pv = p; break;
            case 3145728:  W_qkv = p;  break;
            case 3072:     b_qkv = p;  break;
            case 1048576:  W_out = p;  break;
            case 1024:     b_out = p;  break;
            default: break;
        }
    }
    if (!(x && pk && pv && W_qkv && b_qkv && W_out && b_out)) {
        if (n_in < 7) return;
        x     = (const float*)d_in[0];
        pk    = (const float*)d_in[1];
        pv    = (const float*)d_in[2];
        W_qkv = (const float*)d_in[3];
        b_qkv = (const float*)d_in[4];
        W_out = (const float*)d_in[5];
        b_out = (const float*)d_in[6];
    }

    float* out = (float*)d_out;

    static float* s_ctx = nullptr;
    if (!s_ctx) {
        void* p = 0;
        cudaGetSymbolAddress(&p, g_ctx);
        s_ctx = (float*)p;
    }

    float* kvbuf = out + OUT_ELEMS;   // [out | k | v] element layout

    // 1) QKV GEMM
    {
        dim3 grid(3 * D_MODEL / BN, M_TOT / BM);   // (24, 32)
        sgemm_kernel<0><<<grid, 256>>>(x, W_qkv, b_qkv, kvbuf,
                                       M_TOT, 3 * D_MODEL, D_MODEL);
    }
    // 2) attention (256 threads: 128 queries x 2 dim-halves)
    {
        dim3 grid(SEQ / 128, BATCH * N_HEADS);     // (16, 32)
        attn_kernel<<<grid, 256>>>(kvbuf, pk, pv);
    }
    // 3) output GEMM
    {
        dim3 grid(D_MODEL / BN, M_TOT / BM);       // (8, 32)
        sgemm_kernel<1><<<grid, 256>>>(s_ctx, W_out, b_out, out,
                                       M_TOT, D_MODEL, D_MODEL);
    }
}

// round 9
// speedup vs baseline: 1.3953x; 1.1666x over previous
#include <cuda_runtime.h>
#include <cstdint>

#define D_MODEL  1024
#define N_HEADS  16
#define HEAD_DIM 64
#define BATCH    2
#define SEQ      2048
#define LMEM     8
#define M_TOT    (BATCH * SEQ)            // 4096
#define OUT_ELEMS (M_TOT * D_MODEL)       // 4194304
#define KV_ELEMS  (BATCH * N_HEADS * SEQ * HEAD_DIM)  // 4194304 each

typedef unsigned long long ull;

// scratch (no cudaMalloc). NEVER pass these directly as host-side kernel args
// (host stub address + GB300 ATS = silent host reads) — use cudaGetSymbolAddress.
__device__ float g_q[M_TOT * D_MODEL];
__device__ float g_ctx[M_TOT * D_MODEL];

// ---- packed fp32x2 helpers (base-ISA, proven rounds 6-7) --------------------
__device__ __forceinline__ ull ffma2(ull a, ull b, ull c) {
    ull d;
    asm("fma.rn.f32x2 %0, %1, %2, %3;" : "=l"(d) : "l"(a), "l"(b), "l"(c));
    return d;
}
__device__ __forceinline__ ull fmul2(ull a, ull b) {
    ull d;
    asm("mul.rn.f32x2 %0, %1, %2;" : "=l"(d) : "l"(a), "l"(b));
    return d;
}
__device__ __forceinline__ ull pack2(float lo, float hi) {
    ull r;
    asm("mov.b64 %0, {%1, %2};" : "=l"(r) : "f"(lo), "f"(hi));
    return r;
}
__device__ __forceinline__ void unpack2(ull v, float& lo, float& hi) {
    asm("mov.b64 {%0, %1}, %2;" : "=f"(lo), "=f"(hi) : "l"(v));
}

// ---- bf16 pack/unpack --------------------------------------------------------
// packed uint32: element0 (lower 16b) = lo arg, element1 (upper 16b) = hi arg
__device__ __forceinline__ uint32_t bf2(float lo, float hi) {
    uint32_t r;
    asm("cvt.rn.bf16x2.f32 %0, %1, %2;" : "=r"(r) : "f"(hi), "f"(lo));
    return r;
}
__device__ __forceinline__ float bf_lo_f(uint32_t h) { return __uint_as_float(h << 16); }
__device__ __forceinline__ float bf_hi_f(uint32_t h) { return __uint_as_float(h & 0xFFFF0000u); }

// ---------------------------------------------------------------------------
// bf16 mma.sync GEMM with hi/lo 3-term split (fp32-accurate).
// C = A(Mx1024) @ B(1024xN) + bias. Tile 128x128/CTA, 8 warps (2x4), each
// warp 64x32 via m16n8k16 fragments. K chunks of 64.
// MODE 0: QKV scatter epilogue. MODE 1: plain row-major.
// ---------------------------------------------------------------------------
// SMEM (uint32 words): a_hi/a_lo/b_hi/b_lo each [4][128][9]=4608 words,
// then fp32 transpose scratch 64x129.
#define HG_WORDS (4 * 4608 + 64 * 129)
#define HG_SMEM  (HG_WORDS * 4)

template <int MODE>
__global__ __launch_bounds__(256)
void hgemm_kernel(const float* __restrict__ A,
                  const float* __restrict__ B,
                  const float* __restrict__ bias,
                  float* __restrict__ C,
                  int Nld)
{
    extern __shared__ uint32_t sm[];
    uint32_t* a_hi = sm;
    uint32_t* a_lo = a_hi + 4608;
    uint32_t* b_hi = a_lo + 4608;
    uint32_t* b_lo = b_hi + 4608;
    float*    scr  = (float*)(b_lo + 4608);   // [64][129]

    const int tid   = threadIdx.x;
    const int wid   = tid >> 5;
    const int lane  = tid & 31;
    const int warpM = wid & 1;                // 2 x 64 rows
    const int warpN = wid >> 1;               // 4 x 32 cols
    const int row0  = blockIdx.y * 128;
    const int col0  = blockIdx.x * 128;
    const int lq    = lane >> 2;              // 0..7
    const int lr    = lane & 3;               // 0..3

    float acc[4][4][4];
#pragma unroll
    for (int a = 0; a < 4; a++)
#pragma unroll
        for (int b = 0; b < 4; b++)
#pragma unroll
            for (int c = 0; c < 4; c++) acc[a][b][c] = 0.0f;

#pragma unroll 1
    for (int kt = 0; kt < 16; kt++) {
        const int k0 = kt * 64;

        // ---- A tile: 128x64 fp32 -> bf16 hi/lo in [ks][m][kpair] ----
#pragma unroll
        for (int i = 0; i < 8; i++) {
            int e  = tid + i * 256;           // 0..2047
            int m  = e >> 4;                  // 0..127
            int c4 = (e & 15) * 4;            // 0..60
            float4 v = *(const float4*)(A + (size_t)(row0 + m) * 1024 + k0 + c4);
            int ks = c4 >> 4;
            int kp = (c4 & 15) >> 1;          // 0,2,4,6
            uint32_t h01 = bf2(v.x, v.y), h23 = bf2(v.z, v.w);
            uint32_t l01 = bf2(v.x - bf_lo_f(h01), v.y - bf_hi_f(h01));
            uint32_t l23 = bf2(v.z - bf_lo_f(h23), v.w - bf_hi_f(h23));
            int idx = (ks * 128 + m) * 9 + kp;
            a_hi[idx] = h01; a_hi[idx + 1] = h23;
            a_lo[idx] = l01; a_lo[idx + 1] = l23;
        }
        // ---- B rows -> fp32 scratch ----
#pragma unroll
        for (int i = 0; i < 8; i++) {
            int e  = tid + i * 256;
            int c  = e >> 5;                  // 0..63
            int n4 = (e & 31) * 4;
            float4 w = *(const float4*)(B + (size_t)(k0 + c) * Nld + col0 + n4);
            float* sp = scr + c * 129 + n4;
            sp[0] = w.x; sp[1] = w.y; sp[2] = w.z; sp[3] = w.w;
        }
        __syncthreads();

        // ---- scratch -> b_hi/b_lo in [ks][n][kpair] ----
#pragma unroll
        for (int i = 0; i < 16; i++) {
            int e    = tid + i * 256;         // 0..4095
            int n    = e >> 5;                // 0..127
            int kp32 = e & 31;
            int ks   = kp32 >> 3;
            int kp   = kp32 & 7;
            int k    = ks * 16 + kp * 2;
            float v0 = scr[k * 129 + n];
            float v1 = scr[(k + 1) * 129 + n];
            uint32_t h = bf2(v0, v1);
            uint32_t l = bf2(v0 - bf_lo_f(h), v1 - bf_hi_f(h));
            int idx = (ks * 128 + n) * 9 + kp;
            b_hi[idx] = h; b_lo[idx] = l;
        }
        __syncthreads();

        // ---- compute: 3 terms x 4 K16-steps x 16 mma ----
        const uint32_t* At[3] = { a_hi, a_hi, a_lo };
        const uint32_t* Bt[3] = { b_hi, b_lo, b_hi };
#pragma unroll
        for (int t = 0; t < 3; t++) {
            const uint32_t* Ap = At[t];
            const uint32_t* Bp = Bt[t];
#pragma unroll
            for (int ks = 0; ks < 4; ks++) {
                uint32_t bfr[4][2];
#pragma unroll
                for (int nt = 0; nt < 4; nt++) {
                    int n = warpN * 32 + nt * 8 + lq;
                    int idx = (ks * 128 + n) * 9 + lr;
                    bfr[nt][0] = Bp[idx];
                    bfr[nt][1] = Bp[idx + 4];
                }
#pragma unroll
                for (int mt = 0; mt < 4; mt++) {
                    int r = warpM * 64 + mt * 16 + lq;
                    int idx = (ks * 128 + r) * 9 + lr;
                    uint32_t a0 = Ap[idx];
                    uint32_t a1 = Ap[idx + 72];       // +8 rows * 9
                    uint32_t a2 = Ap[idx + 4];
                    uint32_t a3 = Ap[idx + 76];
#pragma unroll
                    for (int nt = 0; nt < 4; nt++) {
                        asm volatile(
                            "mma.sync.aligned.m16n8k16.row.col.f32.bf16.bf16.f32 "
                            "{%0,%1,%2,%3}, {%4,%5,%6,%7}, {%8,%9}, {%0,%1,%2,%3};"
                            : "+f"(acc[mt][nt][0]), "+f"(acc[mt][nt][1]),
                              "+f"(acc[mt][nt][2]), "+f"(acc[mt][nt][3])
                            : "r"(a0), "r"(a1), "r"(a2), "r"(a3),
                              "r"(bfr[nt][0]), "r"(bfr[nt][1]));
                    }
                }
            }
        }
        __syncthreads();
    }

    // ---- epilogue ----
#pragma unroll
    for (int mt = 0; mt < 4; mt++) {
        int mbase = row0 + warpM * 64 + mt * 16 + lq;
#pragma unroll
        for (int nt = 0; nt < 4; nt++) {
            int nbase = col0 + warpN * 32 + nt * 8 + lr * 2;
#pragma unroll
            for (int q = 0; q < 4; q++) {
                int m = mbase + (q >> 1) * 8;
                int n = nbase + (q & 1);
                float val = acc[mt][nt][q] + __ldg(bias + n);
                if (MODE == 1) {
                    C[(size_t)m * 1024 + n] = val;
                } else {
                    int b = m >> 11;
                    int s = m & 2047;
                    if (n < D_MODEL) {
                        g_q[(size_t)m * D_MODEL + n] = val;
                    } else {
                        int cc = n - D_MODEL;
                        int which = cc >> 10;
                        cc &= 1023;
                        int h = cc >> 6;
                        int d = cc & 63;
                        size_t off = (size_t)which * KV_ELEMS
                                   + (((size_t)(b * N_HEADS + h) * SEQ + s) * HEAD_DIM + d);
                        C[off] = val;
                    }
                }
            }
        }
    }
}

// ---------------------------------------------------------------------------
// Attention (unchanged from round 7, passing): one CTA = (b,h,128 queries).
// ---------------------------------------------------------------------------
__global__ __launch_bounds__(256)
void attn_kernel(const float* __restrict__ kvbuf,
                 const float* __restrict__ pk,
                 const float* __restrict__ pv)
{
    __shared__ float sk[64][64];
    __shared__ float sv[64][64];

    const int tid  = threadIdx.x;
    const int warp = tid >> 5;
    const int lane = tid & 31;
    const int half = lane >> 4;
    const int qi   = (warp << 4) | (lane & 15);
    const int qt   = blockIdx.x;
    const int bh   = blockIdx.y;
    const int qrow = qt * 128 + qi;
    const int b = bh >> 4, h = bh & 15;
    const float MX = 20.0f;

    ull q2[16];
    {
        const ulonglong2* qp = (const ulonglong2*)
            (g_q + ((size_t)(b * SEQ + qrow) * D_MODEL + h * HEAD_DIM + half * 32));
        ull sc2 = pack2(0.125f, 0.125f);
#pragma unroll
        for (int i = 0; i < 8; i++) {
            ulonglong2 t = qp[i];
            q2[2 * i]     = fmul2(t.x, sc2);
            q2[2 * i + 1] = fmul2(t.y, sc2);
        }
    }

    ull acc2[16];
#pragma unroll
    for (int i = 0; i < 16; i++) acc2[i] = 0ull;
    float lsum = 0.0f;

    {
        const size_t mbase = ((size_t)bh * SEQ + qrow) * (LMEM * HEAD_DIM) + half * 32;
#pragma unroll
        for (int l = 0; l < LMEM; l++) {
            const ulonglong2* kp = (const ulonglong2*)(pk + mbase + l * HEAD_DIM);
            ull dot2 = 0ull;
#pragma unroll
            for (int i = 0; i < 8; i++) {
                ulonglong2 kk = kp[i];
                dot2 = ffma2(q2[2 * i], kk.x, dot2);
                dot2 = ffma2(q2[2 * i + 1], kk.y, dot2);
            }
            float dlo, dhi;
            unpack2(dot2, dlo, dhi);
            float d = dlo + dhi;
            d += __shfl_xor_sync(0xFFFFFFFFu, d, 16);
            float p = __expf(d - MX);
            lsum += p;
            ull p2 = pack2(p, p);
            const ulonglong2* vp = (const ulonglong2*)(pv + mbase + l * HEAD_DIM);
#pragma unroll
            for (int i = 0; i < 8; i++) {
                ulonglong2 vv = vp[i];
                acc2[2 * i]     = ffma2(p2, vv.x, acc2[2 * i]);
                acc2[2 * i + 1] = ffma2(p2, vv.y, acc2[2 * i + 1]);
            }
        }
    }

    const float* kb = kvbuf + (size_t)bh * SEQ * HEAD_DIM;
    const float* vb = kvbuf + (size_t)KV_ELEMS + (size_t)bh * SEQ * HEAD_DIM;
    const int nkeys = qt * 128 + 128;
    const int wmax  = qt * 128 + (warp << 4) + 15;

    for (int kt0 = 0; kt0 < nkeys; kt0 += 64) {
#pragma unroll
        for (int i = 0; i < 4; i++) {
            int e = tid + i * 256;
            ((float4*)sk)[e] = ((const float4*)(kb + (size_t)kt0 * HEAD_DIM))[e];
            ((float4*)sv)[e] = ((const float4*)(vb + (size_t)kt0 * HEAD_DIM))[e];
        }
        __syncthreads();

#pragma unroll 1
        for (int c0 = 0; c0 < 64; c0 += 8) {
            if (kt0 + c0 <= wmax) {
                float p[8];
#pragma unroll
                for (int j = 0; j < 8; j++) {
                    const ulonglong2* kr = (const ulonglong2*)&sk[c0 + j][half * 32];
                    ull dot2 = 0ull;
#pragma unroll
                    for (int i = 0; i < 8; i++) {
                        ulonglong2 kk = kr[i];
                        dot2 = ffma2(q2[2 * i], kk.x, dot2);
                        dot2 = ffma2(q2[2 * i + 1], kk.y, dot2);
                    }
                    float dlo, dhi;
                    unpack2(dot2, dlo, dhi);
                    float d = dlo + dhi;
                    d += __shfl_xor_sync(0xFFFFFFFFu, d, 16);
                    int kj = kt0 + c0 + j;
                    p[j] = (kj <= qrow) ? __expf(d - MX) : 0.0f;
                }
#pragma unroll
                for (int j = 0; j < 8; j++) {
                    lsum += p[j];
                    ull p2 = pack2(p[j], p[j]);
                    const ulonglong2* vr = (const ulonglong2*)&sv[c0 + j][half * 32];
#pragma unroll
                    for (int i = 0; i < 8; i++) {
                        ulonglong2 vv = vr[i];
                        acc2[2 * i]     = ffma2(p2, vv.x, acc2[2 * i]);
                        acc2[2 * i + 1] = ffma2(p2, vv.y, acc2[2 * i + 1]);
                    }
                }
            }
        }
        __syncthreads();
    }

    {
        float inv = 1.0f / lsum;
        ull inv2 = pack2(inv, inv);
        ulonglong2* cp = (ulonglong2*)
            (g_ctx + ((size_t)(b * SEQ + qrow) * D_MODEL + h * HEAD_DIM + half * 32));
#pragma unroll
        for (int i = 0; i < 8; i++) {
            ulonglong2 o;
            o.x = fmul2(acc2[2 * i], inv2);
            o.y = fmul2(acc2[2 * i + 1], inv2);
            cp[i] = o;
        }
    }
}

// ---------------------------------------------------------------------------
extern "C" void kernel_launch(void* const* d_in, const int* in_sizes, int n_in,
                              void* d_out, int out_size)
{
    const float* x = 0; const float* pk = 0; const float* pv = 0;
    const float* W_qkv = 0; const float* b_qkv = 0;
    const float* W_out = 0; const float* b_out = 0;
    for (int i = 0; i < n_in; i++) {
        const float* p = (const float*)d_in[i];
        switch (in_sizes[i]) {
            case 4194304:  x = p;      break;
            case 33554432: if (!pk) pk = p; else pv = p; break;
            case 3145728:  W_qkv = p;  break;
            case 3072:     b_qkv = p;  break;
            case 1048576:  W_out = p;  break;
            case 1024:     b_out = p;  break;
            default: break;
        }
    }
    if (!(x && pk && pv && W_qkv && b_qkv && W_out && b_out)) {
        if (n_in < 7) return;
        x     = (const float*)d_in[0];
        pk    = (const float*)d_in[1];
        pv    = (const float*)d_in[2];
        W_qkv = (const float*)d_in[3];
        b_qkv = (const float*)d_in[4];
        W_out = (const float*)d_in[5];
        b_out = (const float*)d_in[6];
    }

    float* out = (float*)d_out;

    static float* s_ctx = nullptr;
    if (!s_ctx) {
        void* p = 0;
        cudaGetSymbolAddress(&p, g_ctx);
        s_ctx = (float*)p;
        cudaFuncSetAttribute((const void*)hgemm_kernel<0>,
                             cudaFuncAttributeMaxDynamicSharedMemorySize, HG_SMEM);
        cudaFuncSetAttribute((const void*)hgemm_kernel<1>,
                             cudaFuncAttributeMaxDynamicSharedMemorySize, HG_SMEM);
    }

    float* kvbuf = out + OUT_ELEMS;   // [out | k | v] element layout

    // 1) QKV GEMM on tensor cores (mma.sync bf16 3-term)
    {
        dim3 grid(3 * D_MODEL / 128, M_TOT / 128);    // (24, 32)
        hgemm_kernel<0><<<grid, 256, HG_SMEM>>>(x, W_qkv, b_qkv, kvbuf, 3 * D_MODEL);
    }
    // 2) attention
    {
        dim3 grid(SEQ / 128, BATCH * N_HEADS);        // (16, 32)
        attn_kernel<<<grid, 256>>>(kvbuf, pk, pv);
    }
    // 3) output GEMM on tensor cores
    {
        dim3 grid(D_MODEL / 128, M_TOT / 128);        // (8, 32)
        hgemm_kernel<1><<<grid, 256, HG_SMEM>>>(s_ctx, W_out, b_out, out, D_MODEL);
    }
}

// round 10
// speedup vs baseline: 1.5020x; 1.0765x over previous
#include <cuda_runtime.h>
#include <cuda_bf16.h>
#include <cstdint>

#define D_MODEL  1024
#define N_HEADS  16
#define HEAD_DIM 64
#define BATCH    2
#define SEQ      2048
#define LMEM     8
#define M_TOT    (BATCH * SEQ)            // 4096
#define OUT_ELEMS (M_TOT * D_MODEL)       // 4194304
#define KV_ELEMS  (BATCH * N_HEADS * SEQ * HEAD_DIM)  // 4194304 each

typedef unsigned long long ull;

// scratch (no cudaMalloc). NEVER pass these directly as host-side kernel args
// (host stub address + GB300 ATS = silent host reads) — use cudaGetSymbolAddress.
__device__ float g_q[M_TOT * D_MODEL];
__device__ float g_ctx[M_TOT * D_MODEL];
__device__ __nv_bfloat16 g_a_hi[M_TOT * D_MODEL];       // A split, [M][1024]
__device__ __nv_bfloat16 g_a_lo[M_TOT * D_MODEL];
__device__ __nv_bfloat16 g_bt_hi[3 * D_MODEL * D_MODEL]; // W^T split, [N][1024]
__device__ __nv_bfloat16 g_bt_lo[3 * D_MODEL * D_MODEL];

// ---- packed fp32x2 helpers ---------------------------------------------------
__device__ __forceinline__ ull ffma2(ull a, ull b, ull c) {
    ull d;
    asm("fma.rn.f32x2 %0, %1, %2, %3;" : "=l"(d) : "l"(a), "l"(b), "l"(c));
    return d;
}
__device__ __forceinline__ ull fmul2(ull a, ull b) {
    ull d;
    asm("mul.rn.f32x2 %0, %1, %2;" : "=l"(d) : "l"(a), "l"(b));
    return d;
}
__device__ __forceinline__ ull pack2(float lo, float hi) {
    ull r;
    asm("mov.b64 %0, {%1, %2};" : "=l"(r) : "f"(lo), "f"(hi));
    return r;
}
__device__ __forceinline__ void unpack2(ull v, float& lo, float& hi) {
    asm("mov.b64 {%0, %1}, %2;" : "=f"(lo), "=f"(hi) : "l"(v));
}

// ---- bf16 helpers --------------------------------------------------------------
// packed uint32: low 16 = first elem, high 16 = second elem
__device__ __forceinline__ uint32_t bf2(float lo, float hi) {
    uint32_t r;
    asm("cvt.rn.bf16x2.f32 %0, %1, %2;" : "=r"(r) : "f"(hi), "f"(lo));
    return r;
}
__device__ __forceinline__ float bf_lo_f(uint32_t h) { return __uint_as_float(h << 16); }
__device__ __forceinline__ float bf_hi_f(uint32_t h) { return __uint_as_float(h & 0xFFFF0000u); }

// ---------------------------------------------------------------------------
// Prep kernel 1: elementwise fp32 -> bf16 hi/lo split (row-major preserved).
// n4 = number of float4s. grid*256 == n4.
// ---------------------------------------------------------------------------
__global__ __launch_bounds__(256)
void split_a_kernel(const float4* __restrict__ src,
                    uint2* __restrict__ hi, uint2* __restrict__ lo)
{
    int i = blockIdx.x * 256 + threadIdx.x;
    float4 v = src[i];
    uint32_t h01 = bf2(v.x, v.y), h23 = bf2(v.z, v.w);
    uint32_t l01 = bf2(v.x - bf_lo_f(h01), v.y - bf_hi_f(h01));
    uint32_t l23 = bf2(v.z - bf_lo_f(h23), v.w - bf_hi_f(h23));
    hi[i] = make_uint2(h01, h23);
    lo[i] = make_uint2(l01, l23);
}

// ---------------------------------------------------------------------------
// Prep kernel 2: W[1024][N] -> W^T[N][1024] bf16 hi/lo. 32x32 tiles.
// block (32,8); grid (N/32, 1024/32).
// ---------------------------------------------------------------------------
__global__ __launch_bounds__(256)
void split_wt_kernel(const float* __restrict__ W,
                     __nv_bfloat16* __restrict__ hiT,
                     __nv_bfloat16* __restrict__ loT,
                     int N)
{
    __shared__ float t[32][33];
    const int tx = threadIdx.x, ty = threadIdx.y;
    const int n0 = blockIdx.x * 32, k0 = blockIdx.y * 32;
#pragma unroll
    for (int i = 0; i < 4; i++)
        t[ty + 8 * i][tx] = W[(size_t)(k0 + ty + 8 * i) * N + n0 + tx];
    __syncthreads();
#pragma unroll
    for (int i = 0; i < 4; i++) {
        int n = n0 + ty + 8 * i;
        float f = t[tx][ty + 8 * i];
        __nv_bfloat16 h = __float2bfloat16(f);
        __nv_bfloat16 l = __float2bfloat16(f - __bfloat162float(h));
        hiT[(size_t)n * 1024 + k0 + tx] = h;
        loT[(size_t)n * 1024 + k0 + tx] = l;
    }
}

// ---------------------------------------------------------------------------
// bf16 mma.sync GEMM, hi/lo 3-term, operands pre-split & pre-transposed.
// C = A(Mx1024) @ B(1024xN) + bias. 128x128 tile/CTA, 8 warps (2x4).
// Double-buffered SMEM (2 stages x 4 arrays x [4][128][9] words = 144KB).
// MODE 0: QKV scatter epilogue. MODE 1: plain row-major.
// ---------------------------------------------------------------------------
#define STG_WORDS 18432                     // 4 arrays x 4608
#define HB_SMEM   (2 * STG_WORDS * 4)       // 147456 B

template <int MODE>
__global__ __launch_bounds__(256)
void hgemm_bf(const uint4* __restrict__ Ah, const uint4* __restrict__ Al,
              const uint4* __restrict__ Bh, const uint4* __restrict__ Bl,
              const float* __restrict__ bias,
              float* __restrict__ C)
{
    extern __shared__ uint32_t sm[];

    const int tid   = threadIdx.x;
    const int wid   = tid >> 5;
    const int lane  = tid & 31;
    const int warpM = wid & 1;
    const int warpN = wid >> 1;
    const int row0  = blockIdx.y * 128;
    const int col0  = blockIdx.x * 128;
    const int lq    = lane >> 2;
    const int lr    = lane & 3;

    // per-thread load geometry (fixed across chunks)
    const int m_   = (tid * 4) >> 3;        // not used; keep simple below

    float acc[4][4][4];
#pragma unroll
    for (int a = 0; a < 4; a++)
#pragma unroll
        for (int b = 0; b < 4; b++)
#pragma unroll
            for (int c = 0; c < 4; c++) acc[a][b][c] = 0.0f;

    uint4 r[16];

    // LDG of one chunk (kt) into regs: uint4 index = (row)*128 + kt*8 + seg
#define LDG_CHUNK(kt)                                                        \
    {                                                                        \
        _Pragma("unroll")                                                    \
        for (int i = 0; i < 4; i++) {                                        \
            int e = tid + i * 256;                                           \
            int m = e >> 3, seg = e & 7;                                     \
            int ai = (row0 + m) * 128 + (kt) * 8 + seg;                      \
            int bi = (col0 + m) * 128 + (kt) * 8 + seg;                      \
            r[i]      = Ah[ai];                                              \
            r[i + 4]  = Al[ai];                                              \
            r[i + 8]  = Bh[bi];                                              \
            r[i + 12] = Bl[bi];                                              \
        }                                                                    \
    }

#define STS_CHUNK(stg)                                                       \
    {                                                                        \
        uint32_t* base = sm + (stg) * STG_WORDS;                             \
        _Pragma("unroll")                                                    \
        for (int i = 0; i < 4; i++) {                                        \
            int e = tid + i * 256;                                           \
            int m = e >> 3, seg = e & 7;                                     \
            int ks = seg >> 1, kp = (seg & 1) * 4;                           \
            int idx = (ks * 128 + m) * 9 + kp;                               \
            uint32_t* ah = base;                                             \
            uint32_t* al = base + 4608;                                      \
            uint32_t* bh = base + 9216;                                      \
            uint32_t* bl = base + 13824;                                     \
            ah[idx] = r[i].x;      ah[idx+1] = r[i].y;                       \
            ah[idx+2] = r[i].z;    ah[idx+3] = r[i].w;                       \
            al[idx] = r[i+4].x;    al[idx+1] = r[i+4].y;                     \
            al[idx+2] = r[i+4].z;  al[idx+3] = r[i+4].w;                     \
            bh[idx] = r[i+8].x;    bh[idx+1] = r[i+8].y;                     \
            bh[idx+2] = r[i+8].z;  bh[idx+3] = r[i+8].w;                     \
            bl[idx] = r[i+12].x;   bl[idx+1] = r[i+12].y;                    \
            bl[idx+2] = r[i+12].z; bl[idx+3] = r[i+12].w;                    \
        }                                                                    \
    }

    // prologue
    LDG_CHUNK(0);
    STS_CHUNK(0);
    LDG_CHUNK(1);
    __syncthreads();

#pragma unroll 1
    for (int kt = 0; kt < 16; kt++) {
        const int s = kt & 1;
        if (kt < 15) STS_CHUNK(s ^ 1);      // regs hold chunk kt+1
        if (kt < 14) LDG_CHUNK(kt + 2);     // prefetch; overlaps mma below
        __syncthreads();                     // stage s^1 writes visible

        uint32_t* base = sm + s * STG_WORDS;
        const uint32_t* At[3] = { base, base, base + 4608 };
        const uint32_t* Bt[3] = { base + 9216, base + 13824, base + 9216 };
#pragma unroll
        for (int t = 0; t < 3; t++) {
            const uint32_t* Ap = At[t];
            const uint32_t* Bp = Bt[t];
#pragma unroll
            for (int ks = 0; ks < 4; ks++) {
                uint32_t bfr[4][2];
#pragma unroll
                for (int nt = 0; nt < 4; nt++) {
                    int n = warpN * 32 + nt * 8 + lq;
                    int idx = (ks * 128 + n) * 9 + lr;
                    bfr[nt][0] = Bp[idx];
                    bfr[nt][1] = Bp[idx + 4];
                }
#pragma unroll
                for (int mt = 0; mt < 4; mt++) {
                    int rr = warpM * 64 + mt * 16 + lq;
                    int idx = (ks * 128 + rr) * 9 + lr;
                    uint32_t a0 = Ap[idx];
                    uint32_t a1 = Ap[idx + 72];
                    uint32_t a2 = Ap[idx + 4];
                    uint32_t a3 = Ap[idx + 76];
#pragma unroll
                    for (int nt = 0; nt < 4; nt++) {
                        asm volatile(
                            "mma.sync.aligned.m16n8k16.row.col.f32.bf16.bf16.f32 "
                            "{%0,%1,%2,%3}, {%4,%5,%6,%7}, {%8,%9}, {%0,%1,%2,%3};"
                            : "+f"(acc[mt][nt][0]), "+f"(acc[mt][nt][1]),
                              "+f"(acc[mt][nt][2]), "+f"(acc[mt][nt][3])
                            : "r"(a0), "r"(a1), "r"(a2), "r"(a3),
                              "r"(bfr[nt][0]), "r"(bfr[nt][1]));
                    }
                }
            }
        }
        __syncthreads();                     // mma done before stage reuse
    }
#undef LDG_CHUNK
#undef STS_CHUNK

    // ---- epilogue (unchanged from round 9) ----
#pragma unroll
    for (int mt = 0; mt < 4; mt++) {
        int mbase = row0 + warpM * 64 + mt * 16 + lq;
#pragma unroll
        for (int nt = 0; nt < 4; nt++) {
            int nbase = col0 + warpN * 32 + nt * 8 + lr * 2;
#pragma unroll
            for (int q = 0; q < 4; q++) {
                int m = mbase + (q >> 1) * 8;
                int n = nbase + (q & 1);
                float val = acc[mt][nt][q] + __ldg(bias + n);
                if (MODE == 1) {
                    C[(size_t)m * 1024 + n] = val;
                } else {
                    int b = m >> 11;
                    int s = m & 2047;
                    if (n < D_MODEL) {
                        g_q[(size_t)m * D_MODEL + n] = val;
                    } else {
                        int cc = n - D_MODEL;
                        int which = cc >> 10;
                        cc &= 1023;
                        int h = cc >> 6;
                        int d = cc & 63;
                        size_t off = (size_t)which * KV_ELEMS
                                   + (((size_t)(b * N_HEADS + h) * SEQ + s) * HEAD_DIM + d);
                        C[off] = val;
                    }
                }
            }
        }
    }
}

// ---------------------------------------------------------------------------
// Attention (unchanged, passing since round 7).
// ---------------------------------------------------------------------------
__global__ __launch_bounds__(256)
void attn_kernel(const float* __restrict__ kvbuf,
                 const float* __restrict__ pk,
                 const float* __restrict__ pv)
{
    __shared__ float sk[64][64];
    __shared__ float sv[64][64];

    const int tid  = threadIdx.x;
    const int warp = tid >> 5;
    const int lane = tid & 31;
    const int half = lane >> 4;
    const int qi   = (warp << 4) | (lane & 15);
    const int qt   = blockIdx.x;
    const int bh   = blockIdx.y;
    const int qrow = qt * 128 + qi;
    const int b = bh >> 4, h = bh & 15;
    const float MX = 20.0f;

    ull q2[16];
    {
        const ulonglong2* qp = (const ulonglong2*)
            (g_q + ((size_t)(b * SEQ + qrow) * D_MODEL + h * HEAD_DIM + half * 32));
        ull sc2 = pack2(0.125f, 0.125f);
#pragma unroll
        for (int i = 0; i < 8; i++) {
            ulonglong2 t = qp[i];
            q2[2 * i]     = fmul2(t.x, sc2);
            q2[2 * i + 1] = fmul2(t.y, sc2);
        }
    }

    ull acc2[16];
#pragma unroll
    for (int i = 0; i < 16; i++) acc2[i] = 0ull;
    float lsum = 0.0f;

    {
        const size_t mbase = ((size_t)bh * SEQ + qrow) * (LMEM * HEAD_DIM) + half * 32;
#pragma unroll
        for (int l = 0; l < LMEM; l++) {
            const ulonglong2* kp = (const ulonglong2*)(pk + mbase + l * HEAD_DIM);
            ull dot2 = 0ull;
#pragma unroll
            for (int i = 0; i < 8; i++) {
                ulonglong2 kk = kp[i];
                dot2 = ffma2(q2[2 * i], kk.x, dot2);
                dot2 = ffma2(q2[2 * i + 1], kk.y, dot2);
            }
            float dlo, dhi;
            unpack2(dot2, dlo, dhi);
            float d = dlo + dhi;
            d += __shfl_xor_sync(0xFFFFFFFFu, d, 16);
            float p = __expf(d - MX);
            lsum += p;
            ull p2 = pack2(p, p);
            const ulonglong2* vp = (const ulonglong2*)(pv + mbase + l * HEAD_DIM);
#pragma unroll
            for (int i = 0; i < 8; i++) {
                ulonglong2 vv = vp[i];
                acc2[2 * i]     = ffma2(p2, vv.x, acc2[2 * i]);
                acc2[2 * i + 1] = ffma2(p2, vv.y, acc2[2 * i + 1]);
            }
        }
    }

    const float* kb = kvbuf + (size_t)bh * SEQ * HEAD_DIM;
    const float* vb = kvbuf + (size_t)KV_ELEMS + (size_t)bh * SEQ * HEAD_DIM;
    const int nkeys = qt * 128 + 128;
    const int wmax  = qt * 128 + (warp << 4) + 15;

    for (int kt0 = 0; kt0 < nkeys; kt0 += 64) {
#pragma unroll
        for (int i = 0; i < 4; i++) {
            int e = tid + i * 256;
            ((float4*)sk)[e] = ((const float4*)(kb + (size_t)kt0 * HEAD_DIM))[e];
            ((float4*)sv)[e] = ((const float4*)(vb + (size_t)kt0 * HEAD_DIM))[e];
        }
        __syncthreads();

#pragma unroll 1
        for (int c0 = 0; c0 < 64; c0 += 8) {
            if (kt0 + c0 <= wmax) {
                float p[8];
#pragma unroll
                for (int j = 0; j < 8; j++) {
                    const ulonglong2* kr = (const ulonglong2*)&sk[c0 + j][half * 32];
                    ull dot2 = 0ull;
#pragma unroll
                    for (int i = 0; i < 8; i++) {
                        ulonglong2 kk = kr[i];
                        dot2 = ffma2(q2[2 * i], kk.x, dot2);
                        dot2 = ffma2(q2[2 * i + 1], kk.y, dot2);
                    }
                    float dlo, dhi;
                    unpack2(dot2, dlo, dhi);
                    float d = dlo + dhi;
                    d += __shfl_xor_sync(0xFFFFFFFFu, d, 16);
                    int kj = kt0 + c0 + j;
                    p[j] = (kj <= qrow) ? __expf(d - MX) : 0.0f;
                }
#pragma unroll
                for (int j = 0; j < 8; j++) {
                    lsum += p[j];
                    ull p2 = pack2(p[j], p[j]);
                    const ulonglong2* vr = (const ulonglong2*)&sv[c0 + j][half * 32];
#pragma unroll
                    for (int i = 0; i < 8; i++) {
                        ulonglong2 vv = vr[i];
                        acc2[2 * i]     = ffma2(p2, vv.x, acc2[2 * i]);
                        acc2[2 * i + 1] = ffma2(p2, vv.y, acc2[2 * i + 1]);
                    }
                }
            }
        }
        __syncthreads();
    }

    {
        float inv = 1.0f / lsum;
        ull inv2 = pack2(inv, inv);
        ulonglong2* cp = (ulonglong2*)
            (g_ctx + ((size_t)(b * SEQ + qrow) * D_MODEL + h * HEAD_DIM + half * 32));
#pragma unroll
        for (int i = 0; i < 8; i++) {
            ulonglong2 o;
            o.x = fmul2(acc2[2 * i], inv2);
            o.y = fmul2(acc2[2 * i + 1], inv2);
            cp[i] = o;
        }
    }
}

// ---------------------------------------------------------------------------
extern "C" void kernel_launch(void* const* d_in, const int* in_sizes, int n_in,
                              void* d_out, int out_size)
{
    const float* x = 0; const float* pk = 0; const float* pv = 0;
    const float* W_qkv = 0; const float* b_qkv = 0;
    const float* W_out = 0; const float* b_out = 0;
    for (int i = 0; i < n_in; i++) {
        const float* p = (const float*)d_in[i];
        switch (in_sizes[i]) {
            case 4194304:  x = p;      break;
            case 33554432: if (!pk) pk = p; else pv = p; break;
            case 3145728:  W_qkv = p;  break;
            case 3072:     b_qkv = p;  break;
            case 1048576:  W_out = p;  break;
            case 1024:     b_out = p;  break;
            default: break;
        }
    }
    if (!(x && pk && pv && W_qkv && b_qkv && W_out && b_out)) {
        if (n_in < 7) return;
        x     = (const float*)d_in[0];
        pk    = (const float*)d_in[1];
        pv    = (const float*)d_in[2];
        W_qkv = (const float*)d_in[3];
        b_qkv = (const float*)d_in[4];
        W_out = (const float*)d_in[5];
        b_out = (const float*)d_in[6];
    }

    float* out = (float*)d_out;

    static float* s_ctx = nullptr;
    static __nv_bfloat16 *s_ah = nullptr, *s_al = nullptr, *s_bh = nullptr, *s_bl = nullptr;
    if (!s_ctx) {
        void* p = 0;
        cudaGetSymbolAddress(&p, g_ctx);   s_ctx = (float*)p;
        cudaGetSymbolAddress(&p, g_a_hi);  s_ah = (__nv_bfloat16*)p;
        cudaGetSymbolAddress(&p, g_a_lo);  s_al = (__nv_bfloat16*)p;
        cudaGetSymbolAddress(&p, g_bt_hi); s_bh = (__nv_bfloat16*)p;
        cudaGetSymbolAddress(&p, g_bt_lo); s_bl = (__nv_bfloat16*)p;
        cudaFuncSetAttribute((const void*)hgemm_bf<0>,
                             cudaFuncAttributeMaxDynamicSharedMemorySize, HB_SMEM);
        cudaFuncSetAttribute((const void*)hgemm_bf<1>,
                             cudaFuncAttributeMaxDynamicSharedMemorySize, HB_SMEM);
    }

    float* kvbuf = out + OUT_ELEMS;   // [out | k | v] element layout

    // --- prep: split x; split+transpose W_qkv ---
    split_a_kernel<<<OUT_ELEMS / 1024, 256>>>((const float4*)x, (uint2*)s_ah, (uint2*)s_al);
    {
        dim3 grid(3 * D_MODEL / 32, D_MODEL / 32);
        split_wt_kernel<<<grid, dim3(32, 8)>>>(W_qkv, s_bh, s_bl, 3 * D_MODEL);
    }
    // 1) QKV GEMM (tensor cores, pre-split operands)
    {
        dim3 grid(3 * D_MODEL / 128, M_TOT / 128);    // (24, 32)
        hgemm_bf<0><<<grid, 256, HB_SMEM>>>((const uint4*)s_ah, (const uint4*)s_al,
                                            (const uint4*)s_bh, (const uint4*)s_bl,
                                            b_qkv, kvbuf);
    }
    // 2) attention
    {
        dim3 grid(SEQ / 128, BATCH * N_HEADS);        // (16, 32)
        attn_kernel<<<grid, 256>>>(kvbuf, pk, pv);
    }
    // --- prep: split ctx; split+transpose W_out ---
    split_a_kernel<<<OUT_ELEMS / 1024, 256>>>((const float4*)s_ctx, (uint2*)s_ah, (uint2*)s_al);
    {
        dim3 grid(D_MODEL / 32, D_MODEL / 32);
        split_wt_kernel<<<grid, dim3(32, 8)>>>(W_out, s_bh, s_bl, D_MODEL);
    }
    // 3) output GEMM
    {
        dim3 grid(D_MODEL / 128, M_TOT / 128);        // (8, 32)
        hgemm_bf<1><<<grid, 256, HB_SMEM>>>((const uint4*)s_ah, (const uint4*)s_al,
                                            (const uint4*)s_bh, (const uint4*)s_bl,
                                            b_out, out);
    }
}

// round 11
// speedup vs baseline: 2.1042x; 1.4009x over previous
#include <cuda_runtime.h>
#include <cuda_bf16.h>
#include <cstdint>

#define D_MODEL  1024
#define N_HEADS  16
#define HEAD_DIM 64
#define BATCH    2
#define SEQ      2048
#define LMEM     8
#define M_TOT    (BATCH * SEQ)            // 4096
#define OUT_ELEMS (M_TOT * D_MODEL)       // 4194304
#define KV_ELEMS  (BATCH * N_HEADS * SEQ * HEAD_DIM)  // 4194304 each

typedef unsigned long long ull;

// scratch (no cudaMalloc). NEVER pass these directly as host-side kernel args
// (host stub address + GB300 ATS = silent host reads) — use cudaGetSymbolAddress
// or reference in device code.
__device__ float g_q[M_TOT * D_MODEL];
__device__ float g_ctx[M_TOT * D_MODEL];
__device__ __nv_bfloat16 g_a_hi[M_TOT * D_MODEL];        // GEMM A split
__device__ __nv_bfloat16 g_a_lo[M_TOT * D_MODEL];
__device__ __nv_bfloat16 g_bt_hi[3 * D_MODEL * D_MODEL]; // W^T split
__device__ __nv_bfloat16 g_bt_lo[3 * D_MODEL * D_MODEL];
// attention pre-split operands (written by hgemm<0> epilogue)
__device__ __nv_bfloat16 g_qh[M_TOT * D_MODEL];          // q*0.125 hi, [bh][s][d]
__device__ __nv_bfloat16 g_ql[M_TOT * D_MODEL];
__device__ __nv_bfloat16 g_kh[KV_ELEMS];                 // [bh][s][d]
__device__ __nv_bfloat16 g_kl[KV_ELEMS];
__device__ __nv_bfloat16 g_vth[KV_ELEMS];                // [bh][d][s]
__device__ __nv_bfloat16 g_vtl[KV_ELEMS];

// ---- packed fp32x2 helpers ---------------------------------------------------
__device__ __forceinline__ ull ffma2(ull a, ull b, ull c) {
    ull d;
    asm("fma.rn.f32x2 %0, %1, %2, %3;" : "=l"(d) : "l"(a), "l"(b), "l"(c));
    return d;
}
__device__ __forceinline__ ull fmul2(ull a, ull b) {
    ull d;
    asm("mul.rn.f32x2 %0, %1, %2;" : "=l"(d) : "l"(a), "l"(b));
    return d;
}
__device__ __forceinline__ ull pack2(float lo, float hi) {
    ull r;
    asm("mov.b64 %0, {%1, %2};" : "=l"(r) : "f"(lo), "f"(hi));
    return r;
}
__device__ __forceinline__ void unpack2(ull v, float& lo, float& hi) {
    asm("mov.b64 {%0, %1}, %2;" : "=f"(lo), "=f"(hi) : "l"(v));
}

// ---- bf16 helpers --------------------------------------------------------------
__device__ __forceinline__ uint32_t bf2(float lo, float hi) {   // low16=lo, high16=hi
    uint32_t r;
    asm("cvt.rn.bf16x2.f32 %0, %1, %2;" : "=r"(r) : "f"(hi), "f"(lo));
    return r;
}
__device__ __forceinline__ float bf_lo_f(uint32_t h) { return __uint_as_float(h << 16); }
__device__ __forceinline__ float bf_hi_f(uint32_t h) { return __uint_as_float(h & 0xFFFF0000u); }

__device__ __forceinline__ void mma_bf16(float* c,
                                         uint32_t a0, uint32_t a1, uint32_t a2, uint32_t a3,
                                         uint32_t b0, uint32_t b1) {
    asm volatile(
        "mma.sync.aligned.m16n8k16.row.col.f32.bf16.bf16.f32 "
        "{%0,%1,%2,%3}, {%4,%5,%6,%7}, {%8,%9}, {%0,%1,%2,%3};"
        : "+f"(c[0]), "+f"(c[1]), "+f"(c[2]), "+f"(c[3])
        : "r"(a0), "r"(a1), "r"(a2), "r"(a3), "r"(b0), "r"(b1));
}

// ---------------------------------------------------------------------------
// Prep kernels (unchanged, passing)
// ---------------------------------------------------------------------------
__global__ __launch_bounds__(256)
void split_a_kernel(const float4* __restrict__ src,
                    uint2* __restrict__ hi, uint2* __restrict__ lo)
{
    int i = blockIdx.x * 256 + threadIdx.x;
    float4 v = src[i];
    uint32_t h01 = bf2(v.x, v.y), h23 = bf2(v.z, v.w);
    uint32_t l01 = bf2(v.x - bf_lo_f(h01), v.y - bf_hi_f(h01));
    uint32_t l23 = bf2(v.z - bf_lo_f(h23), v.w - bf_hi_f(h23));
    hi[i] = make_uint2(h01, h23);
    lo[i] = make_uint2(l01, l23);
}

__global__ __launch_bounds__(256)
void split_wt_kernel(const float* __restrict__ W,
                     __nv_bfloat16* __restrict__ hiT,
                     __nv_bfloat16* __restrict__ loT,
                     int N)
{
    __shared__ float t[32][33];
    const int tx = threadIdx.x, ty = threadIdx.y;
    const int n0 = blockIdx.x * 32, k0 = blockIdx.y * 32;
#pragma unroll
    for (int i = 0; i < 4; i++)
        t[ty + 8 * i][tx] = W[(size_t)(k0 + ty + 8 * i) * N + n0 + tx];
    __syncthreads();
#pragma unroll
    for (int i = 0; i < 4; i++) {
        int n = n0 + ty + 8 * i;
        float f = t[tx][ty + 8 * i];
        __nv_bfloat16 h = __float2bfloat16(f);
        __nv_bfloat16 l = __float2bfloat16(f - __bfloat162float(h));
        hiT[(size_t)n * 1024 + k0 + tx] = h;
        loT[(size_t)n * 1024 + k0 + tx] = l;
    }
}

// ---------------------------------------------------------------------------
// bf16 mma.sync GEMM (proven round 10). MODE 0 epilogue additionally writes
// pre-split attention operands (q*0.125 hi/lo, k hi/lo, v^T hi/lo).
// ---------------------------------------------------------------------------
#define STG_WORDS 18432
#define HB_SMEM   (2 * STG_WORDS * 4)

template <int MODE>
__global__ __launch_bounds__(256)
void hgemm_bf(const uint4* __restrict__ Ah, const uint4* __restrict__ Al,
              const uint4* __restrict__ Bh, const uint4* __restrict__ Bl,
              const float* __restrict__ bias,
              float* __restrict__ C)
{
    extern __shared__ uint32_t sm[];

    const int tid   = threadIdx.x;
    const int wid   = tid >> 5;
    const int lane  = tid & 31;
    const int warpM = wid & 1;
    const int warpN = wid >> 1;
    const int row0  = blockIdx.y * 128;
    const int col0  = blockIdx.x * 128;
    const int lq    = lane >> 2;
    const int lr    = lane & 3;

    float acc[4][4][4];
#pragma unroll
    for (int a = 0; a < 4; a++)
#pragma unroll
        for (int b = 0; b < 4; b++)
#pragma unroll
            for (int c = 0; c < 4; c++) acc[a][b][c] = 0.0f;

    uint4 r[16];

#define LDG_CHUNK(kt)                                                        \
    {                                                                        \
        _Pragma("unroll")                                                    \
        for (int i = 0; i < 4; i++) {                                        \
            int e = tid + i * 256;                                           \
            int m = e >> 3, seg = e & 7;                                     \
            int ai = (row0 + m) * 128 + (kt) * 8 + seg;                      \
            int bi = (col0 + m) * 128 + (kt) * 8 + seg;                      \
            r[i]      = Ah[ai];                                              \
            r[i + 4]  = Al[ai];                                              \
            r[i + 8]  = Bh[bi];                                              \
            r[i + 12] = Bl[bi];                                              \
        }                                                                    \
    }

#define STS_CHUNK(stg)                                                       \
    {                                                                        \
        uint32_t* base = sm + (stg) * STG_WORDS;                             \
        _Pragma("unroll")                                                    \
        for (int i = 0; i < 4; i++) {                                        \
            int e = tid + i * 256;                                           \
            int m = e >> 3, seg = e & 7;                                     \
            int ks = seg >> 1, kp = (seg & 1) * 4;                           \
            int idx = (ks * 128 + m) * 9 + kp;                               \
            uint32_t* ah = base;                                             \
            uint32_t* al = base + 4608;                                      \
            uint32_t* bh = base + 9216;                                      \
            uint32_t* bl = base + 13824;                                     \
            ah[idx] = r[i].x;      ah[idx+1] = r[i].y;                       \
            ah[idx+2] = r[i].z;    ah[idx+3] = r[i].w;                       \
            al[idx] = r[i+4].x;    al[idx+1] = r[i+4].y;                     \
            al[idx+2] = r[i+4].z;  al[idx+3] = r[i+4].w;                     \
            bh[idx] = r[i+8].x;    bh[idx+1] = r[i+8].y;                     \
            bh[idx+2] = r[i+8].z;  bh[idx+3] = r[i+8].w;                     \
            bl[idx] = r[i+12].x;   bl[idx+1] = r[i+12].y;                    \
            bl[idx+2] = r[i+12].z; bl[idx+3] = r[i+12].w;                    \
        }                                                                    \
    }

    LDG_CHUNK(0);
    STS_CHUNK(0);
    LDG_CHUNK(1);
    __syncthreads();

#pragma unroll 1
    for (int kt = 0; kt < 16; kt++) {
        const int s = kt & 1;
        if (kt < 15) STS_CHUNK(s ^ 1);
        if (kt < 14) LDG_CHUNK(kt + 2);
        __syncthreads();

        uint32_t* base = sm + s * STG_WORDS;
        const uint32_t* At[3] = { base, base, base + 4608 };
        const uint32_t* Bt[3] = { base + 9216, base + 13824, base + 9216 };
#pragma unroll
        for (int t = 0; t < 3; t++) {
            const uint32_t* Ap = At[t];
            const uint32_t* Bp = Bt[t];
#pragma unroll
            for (int ks = 0; ks < 4; ks++) {
                uint32_t bfr[4][2];
#pragma unroll
                for (int nt = 0; nt < 4; nt++) {
                    int n = warpN * 32 + nt * 8 + lq;
                    int idx = (ks * 128 + n) * 9 + lr;
                    bfr[nt][0] = Bp[idx];
                    bfr[nt][1] = Bp[idx + 4];
                }
#pragma unroll
                for (int mt = 0; mt < 4; mt++) {
                    int rr = warpM * 64 + mt * 16 + lq;
                    int idx = (ks * 128 + rr) * 9 + lr;
                    uint32_t a0 = Ap[idx];
                    uint32_t a1 = Ap[idx + 72];
                    uint32_t a2 = Ap[idx + 4];
                    uint32_t a3 = Ap[idx + 76];
#pragma unroll
                    for (int nt = 0; nt < 4; nt++)
                        mma_bf16(acc[mt][nt], a0, a1, a2, a3,
                                 bfr[nt][0], bfr[nt][1]);
                }
            }
        }
        __syncthreads();
    }
#undef LDG_CHUNK
#undef STS_CHUNK

#pragma unroll
    for (int mt = 0; mt < 4; mt++) {
        int mbase = row0 + warpM * 64 + mt * 16 + lq;
#pragma unroll
        for (int nt = 0; nt < 4; nt++) {
            int nbase = col0 + warpN * 32 + nt * 8 + lr * 2;
#pragma unroll
            for (int q = 0; q < 4; q++) {
                int m = mbase + (q >> 1) * 8;
                int n = nbase + (q & 1);
                float val = acc[mt][nt][q] + __ldg(bias + n);
                if (MODE == 1) {
                    C[(size_t)m * 1024 + n] = val;
                } else {
                    int b = m >> 11;
                    int s = m & 2047;
                    if (n < D_MODEL) {
                        g_q[(size_t)m * D_MODEL + n] = val;
                        float qs = val * 0.125f;
                        __nv_bfloat16 hh = __float2bfloat16(qs);
                        __nv_bfloat16 ll = __float2bfloat16(qs - __bfloat162float(hh));
                        size_t qo = ((size_t)(b * N_HEADS + (n >> 6)) * SEQ + s) * 64
                                  + (n & 63);
                        g_qh[qo] = hh; g_ql[qo] = ll;
                    } else {
                        int cc = n - D_MODEL;
                        int which = cc >> 10;
                        cc &= 1023;
                        int h = cc >> 6;
                        int d = cc & 63;
                        size_t so = ((size_t)(b * N_HEADS + h) * SEQ + s) * 64 + d;
                        C[(size_t)which * KV_ELEMS + so] = val;
                        __nv_bfloat16 hh = __float2bfloat16(val);
                        __nv_bfloat16 ll = __float2bfloat16(val - __bfloat162float(hh));
                        if (which == 0) {
                            g_kh[so] = hh; g_kl[so] = ll;
                        } else {
                            size_t vo = ((size_t)(b * N_HEADS + h) * 64 + d) * SEQ + s;
                            g_vth[vo] = hh; g_vtl[vo] = ll;
                        }
                    }
                }
            }
        }
    }
}

// ---------------------------------------------------------------------------
// Flash attention on mma.sync. CTA = (b, h, 128-query tile), 8 warps.
// Warp w owns S/O tile rows [w*16, w*16+16). Static softmax base MX=20.
// SMEM words: Qh[4608] Ql[4608] | stage 2x(Kh,Kl,Vh,Vl 2304 each) | macc 8192 | mlsum 128
// ---------------------------------------------------------------------------
#define AT_WORDS (9216 + 18432 + 8192 + 128)
#define AT_SMEM  (AT_WORDS * 4)

__global__ __launch_bounds__(256)
void attn_mma(const float* __restrict__ pk, const float* __restrict__ pv)
{
    extern __shared__ uint32_t sm[];
    uint32_t* Qhs  = sm;
    uint32_t* Qls  = sm + 4608;
    uint32_t* stg  = sm + 9216;
    float*    macc = (float*)(sm + 27648);
    float*    msum = (float*)(sm + 35840);

    const int tid = threadIdx.x;
    const int wid = tid >> 5;
    const int lane = tid & 31;
    const int lq = lane >> 2;
    const int lr = lane & 3;
    const int qt = blockIdx.x;
    const int bh = blockIdx.y;
    const int b = bh >> 4, h = bh & 15;
    const float MX = 20.0f;

    const uint4* Qh4 = (const uint4*)g_qh;
    const uint4* Ql4 = (const uint4*)g_ql;
    const uint4* Kh4 = (const uint4*)g_kh;
    const uint4* Kl4 = (const uint4*)g_kl;
    const uint4* Vh4 = (const uint4*)g_vth;
    const uint4* Vl4 = (const uint4*)g_vtl;

    // ---- Phase A: stage Q tile (128 x 64) hi/lo into fragment layout ----
    {
        const size_t q0 = ((size_t)bh * SEQ + qt * 128) * 8;   // uint4 units
#pragma unroll
        for (int i = 0; i < 4; i++) {
            int e = tid + i * 256;
            int m = e >> 3, seg = e & 7;
            uint4 vh = Qh4[q0 + m * 8 + seg];
            uint4 vl = Ql4[q0 + m * 8 + seg];
            int idx = ((seg >> 1) * 128 + m) * 9 + (seg & 1) * 4;
            Qhs[idx] = vh.x; Qhs[idx+1] = vh.y; Qhs[idx+2] = vh.z; Qhs[idx+3] = vh.w;
            Qls[idx] = vl.x; Qls[idx+1] = vl.y; Qls[idx+2] = vl.z; Qls[idx+3] = vl.w;
        }
    }

    // ---- Phase B: memory attention (8 keys/query) -> macc, msum ----
    {
        const int qi = tid >> 1, half = tid & 1;
        const int qrow = qt * 128 + qi;
        ull q2[16];
        {
            const ulonglong2* qp = (const ulonglong2*)
                (g_q + ((size_t)(b * SEQ + qrow) * D_MODEL + h * HEAD_DIM + half * 32));
            ull sc2 = pack2(0.125f, 0.125f);
#pragma unroll
            for (int i = 0; i < 8; i++) {
                ulonglong2 t = qp[i];
                q2[2 * i]     = fmul2(t.x, sc2);
                q2[2 * i + 1] = fmul2(t.y, sc2);
            }
        }
        ull acc2[16];
#pragma unroll
        for (int i = 0; i < 16; i++) acc2[i] = 0ull;
        float lsum = 0.0f;
        const size_t mbase = ((size_t)bh * SEQ + qrow) * (LMEM * HEAD_DIM) + half * 32;
#pragma unroll
        for (int l = 0; l < LMEM; l++) {
            const ulonglong2* kp = (const ulonglong2*)(pk + mbase + l * HEAD_DIM);
            ull dot2 = 0ull;
#pragma unroll
            for (int i = 0; i < 8; i++) {
                ulonglong2 kk = kp[i];
                dot2 = ffma2(q2[2 * i], kk.x, dot2);
                dot2 = ffma2(q2[2 * i + 1], kk.y, dot2);
            }
            float dlo, dhi;
            unpack2(dot2, dlo, dhi);
            float d = dlo + dhi;
            d += __shfl_xor_sync(0xFFFFFFFFu, d, 1);
            float p = __expf(d - MX);
            lsum += p;
            ull p2 = pack2(p, p);
            const ulonglong2* vp = (const ulonglong2*)(pv + mbase + l * HEAD_DIM);
#pragma unroll
            for (int i = 0; i < 8; i++) {
                ulonglong2 vv = vp[i];
                acc2[2 * i]     = ffma2(p2, vv.x, acc2[2 * i]);
                acc2[2 * i + 1] = ffma2(p2, vv.y, acc2[2 * i + 1]);
            }
        }
        ull* mp = (ull*)(macc + qi * 64 + half * 32);
#pragma unroll
        for (int i = 0; i < 16; i++) mp[i] = acc2[i];
        if (!half) msum[qi] = lsum;
    }
    __syncthreads();

    // ---- main loop over 64-key chunks (double-buffered) ----
    const int nch = 2 * qt + 2;
    const int gr0 = qt * 128 + wid * 16;
    uint4 r[8];

#define LDGKV(c)                                                             \
    {                                                                        \
        int kt0 = (c) * 64;                                                  \
        _Pragma("unroll")                                                    \
        for (int i = 0; i < 2; i++) {                                        \
            int e = tid + i * 256;                                           \
            int m = e >> 3, seg = e & 7;                                     \
            size_t ki = ((size_t)bh * SEQ + kt0 + m) * 8 + seg;              \
            size_t vi = ((size_t)bh * 64 + m) * 256 + (kt0 >> 3) + seg;      \
            r[i]     = Kh4[ki];                                              \
            r[i + 2] = Kl4[ki];                                              \
            r[i + 4] = Vh4[vi];                                              \
            r[i + 6] = Vl4[vi];                                              \
        }                                                                    \
    }
#define STSKV(s)                                                             \
    {                                                                        \
        uint32_t* base = stg + (s) * 9216;                                   \
        _Pragma("unroll")                                                    \
        for (int i = 0; i < 2; i++) {                                        \
            int e = tid + i * 256;                                           \
            int m = e >> 3, seg = e & 7;                                     \
            int idx = ((seg >> 1) * 64 + m) * 9 + (seg & 1) * 4;             \
            uint32_t* kh = base;                                             \
            uint32_t* kl = base + 2304;                                      \
            uint32_t* vh = base + 4608;                                      \
            uint32_t* vl = base + 6912;                                      \
            kh[idx] = r[i].x;     kh[idx+1] = r[i].y;                        \
            kh[idx+2] = r[i].z;   kh[idx+3] = r[i].w;                        \
            kl[idx] = r[i+2].x;   kl[idx+1] = r[i+2].y;                      \
            kl[idx+2] = r[i+2].z; kl[idx+3] = r[i+2].w;                      \
            vh[idx] = r[i+4].x;   vh[idx+1] = r[i+4].y;                      \
            vh[idx+2] = r[i+4].z; vh[idx+3] = r[i+4].w;                      \
            vl[idx] = r[i+6].x;   vl[idx+1] = r[i+6].y;                      \
            vl[idx+2] = r[i+6].z; vl[idx+3] = r[i+6].w;                      \
        }                                                                    \
    }

    LDGKV(0);
    STSKV(0);
    LDGKV(1);
    __syncthreads();

    float O[8][4];
#pragma unroll
    for (int nb = 0; nb < 8; nb++)
#pragma unroll
        for (int q = 0; q < 4; q++) O[nb][q] = 0.0f;
    float lsum0 = 0.0f, lsum1 = 0.0f;

#pragma unroll 1
    for (int c = 0; c < nch; c++) {
        const int s = c & 1;
        if (c + 1 < nch) STSKV(s ^ 1);
        if (c + 2 < nch) LDGKV(c + 2);
        __syncthreads();

        const int kt0 = c * 64;
        if (kt0 <= gr0 + 15) {
            uint32_t* Khs = stg + s * 9216;
            uint32_t* Kls = Khs + 2304;
            uint32_t* Vhs = Khs + 4608;
            uint32_t* Vls = Khs + 6912;

            // S = Q . K^T (3-term hi/lo)
            float S[8][4];
#pragma unroll
            for (int nb = 0; nb < 8; nb++)
#pragma unroll
                for (int q = 0; q < 4; q++) S[nb][q] = 0.0f;
#pragma unroll
            for (int ks = 0; ks < 4; ks++) {
                int aidx = (ks * 128 + wid * 16 + lq) * 9 + lr;
                uint32_t ah0 = Qhs[aidx], ah1 = Qhs[aidx + 72];
                uint32_t ah2 = Qhs[aidx + 4], ah3 = Qhs[aidx + 76];
                uint32_t al0 = Qls[aidx], al1 = Qls[aidx + 72];
                uint32_t al2 = Qls[aidx + 4], al3 = Qls[aidx + 76];
#pragma unroll
                for (int nb = 0; nb < 8; nb++) {
                    int bidx = (ks * 64 + nb * 8 + lq) * 9 + lr;
                    uint32_t bh0 = Khs[bidx], bh1 = Khs[bidx + 4];
                    uint32_t bl0 = Kls[bidx], bl1 = Kls[bidx + 4];
                    mma_bf16(S[nb], ah0, ah1, ah2, ah3, bh0, bh1);
                    mma_bf16(S[nb], ah0, ah1, ah2, ah3, bl0, bl1);
                    mma_bf16(S[nb], al0, al1, al2, al3, bh0, bh1);
                }
            }
            // masked exp (static base)
            const int r0 = gr0 + lq, r1 = r0 + 8;
            float p[8][4];
#pragma unroll
            for (int nb = 0; nb < 8; nb++) {
                int c0 = kt0 + nb * 8 + 2 * lr;
                p[nb][0] = (c0     <= r0) ? __expf(S[nb][0] - MX) : 0.0f;
                p[nb][1] = (c0 + 1 <= r0) ? __expf(S[nb][1] - MX) : 0.0f;
                p[nb][2] = (c0     <= r1) ? __expf(S[nb][2] - MX) : 0.0f;
                p[nb][3] = (c0 + 1 <= r1) ? __expf(S[nb][3] - MX) : 0.0f;
                lsum0 += p[nb][0] + p[nb][1];
                lsum1 += p[nb][2] + p[nb][3];
            }
            // O += P . V  (P hi/lo via FA2 fragment-reuse; 3-term)
#pragma unroll
            for (int ks = 0; ks < 4; ks++) {
                uint32_t ph0 = bf2(p[2*ks][0],   p[2*ks][1]);
                uint32_t ph1 = bf2(p[2*ks][2],   p[2*ks][3]);
                uint32_t ph2 = bf2(p[2*ks+1][0], p[2*ks+1][1]);
                uint32_t ph3 = bf2(p[2*ks+1][2], p[2*ks+1][3]);
                uint32_t pl0 = bf2(p[2*ks][0] - bf_lo_f(ph0),   p[2*ks][1] - bf_hi_f(ph0));
                uint32_t pl1 = bf2(p[2*ks][2] - bf_lo_f(ph1),   p[2*ks][3] - bf_hi_f(ph1));
                uint32_t pl2 = bf2(p[2*ks+1][0] - bf_lo_f(ph2), p[2*ks+1][1] - bf_hi_f(ph2));
                uint32_t pl3 = bf2(p[2*ks+1][2] - bf_lo_f(ph3), p[2*ks+1][3] - bf_hi_f(ph3));
#pragma unroll
                for (int nb = 0; nb < 8; nb++) {
                    int bidx = (ks * 64 + nb * 8 + lq) * 9 + lr;
                    uint32_t vh0 = Vhs[bidx], vh1 = Vhs[bidx + 4];
                    uint32_t vl0 = Vls[bidx], vl1 = Vls[bidx + 4];
                    mma_bf16(O[nb], ph0, ph1, ph2, ph3, vh0, vh1);
                    mma_bf16(O[nb], pl0, pl1, pl2, pl3, vh0, vh1);
                    mma_bf16(O[nb], ph0, ph1, ph2, ph3, vl0, vl1);
                }
            }
        }
        __syncthreads();
    }
#undef LDGKV
#undef STSKV

    // ---- epilogue: merge token + memory, normalize, write ctx ----
    lsum0 += __shfl_xor_sync(0xFFFFFFFFu, lsum0, 1);
    lsum0 += __shfl_xor_sync(0xFFFFFFFFu, lsum0, 2);
    lsum1 += __shfl_xor_sync(0xFFFFFFFFu, lsum1, 1);
    lsum1 += __shfl_xor_sync(0xFFFFFFFFu, lsum1, 2);

    const int rl0 = wid * 16 + lq, rl1 = rl0 + 8;
    const float inv0 = 1.0f / (lsum0 + msum[rl0]);
    const float inv1 = 1.0f / (lsum1 + msum[rl1]);
    float* c0p = g_ctx + ((size_t)(b * SEQ + qt * 128 + rl0)) * D_MODEL + h * HEAD_DIM;
    float* c1p = g_ctx + ((size_t)(b * SEQ + qt * 128 + rl1)) * D_MODEL + h * HEAD_DIM;
#pragma unroll
    for (int nb = 0; nb < 8; nb++) {
        int col = nb * 8 + 2 * lr;
        float2 m0 = *(float2*)(macc + rl0 * 64 + col);
        float2 m1 = *(float2*)(macc + rl1 * 64 + col);
        float2 o0, o1;
        o0.x = (O[nb][0] + m0.x) * inv0;
        o0.y = (O[nb][1] + m0.y) * inv0;
        o1.x = (O[nb][2] + m1.x) * inv1;
        o1.y = (O[nb][3] + m1.y) * inv1;
        *(float2*)(c0p + col) = o0;
        *(float2*)(c1p + col) = o1;
    }
}

// ---------------------------------------------------------------------------
extern "C" void kernel_launch(void* const* d_in, const int* in_sizes, int n_in,
                              void* d_out, int out_size)
{
    const float* x = 0; const float* pk = 0; const float* pv = 0;
    const float* W_qkv = 0; const float* b_qkv = 0;
    const float* W_out = 0; const float* b_out = 0;
    for (int i = 0; i < n_in; i++) {
        const float* p = (const float*)d_in[i];
        switch (in_sizes[i]) {
            case 4194304:  x = p;      break;
            case 33554432: if (!pk) pk = p; else pv = p; break;
            case 3145728:  W_qkv = p;  break;
            case 3072:     b_qkv = p;  break;
            case 1048576:  W_out = p;  break;
            case 1024:     b_out = p;  break;
            default: break;
        }
    }
    if (!(x && pk && pv && W_qkv && b_qkv && W_out && b_out)) {
        if (n_in < 7) return;
        x     = (const float*)d_in[0];
        pk    = (const float*)d_in[1];
        pv    = (const float*)d_in[2];
        W_qkv = (const float*)d_in[3];
        b_qkv = (const float*)d_in[4];
        W_out = (const float*)d_in[5];
        b_out = (const float*)d_in[6];
    }

    float* out = (float*)d_out;

    static float* s_ctx = nullptr;
    static __nv_bfloat16 *s_ah = nullptr, *s_al = nullptr, *s_bh = nullptr, *s_bl = nullptr;
    if (!s_ctx) {
        void* p = 0;
        cudaGetSymbolAddress(&p, g_ctx);   s_ctx = (float*)p;
        cudaGetSymbolAddress(&p, g_a_hi);  s_ah = (__nv_bfloat16*)p;
        cudaGetSymbolAddress(&p, g_a_lo);  s_al = (__nv_bfloat16*)p;
        cudaGetSymbolAddress(&p, g_bt_hi); s_bh = (__nv_bfloat16*)p;
        cudaGetSymbolAddress(&p, g_bt_lo); s_bl = (__nv_bfloat16*)p;
        cudaFuncSetAttribute((const void*)hgemm_bf<0>,
                             cudaFuncAttributeMaxDynamicSharedMemorySize, HB_SMEM);
        cudaFuncSetAttribute((const void*)hgemm_bf<1>,
                             cudaFuncAttributeMaxDynamicSharedMemorySize, HB_SMEM);
        cudaFuncSetAttribute((const void*)attn_mma,
                             cudaFuncAttributeMaxDynamicSharedMemorySize, AT_SMEM);
    }

    float* kvbuf = out + OUT_ELEMS;   // [out | k | v] element layout

    // prep: split x; split+transpose W_qkv
    split_a_kernel<<<OUT_ELEMS / 1024, 256>>>((const float4*)x, (uint2*)s_ah, (uint2*)s_al);
    {
        dim3 grid(3 * D_MODEL / 32, D_MODEL / 32);
        split_wt_kernel<<<grid, dim3(32, 8)>>>(W_qkv, s_bh, s_bl, 3 * D_MODEL);
    }
    // 1) QKV GEMM (also emits pre-split q/k/v^T for attention)
    {
        dim3 grid(3 * D_MODEL / 128, M_TOT / 128);
        hgemm_bf<0><<<grid, 256, HB_SMEM>>>((const uint4*)s_ah, (const uint4*)s_al,
                                            (const uint4*)s_bh, (const uint4*)s_bl,
                                            b_qkv, kvbuf);
    }
    // 2) flash attention on tensor cores
    {
        dim3 grid(SEQ / 128, BATCH * N_HEADS);
        attn_mma<<<grid, 256, AT_SMEM>>>(pk, pv);
    }
    // prep: split ctx; split+transpose W_out
    split_a_kernel<<<OUT_ELEMS / 1024, 256>>>((const float4*)s_ctx, (uint2*)s_ah, (uint2*)s_al);
    {
        dim3 grid(D_MODEL / 32, D_MODEL / 32);
        split_wt_kernel<<<grid, dim3(32, 8)>>>(W_out, s_bh, s_bl, D_MODEL);
    }
    // 3) output GEMM
    {
        dim3 grid(D_MODEL / 128, M_TOT / 128);
        hgemm_bf<1><<<grid, 256, HB_SMEM>>>((const uint4*)s_ah, (const uint4*)s_al,
                                            (const uint4*)s_bh, (const uint4*)s_bl,
                                            b_out, out);
    }
}

// round 13
// speedup vs baseline: 2.3582x; 1.1207x over previous
#include <cuda_runtime.h>
#include <cuda_bf16.h>
#include <cstdint>

#define D_MODEL  1024
#define N_HEADS  16
#define HEAD_DIM 64
#define BATCH    2
#define SEQ      2048
#define LMEM     8
#define M_TOT    (BATCH * SEQ)            // 4096
#define OUT_ELEMS (M_TOT * D_MODEL)       // 4194304
#define KV_ELEMS  (BATCH * N_HEADS * SEQ * HEAD_DIM)  // 4194304 each

typedef unsigned long long ull;

// scratch (no cudaMalloc). NEVER pass these directly as host-side kernel args
// (host stub address + GB300 ATS = silent host reads) — use cudaGetSymbolAddress
// or reference in device code.
__device__ float g_q[M_TOT * D_MODEL];
__device__ float g_ctx[M_TOT * D_MODEL];           // memattn macc lives here
__device__ float g_msum[BATCH * N_HEADS * SEQ];    // memattn partial softmax sums
__device__ __nv_bfloat16 g_a_hi[M_TOT * D_MODEL];  // GEMM A split (x, then ctx)
__device__ __nv_bfloat16 g_a_lo[M_TOT * D_MODEL];
__device__ __nv_bfloat16 g_bt_hi[3 * D_MODEL * D_MODEL];
__device__ __nv_bfloat16 g_bt_lo[3 * D_MODEL * D_MODEL];
__device__ __nv_bfloat16 g_qh[M_TOT * D_MODEL];    // q*0.125 hi/lo, [bh][s][d]
__device__ __nv_bfloat16 g_ql[M_TOT * D_MODEL];
__device__ __nv_bfloat16 g_kh[KV_ELEMS];           // [bh][s][d]
__device__ __nv_bfloat16 g_kl[KV_ELEMS];
__device__ __nv_bfloat16 g_vth[KV_ELEMS];          // [bh][d][s]
__device__ __nv_bfloat16 g_vtl[KV_ELEMS];

// ---- packed fp32x2 helpers ---------------------------------------------------
__device__ __forceinline__ ull ffma2(ull a, ull b, ull c) {
    ull d;
    asm("fma.rn.f32x2 %0, %1, %2, %3;" : "=l"(d) : "l"(a), "l"(b), "l"(c));
    return d;
}
__device__ __forceinline__ ull fmul2(ull a, ull b) {
    ull d;
    asm("mul.rn.f32x2 %0, %1, %2;" : "=l"(d) : "l"(a), "l"(b));
    return d;
}
__device__ __forceinline__ ull pack2(float lo, float hi) {
    ull r;
    asm("mov.b64 %0, {%1, %2};" : "=l"(r) : "f"(lo), "f"(hi));
    return r;
}
__device__ __forceinline__ void unpack2(ull v, float& lo, float& hi) {
    asm("mov.b64 {%0, %1}, %2;" : "=f"(lo), "=f"(hi) : "l"(v));
}

// ---- bf16 helpers ------------------------------------------------------------
__device__ __forceinline__ uint32_t bf2(float lo, float hi) {   // low16=lo, high16=hi
    uint32_t r;
    asm("cvt.rn.bf16x2.f32 %0, %1, %2;" : "=r"(r) : "f"(hi), "f"(lo));
    return r;
}
__device__ __forceinline__ float bf_lo_f(uint32_t h) { return __uint_as_float(h << 16); }
__device__ __forceinline__ float bf_hi_f(uint32_t h) { return __uint_as_float(h & 0xFFFF0000u); }

__device__ __forceinline__ void mma_bf16(float* c,
                                         uint32_t a0, uint32_t a1, uint32_t a2, uint32_t a3,
                                         uint32_t b0, uint32_t b1) {
    asm volatile(
        "mma.sync.aligned.m16n8k16.row.col.f32.bf16.bf16.f32 "
        "{%0,%1,%2,%3}, {%4,%5,%6,%7}, {%8,%9}, {%0,%1,%2,%3};"
        : "+f"(c[0]), "+f"(c[1]), "+f"(c[2]), "+f"(c[3])
        : "r"(a0), "r"(a1), "r"(a2), "r"(a3), "r"(b0), "r"(b1));
}

// ---- cp.async (base sm_80 ISA; LDGSTS). SMEM dst MUST be 16B aligned. ---------
__device__ __forceinline__ uint32_t smem_u32(const void* p) {
    uint32_t a;
    asm("{ .reg .u64 t; cvta.to.shared.u64 t, %1; cvt.u32.u64 %0, t; }"
        : "=r"(a) : "l"(p));
    return a;
}
__device__ __forceinline__ void cpa16(uint32_t smaddr, const void* gptr) {
    asm volatile("cp.async.cg.shared.global [%0], [%1], 16;"
                 :: "r"(smaddr), "l"(__cvta_generic_to_global(gptr)));
}
__device__ __forceinline__ void cpc() {
    asm volatile("cp.async.commit_group;");
}
template <int N>
__device__ __forceinline__ void cpw() {
    asm volatile("cp.async.wait_group %0;" :: "n"(N));
}

// ---------------------------------------------------------------------------
// Prep kernels (proven)
// ---------------------------------------------------------------------------
__global__ __launch_bounds__(256)
void split_a_kernel(const float4* __restrict__ src,
                    uint2* __restrict__ hi, uint2* __restrict__ lo)
{
    int i = blockIdx.x * 256 + threadIdx.x;
    float4 v = src[i];
    uint32_t h01 = bf2(v.x, v.y), h23 = bf2(v.z, v.w);
    uint32_t l01 = bf2(v.x - bf_lo_f(h01), v.y - bf_hi_f(h01));
    uint32_t l23 = bf2(v.z - bf_lo_f(h23), v.w - bf_hi_f(h23));
    hi[i] = make_uint2(h01, h23);
    lo[i] = make_uint2(l01, l23);
}

__global__ __launch_bounds__(256)
void split_wt_kernel(const float* __restrict__ W,
                     __nv_bfloat16* __restrict__ hiT,
                     __nv_bfloat16* __restrict__ loT,
                     int N)
{
    __shared__ float t[32][33];
    const int tx = threadIdx.x, ty = threadIdx.y;
    const int n0 = blockIdx.x * 32, k0 = blockIdx.y * 32;
#pragma unroll
    for (int i = 0; i < 4; i++)
        t[ty + 8 * i][tx] = W[(size_t)(k0 + ty + 8 * i) * N + n0 + tx];
    __syncthreads();
#pragma unroll
    for (int i = 0; i < 4; i++) {
        int n = n0 + ty + 8 * i;
        float f = t[tx][ty + 8 * i];
        __nv_bfloat16 h = __float2bfloat16(f);
        __nv_bfloat16 l = __float2bfloat16(f - __bfloat162float(h));
        hiT[(size_t)n * 1024 + k0 + tx] = h;
        loT[(size_t)n * 1024 + k0 + tx] = l;
    }
}

// ---------------------------------------------------------------------------
// Memory attention (8 keys/query): macc -> g_ctx, lsum -> g_msum.
// ---------------------------------------------------------------------------
__global__ __launch_bounds__(256)
void memattn_kernel(const float* __restrict__ pk, const float* __restrict__ pv)
{
    const int tid = threadIdx.x;
    const int qi = tid >> 1, half = tid & 1;
    const int qt = blockIdx.x, bh = blockIdx.y;
    const int b = bh >> 4, h = bh & 15;
    const int qrow = qt * 128 + qi;
    const float MX = 20.0f;

    ull q2[16];
    {
        const ulonglong2* qp = (const ulonglong2*)
            (g_q + ((size_t)(b * SEQ + qrow) * D_MODEL + h * HEAD_DIM + half * 32));
        ull sc2 = pack2(0.125f, 0.125f);
#pragma unroll
        for (int i = 0; i < 8; i++) {
            ulonglong2 t = qp[i];
            q2[2 * i]     = fmul2(t.x, sc2);
            q2[2 * i + 1] = fmul2(t.y, sc2);
        }
    }
    ull acc2[16];
#pragma unroll
    for (int i = 0; i < 16; i++) acc2[i] = 0ull;
    float lsum = 0.0f;

    const size_t mbase = ((size_t)bh * SEQ + qrow) * (LMEM * HEAD_DIM) + half * 32;
#pragma unroll
    for (int l = 0; l < LMEM; l++) {
        const ulonglong2* kp = (const ulonglong2*)(pk + mbase + l * HEAD_DIM);
        ull dot2 = 0ull;
#pragma unroll
        for (int i = 0; i < 8; i++) {
            ulonglong2 kk = kp[i];
            dot2 = ffma2(q2[2 * i], kk.x, dot2);
            dot2 = ffma2(q2[2 * i + 1], kk.y, dot2);
        }
        float dlo, dhi;
        unpack2(dot2, dlo, dhi);
        float d = dlo + dhi;
        d += __shfl_xor_sync(0xFFFFFFFFu, d, 1);
        float p = __expf(d - MX);
        lsum += p;
        ull p2 = pack2(p, p);
        const ulonglong2* vp = (const ulonglong2*)(pv + mbase + l * HEAD_DIM);
#pragma unroll
        for (int i = 0; i < 8; i++) {
            ulonglong2 vv = vp[i];
            acc2[2 * i]     = ffma2(p2, vv.x, acc2[2 * i]);
            acc2[2 * i + 1] = ffma2(p2, vv.y, acc2[2 * i + 1]);
        }
    }
    ull* mp = (ull*)(g_ctx + ((size_t)(b * SEQ + qrow)) * D_MODEL + h * HEAD_DIM + half * 32);
#pragma unroll
    for (int i = 0; i < 16; i++) mp[i] = acc2[i];
    if (!half) g_msum[(size_t)bh * SEQ + qrow] = lsum;
}

// ---------------------------------------------------------------------------
// bf16 mma.sync GEMM, hi/lo 3-term. cp.async double-buffered, K=32 chunks.
// PITCH-12 rows (48B): 16B-aligned for cp.async AND conflict-free fragments.
// Per stage: 4 arrays x 2ks x 128 x 12 = 12288 words (48KB); 2 stages = 96KB.
// ---------------------------------------------------------------------------
#define HG_ARR 3072                        // words per array (2*128*12)
#define HG_STG (4 * HG_ARR)                // 12288 words per stage
#define HB_SMEM (2 * HG_STG * 4)           // 98304 B

template <int MODE>
__global__ __launch_bounds__(256, 2)
void hgemm_bf(const uint4* __restrict__ Ah, const uint4* __restrict__ Al,
              const uint4* __restrict__ Bh, const uint4* __restrict__ Bl,
              const float* __restrict__ bias,
              float* __restrict__ C)
{
    extern __shared__ uint32_t sm[];
    const uint32_t smb = smem_u32(sm);

    const int tid   = threadIdx.x;
    const int wid   = tid >> 5;
    const int lane  = tid & 31;
    const int warpM = wid & 1;
    const int warpN = wid >> 1;
    const int row0  = blockIdx.y * 128;
    const int col0  = blockIdx.x * 128;
    const int lq    = lane >> 2;
    const int lr    = lane & 3;

    float acc[4][4][4];
#pragma unroll
    for (int a = 0; a < 4; a++)
#pragma unroll
        for (int b = 0; b < 4; b++)
#pragma unroll
            for (int c = 0; c < 4; c++) acc[a][b][c] = 0.0f;

#define CPA_CHUNK(kt, stg)                                                   \
    {                                                                        \
        uint32_t sb = smb + (stg) * (HG_STG * 4);                            \
        _Pragma("unroll")                                                    \
        for (int i = 0; i < 2; i++) {                                        \
            int e = tid + i * 256;                                           \
            int m = e >> 2, seg = e & 3;                                     \
            uint32_t idx = (uint32_t)(((((seg >> 1) * 128 + m) * 12) + (seg & 1) * 4) * 4); \
            size_t ga = (size_t)(row0 + m) * 128 + (size_t)(kt) * 4 + seg;   \
            size_t gb = (size_t)(col0 + m) * 128 + (size_t)(kt) * 4 + seg;   \
            cpa16(sb + idx,                Ah + ga);                         \
            cpa16(sb + HG_ARR * 4 + idx,   Al + ga);                         \
            cpa16(sb + HG_ARR * 8 + idx,   Bh + gb);                         \
            cpa16(sb + HG_ARR * 12 + idx,  Bl + gb);                         \
        }                                                                    \
        cpc();                                                               \
    }

    CPA_CHUNK(0, 0);
    CPA_CHUNK(1, 1);

#pragma unroll 1
    for (int kt = 0; kt < 32; kt++) {
        const int s = kt & 1;
        if (kt + 1 < 32) cpw<1>(); else cpw<0>();
        __syncthreads();

        uint32_t* base = sm + s * HG_STG;
#pragma unroll
        for (int ks = 0; ks < 2; ks++) {
            uint32_t ahf[4][4], alf[4][4];
#pragma unroll
            for (int mt = 0; mt < 4; mt++) {
                int idx = (ks * 128 + warpM * 64 + mt * 16 + lq) * 12 + lr;
                ahf[mt][0] = base[idx];         ahf[mt][1] = base[idx + 96];
                ahf[mt][2] = base[idx + 4];     ahf[mt][3] = base[idx + 100];
                alf[mt][0] = base[HG_ARR + idx];       alf[mt][1] = base[HG_ARR + idx + 96];
                alf[mt][2] = base[HG_ARR + idx + 4];   alf[mt][3] = base[HG_ARR + idx + 100];
            }
            uint32_t bhf[4][2], blf[4][2];
#pragma unroll
            for (int nt = 0; nt < 4; nt++) {
                int idx = (ks * 128 + warpN * 32 + nt * 8 + lq) * 12 + lr;
                bhf[nt][0] = base[2 * HG_ARR + idx];
                bhf[nt][1] = base[2 * HG_ARR + idx + 4];
                blf[nt][0] = base[3 * HG_ARR + idx];
                blf[nt][1] = base[3 * HG_ARR + idx + 4];
            }
#pragma unroll
            for (int mt = 0; mt < 4; mt++)
#pragma unroll
                for (int nt = 0; nt < 4; nt++) {
                    mma_bf16(acc[mt][nt], ahf[mt][0], ahf[mt][1], ahf[mt][2], ahf[mt][3],
                             bhf[nt][0], bhf[nt][1]);
                    mma_bf16(acc[mt][nt], ahf[mt][0], ahf[mt][1], ahf[mt][2], ahf[mt][3],
                             blf[nt][0], blf[nt][1]);
                    mma_bf16(acc[mt][nt], alf[mt][0], alf[mt][1], alf[mt][2], alf[mt][3],
                             bhf[nt][0], bhf[nt][1]);
                }
        }
        __syncthreads();
        if (kt + 2 < 32) CPA_CHUNK(kt + 2, s);
    }
#undef CPA_CHUNK

    // ---- epilogue (pairwise over n) ----
#pragma unroll
    for (int mt = 0; mt < 4; mt++) {
        int mb = row0 + warpM * 64 + mt * 16 + lq;
#pragma unroll
        for (int nt = 0; nt < 4; nt++) {
            int n0 = col0 + warpN * 32 + nt * 8 + lr * 2;
            float bi0 = __ldg(bias + n0), bi1 = __ldg(bias + n0 + 1);
#pragma unroll
            for (int rh = 0; rh < 2; rh++) {
                int m = mb + rh * 8;
                float v0 = acc[mt][nt][rh * 2 + 0] + bi0;
                float v1 = acc[mt][nt][rh * 2 + 1] + bi1;
                if (MODE == 1) {
                    *(float2*)(C + (size_t)m * 1024 + n0) = make_float2(v0, v1);
                } else {
                    int b = m >> 11;
                    int s = m & 2047;
                    if (n0 < D_MODEL) {
                        *(float2*)(g_q + (size_t)m * 1024 + n0) = make_float2(v0, v1);
                        float q0 = v0 * 0.125f, q1 = v1 * 0.125f;
                        uint32_t hh = bf2(q0, q1);
                        uint32_t ll = bf2(q0 - bf_lo_f(hh), q1 - bf_hi_f(hh));
                        size_t qo = ((size_t)(b * 16 + (n0 >> 6)) * SEQ + s) * 64 + (n0 & 63);
                        *(uint32_t*)(g_qh + qo) = hh;
                        *(uint32_t*)(g_ql + qo) = ll;
                    } else {
                        int cc = n0 - D_MODEL;
                        int which = cc >> 10;
                        cc &= 1023;
                        int hd = cc >> 6, d = cc & 63;
                        size_t so = ((size_t)(b * 16 + hd) * SEQ + s) * 64 + d;
                        *(float2*)(C + (size_t)which * KV_ELEMS + so) = make_float2(v0, v1);
                        uint32_t hp = bf2(v0, v1);
                        uint32_t lp = bf2(v0 - bf_lo_f(hp), v1 - bf_hi_f(hp));
                        if (which == 0) {
                            *(uint32_t*)(g_kh + so) = hp;
                            *(uint32_t*)(g_kl + so) = lp;
                        } else {
                            size_t vo = ((size_t)(b * 16 + hd) * 64 + d) * SEQ + s;
                            __nv_bfloat16 h0 = __float2bfloat16(v0);
                            __nv_bfloat16 h1 = __float2bfloat16(v1);
                            g_vth[vo] = h0;
                            g_vtl[vo] = __float2bfloat16(v0 - __bfloat162float(h0));
                            g_vth[vo + SEQ] = h1;
                            g_vtl[vo + SEQ] = __float2bfloat16(v1 - __bfloat162float(h1));
                        }
                    }
                }
            }
        }
    }
}

// ---------------------------------------------------------------------------
// Flash attention on mma.sync. Q fragments live in REGISTERS (staged once
// through KV stage-0 SMEM). KV cp.async double-buffered, pitch-12 layout.
// SMEM = 2 stages x 12288 words = 96KB -> 2 CTAs/SM.
// ---------------------------------------------------------------------------
#define AT_ARR 3072                        // words per KV array (4*64*12)
#define AT_STG (4 * AT_ARR)                // 12288 words per stage
#define AT_SMEM (2 * AT_STG * 4)           // 98304 B

__global__ __launch_bounds__(256, 2)
void attn_mma()
{
    extern __shared__ uint32_t sm[];
    const uint32_t smb = smem_u32(sm);

    const int tid = threadIdx.x;
    const int wid = tid >> 5;
    const int lane = tid & 31;
    const int lq = lane >> 2;
    const int lr = lane & 3;
    const int qt = blockIdx.x;
    const int bh = blockIdx.y;
    const int b = bh >> 4, h = bh & 15;
    const float MX = 20.0f;

    const uint4* Qh4 = (const uint4*)g_qh;
    const uint4* Ql4 = (const uint4*)g_ql;
    const uint4* Kh4 = (const uint4*)g_kh;
    const uint4* Kl4 = (const uint4*)g_kl;
    const uint4* Vh4 = (const uint4*)g_vth;
    const uint4* Vl4 = (const uint4*)g_vtl;

    // ---- stage Q tile through stage-0 SMEM -> registers, then release ----
    uint32_t qh[4][4], ql[4][4];
    {
        // Qh at words [0, 6144), Ql at [6144, 12288): pitch 12 rows of 128
        const size_t q0 = ((size_t)bh * SEQ + qt * 128) * 8;
#pragma unroll
        for (int i = 0; i < 4; i++) {
            int e = tid + i * 256;
            int m = e >> 3, seg = e & 7;
            uint4 vh = Qh4[q0 + m * 8 + seg];
            uint4 vl = Ql4[q0 + m * 8 + seg];
            int idx = ((seg >> 1) * 128 + m) * 12 + (seg & 1) * 4;
            sm[idx] = vh.x; sm[idx+1] = vh.y; sm[idx+2] = vh.z; sm[idx+3] = vh.w;
            sm[6144 + idx] = vl.x; sm[6144 + idx+1] = vl.y;
            sm[6144 + idx+2] = vl.z; sm[6144 + idx+3] = vl.w;
        }
        __syncthreads();
#pragma unroll
        for (int ks = 0; ks < 4; ks++) {
            int aidx = (ks * 128 + wid * 16 + lq) * 12 + lr;
            qh[ks][0] = sm[aidx];       qh[ks][1] = sm[aidx + 96];
            qh[ks][2] = sm[aidx + 4];   qh[ks][3] = sm[aidx + 100];
            ql[ks][0] = sm[6144 + aidx];     ql[ks][1] = sm[6144 + aidx + 96];
            ql[ks][2] = sm[6144 + aidx + 4]; ql[ks][3] = sm[6144 + aidx + 100];
        }
        __syncthreads();
    }

#define CPAKV(c, stg)                                                        \
    {                                                                        \
        uint32_t sb = smb + (stg) * (AT_STG * 4);                            \
        int kt0_ = (c) * 64;                                                 \
        _Pragma("unroll")                                                    \
        for (int i = 0; i < 2; i++) {                                        \
            int e = tid + i * 256;                                           \
            int m = e >> 3, seg = e & 7;                                     \
            uint32_t idx = (uint32_t)(((((seg >> 1) * 64 + m) * 12) + (seg & 1) * 4) * 4); \
            size_t ki = ((size_t)bh * SEQ + kt0_ + m) * 8 + seg;             \
            size_t vi = ((size_t)bh * 64 + m) * 256 + (kt0_ >> 3) + seg;     \
            cpa16(sb + idx,               Kh4 + ki);                         \
            cpa16(sb + AT_ARR * 4 + idx,  Kl4 + ki);                         \
            cpa16(sb + AT_ARR * 8 + idx,  Vh4 + vi);                         \
            cpa16(sb + AT_ARR * 12 + idx, Vl4 + vi);                         \
        }                                                                    \
        cpc();                                                               \
    }

    const int nch = 2 * qt + 2;
    const int gr0 = qt * 128 + wid * 16;

    CPAKV(0, 0);
    CPAKV(1, 1);

    float O[8][4];
#pragma unroll
    for (int nb = 0; nb < 8; nb++)
#pragma unroll
        for (int q = 0; q < 4; q++) O[nb][q] = 0.0f;
    float lsum0 = 0.0f, lsum1 = 0.0f;

#pragma unroll 1
    for (int c = 0; c < nch; c++) {
        const int s = c & 1;
        if (c + 1 < nch) cpw<1>(); else cpw<0>();
        __syncthreads();

        const int kt0 = c * 64;
        if (kt0 <= gr0 + 15) {
            uint32_t* Khs = sm + s * AT_STG;
            uint32_t* Kls = Khs + AT_ARR;
            uint32_t* Vhs = Khs + 2 * AT_ARR;
            uint32_t* Vls = Khs + 3 * AT_ARR;

            float S[8][4];
#pragma unroll
            for (int nb = 0; nb < 8; nb++)
#pragma unroll
                for (int q = 0; q < 4; q++) S[nb][q] = 0.0f;
#pragma unroll
            for (int ks = 0; ks < 4; ks++) {
#pragma unroll
                for (int nb = 0; nb < 8; nb++) {
                    int bidx = (ks * 64 + nb * 8 + lq) * 12 + lr;
                    uint32_t bh0 = Khs[bidx], bh1 = Khs[bidx + 4];
                    uint32_t bl0 = Kls[bidx], bl1 = Kls[bidx + 4];
                    mma_bf16(S[nb], qh[ks][0], qh[ks][1], qh[ks][2], qh[ks][3], bh0, bh1);
                    mma_bf16(S[nb], qh[ks][0], qh[ks][1], qh[ks][2], qh[ks][3], bl0, bl1);
                    mma_bf16(S[nb], ql[ks][0], ql[ks][1], ql[ks][2], ql[ks][3], bh0, bh1);
                }
            }
            const int r0 = gr0 + lq, r1 = r0 + 8;
            float p[8][4];
#pragma unroll
            for (int nb = 0; nb < 8; nb++) {
                int c0 = kt0 + nb * 8 + 2 * lr;
                p[nb][0] = (c0     <= r0) ? __expf(S[nb][0] - MX) : 0.0f;
                p[nb][1] = (c0 + 1 <= r0) ? __expf(S[nb][1] - MX) : 0.0f;
                p[nb][2] = (c0     <= r1) ? __expf(S[nb][2] - MX) : 0.0f;
                p[nb][3] = (c0 + 1 <= r1) ? __expf(S[nb][3] - MX) : 0.0f;
                lsum0 += p[nb][0] + p[nb][1];
                lsum1 += p[nb][2] + p[nb][3];
            }
#pragma unroll
            for (int ks = 0; ks < 4; ks++) {
                uint32_t ph0 = bf2(p[2*ks][0],   p[2*ks][1]);
                uint32_t ph1 = bf2(p[2*ks][2],   p[2*ks][3]);
                uint32_t ph2 = bf2(p[2*ks+1][0], p[2*ks+1][1]);
                uint32_t ph3 = bf2(p[2*ks+1][2], p[2*ks+1][3]);
                uint32_t pl0 = bf2(p[2*ks][0] - bf_lo_f(ph0),   p[2*ks][1] - bf_hi_f(ph0));
                uint32_t pl1 = bf2(p[2*ks][2] - bf_lo_f(ph1),   p[2*ks][3] - bf_hi_f(ph1));
                uint32_t pl2 = bf2(p[2*ks+1][0] - bf_lo_f(ph2), p[2*ks+1][1] - bf_hi_f(ph2));
                uint32_t pl3 = bf2(p[2*ks+1][2] - bf_lo_f(ph3), p[2*ks+1][3] - bf_hi_f(ph3));
#pragma unroll
                for (int nb = 0; nb < 8; nb++) {
                    int bidx = (ks * 64 + nb * 8 + lq) * 12 + lr;
                    uint32_t vh0 = Vhs[bidx], vh1 = Vhs[bidx + 4];
                    uint32_t vl0 = Vls[bidx], vl1 = Vls[bidx + 4];
                    mma_bf16(O[nb], ph0, ph1, ph2, ph3, vh0, vh1);
                    mma_bf16(O[nb], pl0, pl1, pl2, pl3, vh0, vh1);
                    mma_bf16(O[nb], ph0, ph1, ph2, ph3, vl0, vl1);
                }
            }
        }
        __syncthreads();
        if (c + 2 < nch) CPAKV(c + 2, s);
    }
#undef CPAKV

    // ---- epilogue: merge memattn partials, normalize, emit ctx bf16 hi/lo ----
    lsum0 += __shfl_xor_sync(0xFFFFFFFFu, lsum0, 1);
    lsum0 += __shfl_xor_sync(0xFFFFFFFFu, lsum0, 2);
    lsum1 += __shfl_xor_sync(0xFFFFFFFFu, lsum1, 1);
    lsum1 += __shfl_xor_sync(0xFFFFFFFFu, lsum1, 2);

    const int rl0 = wid * 16 + lq, rl1 = rl0 + 8;
    const int row0g = qt * 128;
    const float inv0 = 1.0f / (lsum0 + g_msum[(size_t)bh * SEQ + row0g + rl0]);
    const float inv1 = 1.0f / (lsum1 + g_msum[(size_t)bh * SEQ + row0g + rl1]);
    const size_t c0base = ((size_t)(b * SEQ + row0g + rl0)) * D_MODEL + h * HEAD_DIM;
    const size_t c1base = ((size_t)(b * SEQ + row0g + rl1)) * D_MODEL + h * HEAD_DIM;
#pragma unroll
    for (int nb = 0; nb < 8; nb++) {
        int col = nb * 8 + 2 * lr;
        float2 m0 = *(float2*)(g_ctx + c0base + col);
        float2 m1 = *(float2*)(g_ctx + c1base + col);
        float o0x = (O[nb][0] + m0.x) * inv0;
        float o0y = (O[nb][1] + m0.y) * inv0;
        float o1x = (O[nb][2] + m1.x) * inv1;
        float o1y = (O[nb][3] + m1.y) * inv1;
        uint32_t h0 = bf2(o0x, o0y);
        uint32_t l0 = bf2(o0x - bf_lo_f(h0), o0y - bf_hi_f(h0));
        uint32_t h1 = bf2(o1x, o1y);
        uint32_t l1 = bf2(o1x - bf_lo_f(h1), o1y - bf_hi_f(h1));
        *(uint32_t*)(g_a_hi + c0base + col) = h0;
        *(uint32_t*)(g_a_lo + c0base + col) = l0;
        *(uint32_t*)(g_a_hi + c1base + col) = h1;
        *(uint32_t*)(g_a_lo + c1base + col) = l1;
    }
}

// ---------------------------------------------------------------------------
extern "C" void kernel_launch(void* const* d_in, const int* in_sizes, int n_in,
                              void* d_out, int out_size)
{
    const float* x = 0; const float* pk = 0; const float* pv = 0;
    const float* W_qkv = 0; const float* b_qkv = 0;
    const float* W_out = 0; const float* b_out = 0;
    for (int i = 0; i < n_in; i++) {
        const float* p = (const float*)d_in[i];
        switch (in_sizes[i]) {
            case 4194304:  x = p;      break;
            case 33554432: if (!pk) pk = p; else pv = p; break;
            case 3145728:  W_qkv = p;  break;
            case 3072:     b_qkv = p;  break;
            case 1048576:  W_out = p;  break;
            case 1024:     b_out = p;  break;
            default: break;
        }
    }
    if (!(x && pk && pv && W_qkv && b_qkv && W_out && b_out)) {
        if (n_in < 7) return;
        x     = (const float*)d_in[0];
        pk    = (const float*)d_in[1];
        pv    = (const float*)d_in[2];
        W_qkv = (const float*)d_in[3];
        b_qkv = (const float*)d_in[4];
        W_out = (const float*)d_in[5];
        b_out = (const float*)d_in[6];
    }

    float* out = (float*)d_out;

    static __nv_bfloat16 *s_ah = nullptr, *s_al = nullptr, *s_bh = nullptr, *s_bl = nullptr;
    if (!s_ah) {
        void* p = 0;
        cudaGetSymbolAddress(&p, g_a_hi);  s_ah = (__nv_bfloat16*)p;
        cudaGetSymbolAddress(&p, g_a_lo);  s_al = (__nv_bfloat16*)p;
        cudaGetSymbolAddress(&p, g_bt_hi); s_bh = (__nv_bfloat16*)p;
        cudaGetSymbolAddress(&p, g_bt_lo); s_bl = (__nv_bfloat16*)p;
        cudaFuncSetAttribute((const void*)hgemm_bf<0>,
                             cudaFuncAttributeMaxDynamicSharedMemorySize, HB_SMEM);
        cudaFuncSetAttribute((const void*)hgemm_bf<1>,
                             cudaFuncAttributeMaxDynamicSharedMemorySize, HB_SMEM);
        cudaFuncSetAttribute((const void*)attn_mma,
                             cudaFuncAttributeMaxDynamicSharedMemorySize, AT_SMEM);
    }

    float* kvbuf = out + OUT_ELEMS;   // [out | k | v] element layout

    // prep: split x; split+transpose W_qkv
    split_a_kernel<<<OUT_ELEMS / 1024, 256>>>((const float4*)x, (uint2*)s_ah, (uint2*)s_al);
    {
        dim3 grid(3 * D_MODEL / 32, D_MODEL / 32);
        split_wt_kernel<<<grid, dim3(32, 8)>>>(W_qkv, s_bh, s_bl, 3 * D_MODEL);
    }
    // 1) QKV GEMM (emits q/k/v + pre-split attention operands)
    {
        dim3 grid(3 * D_MODEL / 128, M_TOT / 128);
        hgemm_bf<0><<<grid, 256, HB_SMEM>>>((const uint4*)s_ah, (const uint4*)s_al,
                                            (const uint4*)s_bh, (const uint4*)s_bl,
                                            b_qkv, kvbuf);
    }
    // 2a) memory attention partials
    {
        dim3 grid(SEQ / 128, BATCH * N_HEADS);
        memattn_kernel<<<grid, 256>>>(pk, pv);
    }
    // 2b) token flash attention + merge (writes ctx bf16 hi/lo)
    {
        dim3 grid(SEQ / 128, BATCH * N_HEADS);
        attn_mma<<<grid, 256, AT_SMEM>>>();
    }
    // prep: split+transpose W_out
    {
        dim3 grid(D_MODEL / 32, D_MODEL / 32);
        split_wt_kernel<<<grid, dim3(32, 8)>>>(W_out, s_bh, s_bl, D_MODEL);
    }
    // 3) output GEMM (A = ctx hi/lo from attn epilogue)
    {
        dim3 grid(D_MODEL / 128, M_TOT / 128);
        hgemm_bf<1><<<grid, 256, HB_SMEM>>>((const uint4*)s_ah, (const uint4*)s_al,
                                            (const uint4*)s_bh, (const uint4*)s_bl,
                                            b_out, out);
    }
}

// round 14
// speedup vs baseline: 2.6156x; 1.1091x over previous
#include <cuda_runtime.h>
#include <cuda_bf16.h>
#include <cstdint>

#define D_MODEL  1024
#define N_HEADS  16
#define HEAD_DIM 64
#define BATCH    2
#define SEQ      2048
#define LMEM     8
#define M_TOT    (BATCH * SEQ)            // 4096
#define OUT_ELEMS (M_TOT * D_MODEL)       // 4194304
#define KV_ELEMS  (BATCH * N_HEADS * SEQ * HEAD_DIM)  // 4194304 each

typedef unsigned long long ull;

// scratch (no cudaMalloc). NEVER pass these directly as host-side kernel args
// (host stub address + GB300 ATS = silent host reads) — use cudaGetSymbolAddress
// or reference in device code.
__device__ float g_q[M_TOT * D_MODEL];
__device__ float g_ctx[M_TOT * D_MODEL];           // memattn macc lives here
__device__ float g_msum[BATCH * N_HEADS * SEQ];    // memattn partial softmax sums
__device__ __nv_bfloat16 g_a_hi[M_TOT * D_MODEL];  // GEMM A split (x, then ctx)
__device__ __nv_bfloat16 g_a_lo[M_TOT * D_MODEL];
__device__ __nv_bfloat16 g_bt_hi[3 * D_MODEL * D_MODEL];
__device__ __nv_bfloat16 g_bt_lo[3 * D_MODEL * D_MODEL];
__device__ __nv_bfloat16 g_qh[M_TOT * D_MODEL];    // q*0.125 hi/lo, [bh][s][d]
__device__ __nv_bfloat16 g_ql[M_TOT * D_MODEL];
__device__ __nv_bfloat16 g_kh[KV_ELEMS];           // [bh][s][d]
__device__ __nv_bfloat16 g_kl[KV_ELEMS];
__device__ __nv_bfloat16 g_vth[KV_ELEMS];          // [bh][d][s]
__device__ __nv_bfloat16 g_vtl[KV_ELEMS];

// ---- bf16 helpers ------------------------------------------------------------
__device__ __forceinline__ uint32_t bf2(float lo, float hi) {   // low16=lo, high16=hi
    uint32_t r;
    asm("cvt.rn.bf16x2.f32 %0, %1, %2;" : "=r"(r) : "f"(hi), "f"(lo));
    return r;
}
__device__ __forceinline__ float bf_lo_f(uint32_t h) { return __uint_as_float(h << 16); }
__device__ __forceinline__ float bf_hi_f(uint32_t h) { return __uint_as_float(h & 0xFFFF0000u); }

__device__ __forceinline__ void mma_bf16(float* c,
                                         uint32_t a0, uint32_t a1, uint32_t a2, uint32_t a3,
                                         uint32_t b0, uint32_t b1) {
    asm volatile(
        "mma.sync.aligned.m16n8k16.row.col.f32.bf16.bf16.f32 "
        "{%0,%1,%2,%3}, {%4,%5,%6,%7}, {%8,%9}, {%0,%1,%2,%3};"
        : "+f"(c[0]), "+f"(c[1]), "+f"(c[2]), "+f"(c[3])
        : "r"(a0), "r"(a1), "r"(a2), "r"(a3), "r"(b0), "r"(b1));
}

// ---- cp.async (base sm_80 ISA; LDGSTS). SMEM dst MUST be 16B aligned. ---------
__device__ __forceinline__ uint32_t smem_u32(const void* p) {
    uint32_t a;
    asm("{ .reg .u64 t; cvta.to.shared.u64 t, %1; cvt.u32.u64 %0, t; }"
        : "=r"(a) : "l"(p));
    return a;
}
__device__ __forceinline__ void cpa16(uint32_t smaddr, const void* gptr) {
    asm volatile("cp.async.cg.shared.global [%0], [%1], 16;"
                 :: "r"(smaddr), "l"(__cvta_generic_to_global(gptr)));
}
__device__ __forceinline__ void cpc() {
    asm volatile("cp.async.commit_group;");
}
template <int N>
__device__ __forceinline__ void cpw() {
    asm volatile("cp.async.wait_group %0;" :: "n"(N));
}

// ---------------------------------------------------------------------------
// Prep kernels (proven)
// ---------------------------------------------------------------------------
__global__ __launch_bounds__(256)
void split_a_kernel(const float4* __restrict__ src,
                    uint2* __restrict__ hi, uint2* __restrict__ lo)
{
    int i = blockIdx.x * 256 + threadIdx.x;
    float4 v = src[i];
    uint32_t h01 = bf2(v.x, v.y), h23 = bf2(v.z, v.w);
    uint32_t l01 = bf2(v.x - bf_lo_f(h01), v.y - bf_hi_f(h01));
    uint32_t l23 = bf2(v.z - bf_lo_f(h23), v.w - bf_hi_f(h23));
    hi[i] = make_uint2(h01, h23);
    lo[i] = make_uint2(l01, l23);
}

__global__ __launch_bounds__(256)
void split_wt_kernel(const float* __restrict__ W,
                     __nv_bfloat16* __restrict__ hiT,
                     __nv_bfloat16* __restrict__ loT,
                     int N)
{
    __shared__ float t[32][33];
    const int tx = threadIdx.x, ty = threadIdx.y;
    const int n0 = blockIdx.x * 32, k0 = blockIdx.y * 32;
#pragma unroll
    for (int i = 0; i < 4; i++)
        t[ty + 8 * i][tx] = W[(size_t)(k0 + ty + 8 * i) * N + n0 + tx];
    __syncthreads();
#pragma unroll
    for (int i = 0; i < 4; i++) {
        int n = n0 + ty + 8 * i;
        float f = t[tx][ty + 8 * i];
        __nv_bfloat16 h = __float2bfloat16(f);
        __nv_bfloat16 l = __float2bfloat16(f - __bfloat162float(h));
        hiT[(size_t)n * 1024 + k0 + tx] = h;
        loT[(size_t)n * 1024 + k0 + tx] = l;
    }
}

// ---------------------------------------------------------------------------
// Memory attention v2 — warp-per-query, fully coalesced.
// Pass p: lanes 0-15 stream key 2p (256B), lanes 16-31 key 2p+1.
// grid (SEQ/8, BATCH*N_HEADS), 256 threads (8 warps = 8 queries).
// ---------------------------------------------------------------------------
__global__ __launch_bounds__(256)
void memattn_kernel(const float* __restrict__ pk, const float* __restrict__ pv)
{
    const int tid  = threadIdx.x;
    const int wid  = tid >> 5;
    const int lane = tid & 31;
    const int half = lane >> 4;              // key parity within pass
    const int d4   = (lane & 15) * 4;        // dim group (same across passes)
    const int bh   = blockIdx.y;
    const int b    = bh >> 4, h = bh & 15;
    const int qrow = blockIdx.x * 8 + wid;
    const float MX = 20.0f;

    // q (scaled): 4 dims per lane
    float4 q4;
    {
        const float* qp = g_q + ((size_t)(b * SEQ + qrow) * D_MODEL + h * HEAD_DIM + d4);
        q4 = *(const float4*)qp;
        q4.x *= 0.125f; q4.y *= 0.125f; q4.z *= 0.125f; q4.w *= 0.125f;
    }

    const size_t blk = ((size_t)bh * SEQ + qrow) * (LMEM * HEAD_DIM);
    const float* kp = pk + blk;
    const float* vp = pv + blk;

    float4 acc = make_float4(0.f, 0.f, 0.f, 0.f);
    float lsum = 0.0f;

#pragma unroll
    for (int p = 0; p < 4; p++) {
        const int key = 2 * p + half;
        float4 k4 = *(const float4*)(kp + key * HEAD_DIM + d4);
        float d = q4.x * k4.x + q4.y * k4.y + q4.z * k4.z + q4.w * k4.w;
        d += __shfl_xor_sync(0xFFFFFFFFu, d, 1);
        d += __shfl_xor_sync(0xFFFFFFFFu, d, 2);
        d += __shfl_xor_sync(0xFFFFFFFFu, d, 4);
        d += __shfl_xor_sync(0xFFFFFFFFu, d, 8);
        float pe = __expf(d - MX);
        lsum += pe;
        float4 v4 = *(const float4*)(vp + key * HEAD_DIM + d4);
        acc.x += pe * v4.x;
        acc.y += pe * v4.y;
        acc.z += pe * v4.z;
        acc.w += pe * v4.w;
    }
    // combine the two 16-lane halves (same d4 in lanes l and l^16)
    acc.x += __shfl_xor_sync(0xFFFFFFFFu, acc.x, 16);
    acc.y += __shfl_xor_sync(0xFFFFFFFFu, acc.y, 16);
    acc.z += __shfl_xor_sync(0xFFFFFFFFu, acc.z, 16);
    acc.w += __shfl_xor_sync(0xFFFFFFFFu, acc.w, 16);
    lsum  += __shfl_xor_sync(0xFFFFFFFFu, lsum, 16);

    if (lane < 16)
        *(float4*)(g_ctx + ((size_t)(b * SEQ + qrow)) * D_MODEL + h * HEAD_DIM + d4) = acc;
    if (lane == 0)
        g_msum[(size_t)bh * SEQ + qrow] = lsum;
}

// ---------------------------------------------------------------------------
// bf16 mma.sync GEMM, hi/lo 3-term. cp.async double-buffered, K=32 chunks.
// PITCH-12 rows (48B): 16B-aligned for cp.async AND conflict-free fragments.
// ---------------------------------------------------------------------------
#define HG_ARR 3072                        // words per array (2*128*12)
#define HG_STG (4 * HG_ARR)                // 12288 words per stage
#define HB_SMEM (2 * HG_STG * 4)           // 98304 B

template <int MODE>
__global__ __launch_bounds__(256, 2)
void hgemm_bf(const uint4* __restrict__ Ah, const uint4* __restrict__ Al,
              const uint4* __restrict__ Bh, const uint4* __restrict__ Bl,
              const float* __restrict__ bias,
              float* __restrict__ C)
{
    extern __shared__ uint32_t sm[];
    const uint32_t smb = smem_u32(sm);

    const int tid   = threadIdx.x;
    const int wid   = tid >> 5;
    const int lane  = tid & 31;
    const int warpM = wid & 1;
    const int warpN = wid >> 1;
    const int row0  = blockIdx.y * 128;
    const int col0  = blockIdx.x * 128;
    const int lq    = lane >> 2;
    const int lr    = lane & 3;

    float acc[4][4][4];
#pragma unroll
    for (int a = 0; a < 4; a++)
#pragma unroll
        for (int b = 0; b < 4; b++)
#pragma unroll
            for (int c = 0; c < 4; c++) acc[a][b][c] = 0.0f;

#define CPA_CHUNK(kt, stg)                                                   \
    {                                                                        \
        uint32_t sb = smb + (stg) * (HG_STG * 4);                            \
        _Pragma("unroll")                                                    \
        for (int i = 0; i < 2; i++) {                                        \
            int e = tid + i * 256;                                           \
            int m = e >> 2, seg = e & 3;                                     \
            uint32_t idx = (uint32_t)(((((seg >> 1) * 128 + m) * 12) + (seg & 1) * 4) * 4); \
            size_t ga = (size_t)(row0 + m) * 128 + (size_t)(kt) * 4 + seg;   \
            size_t gb = (size_t)(col0 + m) * 128 + (size_t)(kt) * 4 + seg;   \
            cpa16(sb + idx,                Ah + ga);                         \
            cpa16(sb + HG_ARR * 4 + idx,   Al + ga);                         \
            cpa16(sb + HG_ARR * 8 + idx,   Bh + gb);                         \
            cpa16(sb + HG_ARR * 12 + idx,  Bl + gb);                         \
        }                                                                    \
        cpc();                                                               \
    }

    CPA_CHUNK(0, 0);
    CPA_CHUNK(1, 1);

#pragma unroll 1
    for (int kt = 0; kt < 32; kt++) {
        const int s = kt & 1;
        if (kt + 1 < 32) cpw<1>(); else cpw<0>();
        __syncthreads();

        uint32_t* base = sm + s * HG_STG;
#pragma unroll
        for (int ks = 0; ks < 2; ks++) {
            uint32_t ahf[4][4], alf[4][4];
#pragma unroll
            for (int mt = 0; mt < 4; mt++) {
                int idx = (ks * 128 + warpM * 64 + mt * 16 + lq) * 12 + lr;
                ahf[mt][0] = base[idx];         ahf[mt][1] = base[idx + 96];
                ahf[mt][2] = base[idx + 4];     ahf[mt][3] = base[idx + 100];
                alf[mt][0] = base[HG_ARR + idx];       alf[mt][1] = base[HG_ARR + idx + 96];
                alf[mt][2] = base[HG_ARR + idx + 4];   alf[mt][3] = base[HG_ARR + idx + 100];
            }
            uint32_t bhf[4][2], blf[4][2];
#pragma unroll
            for (int nt = 0; nt < 4; nt++) {
                int idx = (ks * 128 + warpN * 32 + nt * 8 + lq) * 12 + lr;
                bhf[nt][0] = base[2 * HG_ARR + idx];
                bhf[nt][1] = base[2 * HG_ARR + idx + 4];
                blf[nt][0] = base[3 * HG_ARR + idx];
                blf[nt][1] = base[3 * HG_ARR + idx + 4];
            }
#pragma unroll
            for (int mt = 0; mt < 4; mt++)
#pragma unroll
                for (int nt = 0; nt < 4; nt++) {
                    mma_bf16(acc[mt][nt], ahf[mt][0], ahf[mt][1], ahf[mt][2], ahf[mt][3],
                             bhf[nt][0], bhf[nt][1]);
                    mma_bf16(acc[mt][nt], ahf[mt][0], ahf[mt][1], ahf[mt][2], ahf[mt][3],
                             blf[nt][0], blf[nt][1]);
                    mma_bf16(acc[mt][nt], alf[mt][0], alf[mt][1], alf[mt][2], alf[mt][3],
                             bhf[nt][0], bhf[nt][1]);
                }
        }
        __syncthreads();
        if (kt + 2 < 32) CPA_CHUNK(kt + 2, s);
    }
#undef CPA_CHUNK

    // ---- epilogue (pairwise over n) ----
#pragma unroll
    for (int mt = 0; mt < 4; mt++) {
        int mb = row0 + warpM * 64 + mt * 16 + lq;
#pragma unroll
        for (int nt = 0; nt < 4; nt++) {
            int n0 = col0 + warpN * 32 + nt * 8 + lr * 2;
            float bi0 = __ldg(bias + n0), bi1 = __ldg(bias + n0 + 1);
#pragma unroll
            for (int rh = 0; rh < 2; rh++) {
                int m = mb + rh * 8;
                float v0 = acc[mt][nt][rh * 2 + 0] + bi0;
                float v1 = acc[mt][nt][rh * 2 + 1] + bi1;
                if (MODE == 1) {
                    *(float2*)(C + (size_t)m * 1024 + n0) = make_float2(v0, v1);
                } else {
                    int b = m >> 11;
                    int s = m & 2047;
                    if (n0 < D_MODEL) {
                        *(float2*)(g_q + (size_t)m * 1024 + n0) = make_float2(v0, v1);
                        float q0 = v0 * 0.125f, q1 = v1 * 0.125f;
                        uint32_t hh = bf2(q0, q1);
                        uint32_t ll = bf2(q0 - bf_lo_f(hh), q1 - bf_hi_f(hh));
                        size_t qo = ((size_t)(b * 16 + (n0 >> 6)) * SEQ + s) * 64 + (n0 & 63);
                        *(uint32_t*)(g_qh + qo) = hh;
                        *(uint32_t*)(g_ql + qo) = ll;
                    } else {
                        int cc = n0 - D_MODEL;
                        int which = cc >> 10;
                        cc &= 1023;
                        int hd = cc >> 6, d = cc & 63;
                        size_t so = ((size_t)(b * 16 + hd) * SEQ + s) * 64 + d;
                        *(float2*)(C + (size_t)which * KV_ELEMS + so) = make_float2(v0, v1);
                        uint32_t hp = bf2(v0, v1);
                        uint32_t lp = bf2(v0 - bf_lo_f(hp), v1 - bf_hi_f(hp));
                        if (which == 0) {
                            *(uint32_t*)(g_kh + so) = hp;
                            *(uint32_t*)(g_kl + so) = lp;
                        } else {
                            size_t vo = ((size_t)(b * 16 + hd) * 64 + d) * SEQ + s;
                            __nv_bfloat16 h0 = __float2bfloat16(v0);
                            __nv_bfloat16 h1 = __float2bfloat16(v1);
                            g_vth[vo] = h0;
                            g_vtl[vo] = __float2bfloat16(v0 - __bfloat162float(h0));
                            g_vth[vo + SEQ] = h1;
                            g_vtl[vo + SEQ] = __float2bfloat16(v1 - __bfloat162float(h1));
                        }
                    }
                }
            }
        }
    }
}

// ---------------------------------------------------------------------------
// Flash attention on mma.sync. Q fragments in registers. KV cp.async
// double-buffered, pitch-12. SMEM = 96KB -> 2 CTAs/SM. (proven round 13)
// ---------------------------------------------------------------------------
#define AT_ARR 3072                        // words per KV array (4*64*12)
#define AT_STG (4 * AT_ARR)                // 12288 words per stage
#define AT_SMEM (2 * AT_STG * 4)           // 98304 B

__global__ __launch_bounds__(256, 2)
void attn_mma()
{
    extern __shared__ uint32_t sm[];
    const uint32_t smb = smem_u32(sm);

    const int tid = threadIdx.x;
    const int wid = tid >> 5;
    const int lane = tid & 31;
    const int lq = lane >> 2;
    const int lr = lane & 3;
    const int qt = blockIdx.x;
    const int bh = blockIdx.y;
    const int b = bh >> 4, h = bh & 15;
    const float MX = 20.0f;

    const uint4* Qh4 = (const uint4*)g_qh;
    const uint4* Ql4 = (const uint4*)g_ql;
    const uint4* Kh4 = (const uint4*)g_kh;
    const uint4* Kl4 = (const uint4*)g_kl;
    const uint4* Vh4 = (const uint4*)g_vth;
    const uint4* Vl4 = (const uint4*)g_vtl;

    // ---- stage Q tile through stage-0 SMEM -> registers, then release ----
    uint32_t qh[4][4], ql[4][4];
    {
        const size_t q0 = ((size_t)bh * SEQ + qt * 128) * 8;
#pragma unroll
        for (int i = 0; i < 4; i++) {
            int e = tid + i * 256;
            int m = e >> 3, seg = e & 7;
            uint4 vh = Qh4[q0 + m * 8 + seg];
            uint4 vl = Ql4[q0 + m * 8 + seg];
            int idx = ((seg >> 1) * 128 + m) * 12 + (seg & 1) * 4;
            sm[idx] = vh.x; sm[idx+1] = vh.y; sm[idx+2] = vh.z; sm[idx+3] = vh.w;
            sm[6144 + idx] = vl.x; sm[6144 + idx+1] = vl.y;
            sm[6144 + idx+2] = vl.z; sm[6144 + idx+3] = vl.w;
        }
        __syncthreads();
#pragma unroll
        for (int ks = 0; ks < 4; ks++) {
            int aidx = (ks * 128 + wid * 16 + lq) * 12 + lr;
            qh[ks][0] = sm[aidx];       qh[ks][1] = sm[aidx + 96];
            qh[ks][2] = sm[aidx + 4];   qh[ks][3] = sm[aidx + 100];
            ql[ks][0] = sm[6144 + aidx];     ql[ks][1] = sm[6144 + aidx + 96];
            ql[ks][2] = sm[6144 + aidx + 4]; ql[ks][3] = sm[6144 + aidx + 100];
        }
        __syncthreads();
    }

#define CPAKV(c, stg)                                                        \
    {                                                                        \
        uint32_t sb = smb + (stg) * (AT_STG * 4);                            \
        int kt0_ = (c) * 64;                                                 \
        _Pragma("unroll")                                                    \
        for (int i = 0; i < 2; i++) {                                        \
            int e = tid + i * 256;                                           \
            int m = e >> 3, seg = e & 7;                                     \
            uint32_t idx = (uint32_t)(((((seg >> 1) * 64 + m) * 12) + (seg & 1) * 4) * 4); \
            size_t ki = ((size_t)bh * SEQ + kt0_ + m) * 8 + seg;             \
            size_t vi = ((size_t)bh * 64 + m) * 256 + (kt0_ >> 3) + seg;     \
            cpa16(sb + idx,               Kh4 + ki);                         \
            cpa16(sb + AT_ARR * 4 + idx,  Kl4 + ki);                         \
            cpa16(sb + AT_ARR * 8 + idx,  Vh4 + vi);                         \
            cpa16(sb + AT_ARR * 12 + idx, Vl4 + vi);                         \
        }                                                                    \
        cpc();                                                               \
    }

    const int nch = 2 * qt + 2;
    const int gr0 = qt * 128 + wid * 16;

    CPAKV(0, 0);
    CPAKV(1, 1);

    float O[8][4];
#pragma unroll
    for (int nb = 0; nb < 8; nb++)
#pragma unroll
        for (int q = 0; q < 4; q++) O[nb][q] = 0.0f;
    float lsum0 = 0.0f, lsum1 = 0.0f;

#pragma unroll 1
    for (int c = 0; c < nch; c++) {
        const int s = c & 1;
        if (c + 1 < nch) cpw<1>(); else cpw<0>();
        __syncthreads();

        const int kt0 = c * 64;
        if (kt0 <= gr0 + 15) {
            uint32_t* Khs = sm + s * AT_STG;
            uint32_t* Kls = Khs + AT_ARR;
            uint32_t* Vhs = Khs + 2 * AT_ARR;
            uint32_t* Vls = Khs + 3 * AT_ARR;

            float S[8][4];
#pragma unroll
            for (int nb = 0; nb < 8; nb++)
#pragma unroll
                for (int q = 0; q < 4; q++) S[nb][q] = 0.0f;
#pragma unroll
            for (int ks = 0; ks < 4; ks++) {
#pragma unroll
                for (int nb = 0; nb < 8; nb++) {
                    int bidx = (ks * 64 + nb * 8 + lq) * 12 + lr;
                    uint32_t bh0 = Khs[bidx], bh1 = Khs[bidx + 4];
                    uint32_t bl0 = Kls[bidx], bl1 = Kls[bidx + 4];
                    mma_bf16(S[nb], qh[ks][0], qh[ks][1], qh[ks][2], qh[ks][3], bh0, bh1);
                    mma_bf16(S[nb], qh[ks][0], qh[ks][1], qh[ks][2], qh[ks][3], bl0, bl1);
                    mma_bf16(S[nb], ql[ks][0], ql[ks][1], ql[ks][2], ql[ks][3], bh0, bh1);
                }
            }
            const int r0 = gr0 + lq, r1 = r0 + 8;
            float p[8][4];
#pragma unroll
            for (int nb = 0; nb < 8; nb++) {
                int c0 = kt0 + nb * 8 + 2 * lr;
                p[nb][0] = (c0     <= r0) ? __expf(S[nb][0] - MX) : 0.0f;
                p[nb][1] = (c0 + 1 <= r0) ? __expf(S[nb][1] - MX) : 0.0f;
                p[nb][2] = (c0     <= r1) ? __expf(S[nb][2] - MX) : 0.0f;
                p[nb][3] = (c0 + 1 <= r1) ? __expf(S[nb][3] - MX) : 0.0f;
                lsum0 += p[nb][0] + p[nb][1];
                lsum1 += p[nb][2] + p[nb][3];
            }
#pragma unroll
            for (int ks = 0; ks < 4; ks++) {
                uint32_t ph0 = bf2(p[2*ks][0],   p[2*ks][1]);
                uint32_t ph1 = bf2(p[2*ks][2],   p[2*ks][3]);
                uint32_t ph2 = bf2(p[2*ks+1][0], p[2*ks+1][1]);
                uint32_t ph3 = bf2(p[2*ks+1][2], p[2*ks+1][3]);
                uint32_t pl0 = bf2(p[2*ks][0] - bf_lo_f(ph0),   p[2*ks][1] - bf_hi_f(ph0));
                uint32_t pl1 = bf2(p[2*ks][2] - bf_lo_f(ph1),   p[2*ks][3] - bf_hi_f(ph1));
                uint32_t pl2 = bf2(p[2*ks+1][0] - bf_lo_f(ph2), p[2*ks+1][1] - bf_hi_f(ph2));
                uint32_t pl3 = bf2(p[2*ks+1][2] - bf_lo_f(ph3), p[2*ks+1][3] - bf_hi_f(ph3));
#pragma unroll
                for (int nb = 0; nb < 8; nb++) {
                    int bidx = (ks * 64 + nb * 8 + lq) * 12 + lr;
                    uint32_t vh0 = Vhs[bidx], vh1 = Vhs[bidx + 4];
                    uint32_t vl0 = Vls[bidx], vl1 = Vls[bidx + 4];
                    mma_bf16(O[nb], ph0, ph1, ph2, ph3, vh0, vh1);
                    mma_bf16(O[nb], pl0, pl1, pl2, pl3, vh0, vh1);
                    mma_bf16(O[nb], ph0, ph1, ph2, ph3, vl0, vl1);
                }
            }
        }
        __syncthreads();
        if (c + 2 < nch) CPAKV(c + 2, s);
    }
#undef CPAKV

    // ---- epilogue: merge memattn partials, normalize, emit ctx bf16 hi/lo ----
    lsum0 += __shfl_xor_sync(0xFFFFFFFFu, lsum0, 1);
    lsum0 += __shfl_xor_sync(0xFFFFFFFFu, lsum0, 2);
    lsum1 += __shfl_xor_sync(0xFFFFFFFFu, lsum1, 1);
    lsum1 += __shfl_xor_sync(0xFFFFFFFFu, lsum1, 2);

    const int rl0 = wid * 16 + lq, rl1 = rl0 + 8;
    const int row0g = qt * 128;
    const float inv0 = 1.0f / (lsum0 + g_msum[(size_t)bh * SEQ + row0g + rl0]);
    const float inv1 = 1.0f / (lsum1 + g_msum[(size_t)bh * SEQ + row0g + rl1]);
    const size_t c0base = ((size_t)(b * SEQ + row0g + rl0)) * D_MODEL + h * HEAD_DIM;
    const size_t c1base = ((size_t)(b * SEQ + row0g + rl1)) * D_MODEL + h * HEAD_DIM;
#pragma unroll
    for (int nb = 0; nb < 8; nb++) {
        int col = nb * 8 + 2 * lr;
        float2 m0 = *(float2*)(g_ctx + c0base + col);
        float2 m1 = *(float2*)(g_ctx + c1base + col);
        float o0x = (O[nb][0] + m0.x) * inv0;
        float o0y = (O[nb][1] + m0.y) * inv0;
        float o1x = (O[nb][2] + m1.x) * inv1;
        float o1y = (O[nb][3] + m1.y) * inv1;
        uint32_t h0 = bf2(o0x, o0y);
        uint32_t l0 = bf2(o0x - bf_lo_f(h0), o0y - bf_hi_f(h0));
        uint32_t h1 = bf2(o1x, o1y);
        uint32_t l1 = bf2(o1x - bf_lo_f(h1), o1y - bf_hi_f(h1));
        *(uint32_t*)(g_a_hi + c0base + col) = h0;
        *(uint32_t*)(g_a_lo + c0base + col) = l0;
        *(uint32_t*)(g_a_hi + c1base + col) = h1;
        *(uint32_t*)(g_a_lo + c1base + col) = l1;
    }
}

// ---------------------------------------------------------------------------
extern "C" void kernel_launch(void* const* d_in, const int* in_sizes, int n_in,
                              void* d_out, int out_size)
{
    const float* x = 0; const float* pk = 0; const float* pv = 0;
    const float* W_qkv = 0; const float* b_qkv = 0;
    const float* W_out = 0; const float* b_out = 0;
    for (int i = 0; i < n_in; i++) {
        const float* p = (const float*)d_in[i];
        switch (in_sizes[i]) {
            case 4194304:  x = p;      break;
            case 33554432: if (!pk) pk = p; else pv = p; break;
            case 3145728:  W_qkv = p;  break;
            case 3072:     b_qkv = p;  break;
            case 1048576:  W_out = p;  break;
            case 1024:     b_out = p;  break;
            default: break;
        }
    }
    if (!(x && pk && pv && W_qkv && b_qkv && W_out && b_out)) {
        if (n_in < 7) return;
        x     = (const float*)d_in[0];
        pk    = (const float*)d_in[1];
        pv    = (const float*)d_in[2];
        W_qkv = (const float*)d_in[3];
        b_qkv = (const float*)d_in[4];
        W_out = (const float*)d_in[5];
        b_out = (const float*)d_in[6];
    }

    float* out = (float*)d_out;

    static __nv_bfloat16 *s_ah = nullptr, *s_al = nullptr, *s_bh = nullptr, *s_bl = nullptr;
    if (!s_ah) {
        void* p = 0;
        cudaGetSymbolAddress(&p, g_a_hi);  s_ah = (__nv_bfloat16*)p;
        cudaGetSymbolAddress(&p, g_a_lo);  s_al = (__nv_bfloat16*)p;
        cudaGetSymbolAddress(&p, g_bt_hi); s_bh = (__nv_bfloat16*)p;
        cudaGetSymbolAddress(&p, g_bt_lo); s_bl = (__nv_bfloat16*)p;
        cudaFuncSetAttribute((const void*)hgemm_bf<0>,
                             cudaFuncAttributeMaxDynamicSharedMemorySize, HB_SMEM);
        cudaFuncSetAttribute((const void*)hgemm_bf<1>,
                             cudaFuncAttributeMaxDynamicSharedMemorySize, HB_SMEM);
        cudaFuncSetAttribute((const void*)attn_mma,
                             cudaFuncAttributeMaxDynamicSharedMemorySize, AT_SMEM);
    }

    float* kvbuf = out + OUT_ELEMS;   // [out | k | v] element layout

    // prep: split x; split+transpose W_qkv
    split_a_kernel<<<OUT_ELEMS / 1024, 256>>>((const float4*)x, (uint2*)s_ah, (uint2*)s_al);
    {
        dim3 grid(3 * D_MODEL / 32, D_MODEL / 32);
        split_wt_kernel<<<grid, dim3(32, 8)>>>(W_qkv, s_bh, s_bl, 3 * D_MODEL);
    }
    // 1) QKV GEMM (emits q/k/v + pre-split attention operands)
    {
        dim3 grid(3 * D_MODEL / 128, M_TOT / 128);
        hgemm_bf<0><<<grid, 256, HB_SMEM>>>((const uint4*)s_ah, (const uint4*)s_al,
                                            (const uint4*)s_bh, (const uint4*)s_bl,
                                            b_qkv, kvbuf);
    }
    // 2a) memory attention partials (coalesced warp-per-query)
    {
        dim3 grid(SEQ / 8, BATCH * N_HEADS);
        memattn_kernel<<<grid, 256>>>(pk, pv);
    }
    // 2b) token flash attention + merge (writes ctx bf16 hi/lo)
    {
        dim3 grid(SEQ / 128, BATCH * N_HEADS);
        attn_mma<<<grid, 256, AT_SMEM>>>();
    }
    // prep: split+transpose W_out
    {
        dim3 grid(D_MODEL / 32, D_MODEL / 32);
        split_wt_kernel<<<grid, dim3(32, 8)>>>(W_out, s_bh, s_bl, D_MODEL);
    }
    // 3) output GEMM (A = ctx hi/lo from attn epilogue)
    {
        dim3 grid(D_MODEL / 128, M_TOT / 128);
        hgemm_bf<1><<<grid, 256, HB_SMEM>>>((const uint4*)s_ah, (const uint4*)s_al,
                                            (const uint4*)s_bh, (const uint4*)s_bl,
                                            b_out, out);
    }
}

// round 15
// speedup vs baseline: 2.6666x; 1.0195x over previous
#include <cuda_runtime.h>
#include <cuda_bf16.h>
#include <cstdint>

#define D_MODEL  1024
#define N_HEADS  16
#define HEAD_DIM 64
#define BATCH    2
#define SEQ      2048
#define LMEM     8
#define M_TOT    (BATCH * SEQ)            // 4096
#define OUT_ELEMS (M_TOT * D_MODEL)       // 4194304
#define KV_ELEMS  (BATCH * N_HEADS * SEQ * HEAD_DIM)  // 4194304 each

typedef unsigned long long ull;

// scratch (no cudaMalloc). NEVER pass these directly as host-side kernel args
// (host stub address + GB300 ATS = silent host reads) — use cudaGetSymbolAddress
// or reference in device code.
__device__ float g_q[M_TOT * D_MODEL];
__device__ float g_ctx[M_TOT * D_MODEL];           // memattn macc lives here
__device__ float g_msum[BATCH * N_HEADS * SEQ];    // memattn partial softmax sums
__device__ __nv_bfloat16 g_a_hi[M_TOT * D_MODEL];  // GEMM A split (x, then ctx)
__device__ __nv_bfloat16 g_a_lo[M_TOT * D_MODEL];
__device__ __nv_bfloat16 g_bt_hi[3 * D_MODEL * D_MODEL];
__device__ __nv_bfloat16 g_bt_lo[3 * D_MODEL * D_MODEL];
__device__ __nv_bfloat16 g_qh[M_TOT * D_MODEL];    // q*0.125 hi/lo, [bh][s][d]
__device__ __nv_bfloat16 g_ql[M_TOT * D_MODEL];
__device__ __nv_bfloat16 g_kh[KV_ELEMS];           // [bh][s][d]
__device__ __nv_bfloat16 g_kl[KV_ELEMS];
__device__ __nv_bfloat16 g_vth[KV_ELEMS];          // [bh][d][s]
__device__ __nv_bfloat16 g_vtl[KV_ELEMS];

// ---- bf16 helpers ------------------------------------------------------------
__device__ __forceinline__ uint32_t bf2(float lo, float hi) {   // low16=lo, high16=hi
    uint32_t r;
    asm("cvt.rn.bf16x2.f32 %0, %1, %2;" : "=r"(r) : "f"(hi), "f"(lo));
    return r;
}
__device__ __forceinline__ float bf_lo_f(uint32_t h) { return __uint_as_float(h << 16); }
__device__ __forceinline__ float bf_hi_f(uint32_t h) { return __uint_as_float(h & 0xFFFF0000u); }

__device__ __forceinline__ void mma_bf16(float* c,
                                         uint32_t a0, uint32_t a1, uint32_t a2, uint32_t a3,
                                         uint32_t b0, uint32_t b1) {
    asm volatile(
        "mma.sync.aligned.m16n8k16.row.col.f32.bf16.bf16.f32 "
        "{%0,%1,%2,%3}, {%4,%5,%6,%7}, {%8,%9}, {%0,%1,%2,%3};"
        : "+f"(c[0]), "+f"(c[1]), "+f"(c[2]), "+f"(c[3])
        : "r"(a0), "r"(a1), "r"(a2), "r"(a3), "r"(b0), "r"(b1));
}

// ---- ldmatrix (LDSM) ----------------------------------------------------------
__device__ __forceinline__ void ldsm4(uint32_t* r, uint32_t addr) {
    asm volatile("ldmatrix.sync.aligned.m8n8.x4.shared.b16 {%0,%1,%2,%3}, [%4];"
        : "=r"(r[0]), "=r"(r[1]), "=r"(r[2]), "=r"(r[3]) : "r"(addr));
}
__device__ __forceinline__ void ldsm2(uint32_t& r0, uint32_t& r1, uint32_t addr) {
    asm volatile("ldmatrix.sync.aligned.m8n8.x2.shared.b16 {%0,%1}, [%2];"
        : "=r"(r0), "=r"(r1) : "r"(addr));
}

// ---- cp.async (base sm_80 ISA; LDGSTS). SMEM dst MUST be 16B aligned. ---------
__device__ __forceinline__ uint32_t smem_u32(const void* p) {
    uint32_t a;
    asm("{ .reg .u64 t; cvta.to.shared.u64 t, %1; cvt.u32.u64 %0, t; }"
        : "=r"(a) : "l"(p));
    return a;
}
__device__ __forceinline__ void cpa16(uint32_t smaddr, const void* gptr) {
    asm volatile("cp.async.cg.shared.global [%0], [%1], 16;"
                 :: "r"(smaddr), "l"(__cvta_generic_to_global(gptr)));
}
__device__ __forceinline__ void cpc() {
    asm volatile("cp.async.commit_group;");
}
template <int N>
__device__ __forceinline__ void cpw() {
    asm volatile("cp.async.wait_group %0;" :: "n"(N));
}

// ---------------------------------------------------------------------------
// Prep kernels (proven)
// ---------------------------------------------------------------------------
__global__ __launch_bounds__(256)
void split_a_kernel(const float4* __restrict__ src,
                    uint2* __restrict__ hi, uint2* __restrict__ lo)
{
    int i = blockIdx.x * 256 + threadIdx.x;
    float4 v = src[i];
    uint32_t h01 = bf2(v.x, v.y), h23 = bf2(v.z, v.w);
    uint32_t l01 = bf2(v.x - bf_lo_f(h01), v.y - bf_hi_f(h01));
    uint32_t l23 = bf2(v.z - bf_lo_f(h23), v.w - bf_hi_f(h23));
    hi[i] = make_uint2(h01, h23);
    lo[i] = make_uint2(l01, l23);
}

__global__ __launch_bounds__(256)
void split_wt_kernel(const float* __restrict__ W,
                     __nv_bfloat16* __restrict__ hiT,
                     __nv_bfloat16* __restrict__ loT,
                     int N)
{
    __shared__ float t[32][33];
    const int tx = threadIdx.x, ty = threadIdx.y;
    const int n0 = blockIdx.x * 32, k0 = blockIdx.y * 32;
#pragma unroll
    for (int i = 0; i < 4; i++)
        t[ty + 8 * i][tx] = W[(size_t)(k0 + ty + 8 * i) * N + n0 + tx];
    __syncthreads();
#pragma unroll
    for (int i = 0; i < 4; i++) {
        int n = n0 + ty + 8 * i;
        float f = t[tx][ty + 8 * i];
        __nv_bfloat16 h = __float2bfloat16(f);
        __nv_bfloat16 l = __float2bfloat16(f - __bfloat162float(h));
        hiT[(size_t)n * 1024 + k0 + tx] = h;
        loT[(size_t)n * 1024 + k0 + tx] = l;
    }
}

// ---------------------------------------------------------------------------
// Memory attention — warp-per-query, fully coalesced (proven round 14).
// ---------------------------------------------------------------------------
__global__ __launch_bounds__(256)
void memattn_kernel(const float* __restrict__ pk, const float* __restrict__ pv)
{
    const int tid  = threadIdx.x;
    const int wid  = tid >> 5;
    const int lane = tid & 31;
    const int half = lane >> 4;
    const int d4   = (lane & 15) * 4;
    const int bh   = blockIdx.y;
    const int b    = bh >> 4, h = bh & 15;
    const int qrow = blockIdx.x * 8 + wid;
    const float MX = 20.0f;

    float4 q4;
    {
        const float* qp = g_q + ((size_t)(b * SEQ + qrow) * D_MODEL + h * HEAD_DIM + d4);
        q4 = *(const float4*)qp;
        q4.x *= 0.125f; q4.y *= 0.125f; q4.z *= 0.125f; q4.w *= 0.125f;
    }

    const size_t blk = ((size_t)bh * SEQ + qrow) * (LMEM * HEAD_DIM);
    const float* kp = pk + blk;
    const float* vp = pv + blk;

    float4 acc = make_float4(0.f, 0.f, 0.f, 0.f);
    float lsum = 0.0f;

#pragma unroll
    for (int p = 0; p < 4; p++) {
        const int key = 2 * p + half;
        float4 k4 = *(const float4*)(kp + key * HEAD_DIM + d4);
        float d = q4.x * k4.x + q4.y * k4.y + q4.z * k4.z + q4.w * k4.w;
        d += __shfl_xor_sync(0xFFFFFFFFu, d, 1);
        d += __shfl_xor_sync(0xFFFFFFFFu, d, 2);
        d += __shfl_xor_sync(0xFFFFFFFFu, d, 4);
        d += __shfl_xor_sync(0xFFFFFFFFu, d, 8);
        float pe = __expf(d - MX);
        lsum += pe;
        float4 v4 = *(const float4*)(vp + key * HEAD_DIM + d4);
        acc.x += pe * v4.x;
        acc.y += pe * v4.y;
        acc.z += pe * v4.z;
        acc.w += pe * v4.w;
    }
    acc.x += __shfl_xor_sync(0xFFFFFFFFu, acc.x, 16);
    acc.y += __shfl_xor_sync(0xFFFFFFFFu, acc.y, 16);
    acc.z += __shfl_xor_sync(0xFFFFFFFFu, acc.z, 16);
    acc.w += __shfl_xor_sync(0xFFFFFFFFu, acc.w, 16);
    lsum  += __shfl_xor_sync(0xFFFFFFFFu, lsum, 16);

    if (lane < 16)
        *(float4*)(g_ctx + ((size_t)(b * SEQ + qrow)) * D_MODEL + h * HEAD_DIM + d4) = acc;
    if (lane == 0)
        g_msum[(size_t)bh * SEQ + qrow] = lsum;
}

// ---------------------------------------------------------------------------
// bf16 mma.sync GEMM, hi/lo 3-term. cp.async double-buffered, K=32 chunks.
// PITCH-12 rows (48B). Fragment loads via ldmatrix (x4 for A, x2 for B).
// ---------------------------------------------------------------------------
#define HG_ARR 3072                        // words per array (2*128*12)
#define HG_STG (4 * HG_ARR)                // 12288 words per stage
#define HB_SMEM (2 * HG_STG * 4)           // 98304 B

template <int MODE>
__global__ __launch_bounds__(256, 2)
void hgemm_bf(const uint4* __restrict__ Ah, const uint4* __restrict__ Al,
              const uint4* __restrict__ Bh, const uint4* __restrict__ Bl,
              const float* __restrict__ bias,
              float* __restrict__ C)
{
    extern __shared__ uint32_t sm[];
    const uint32_t smb = smem_u32(sm);

    const int tid   = threadIdx.x;
    const int wid   = tid >> 5;
    const int lane  = tid & 31;
    const int warpM = wid & 1;
    const int warpN = wid >> 1;
    const int row0  = blockIdx.y * 128;
    const int col0  = blockIdx.x * 128;
    const int lq    = lane >> 2;
    const int lr    = lane & 3;

    // ldmatrix per-lane address components (word offsets within an array)
    const int a_row  = warpM * 64 + (lane & 15);      // + mt*16
    const int a_half = (lane >> 4) & 1;                // k-half (x4 groups 2,3)
    const int b_row  = warpN * 32 + (lane & 7);        // + nt*8
    const int b_half = (lane >> 3) & 1;                // x2: t0-7 half0, t8-15 half1

    float acc[4][4][4];
#pragma unroll
    for (int a = 0; a < 4; a++)
#pragma unroll
        for (int b = 0; b < 4; b++)
#pragma unroll
            for (int c = 0; c < 4; c++) acc[a][b][c] = 0.0f;

#define CPA_CHUNK(kt, stg)                                                   \
    {                                                                        \
        uint32_t sb = smb + (stg) * (HG_STG * 4);                            \
        _Pragma("unroll")                                                    \
        for (int i = 0; i < 2; i++) {                                        \
            int e = tid + i * 256;                                           \
            int m = e >> 2, seg = e & 3;                                     \
            uint32_t idx = (uint32_t)(((((seg >> 1) * 128 + m) * 12) + (seg & 1) * 4) * 4); \
            size_t ga = (size_t)(row0 + m) * 128 + (size_t)(kt) * 4 + seg;   \
            size_t gb = (size_t)(col0 + m) * 128 + (size_t)(kt) * 4 + seg;   \
            cpa16(sb + idx,                Ah + ga);                         \
            cpa16(sb + HG_ARR * 4 + idx,   Al + ga);                         \
            cpa16(sb + HG_ARR * 8 + idx,   Bh + gb);                         \
            cpa16(sb + HG_ARR * 12 + idx,  Bl + gb);                         \
        }                                                                    \
        cpc();                                                               \
    }

    CPA_CHUNK(0, 0);
    CPA_CHUNK(1, 1);

#pragma unroll 1
    for (int kt = 0; kt < 32; kt++) {
        const int s = kt & 1;
        if (kt + 1 < 32) cpw<1>(); else cpw<0>();
        __syncthreads();

        const uint32_t sbase = smb + s * (HG_STG * 4);
#pragma unroll
        for (int ks = 0; ks < 2; ks++) {
            uint32_t ahf[4][4], alf[4][4];
#pragma unroll
            for (int mt = 0; mt < 4; mt++) {
                uint32_t aaddr = sbase +
                    (uint32_t)(((ks * 128 + a_row + mt * 16) * 12 + a_half * 4) * 4);
                ldsm4(ahf[mt], aaddr);
                ldsm4(alf[mt], aaddr + HG_ARR * 4);
            }
            uint32_t bhf[4][2], blf[4][2];
#pragma unroll
            for (int nt = 0; nt < 4; nt++) {
                uint32_t baddr = sbase + HG_ARR * 8 +
                    (uint32_t)(((ks * 128 + b_row + nt * 8) * 12 + b_half * 4) * 4);
                ldsm2(bhf[nt][0], bhf[nt][1], baddr);
                ldsm2(blf[nt][0], blf[nt][1], baddr + HG_ARR * 4);
            }
#pragma unroll
            for (int mt = 0; mt < 4; mt++)
#pragma unroll
                for (int nt = 0; nt < 4; nt++) {
                    mma_bf16(acc[mt][nt], ahf[mt][0], ahf[mt][1], ahf[mt][2], ahf[mt][3],
                             bhf[nt][0], bhf[nt][1]);
                    mma_bf16(acc[mt][nt], ahf[mt][0], ahf[mt][1], ahf[mt][2], ahf[mt][3],
                             blf[nt][0], blf[nt][1]);
                    mma_bf16(acc[mt][nt], alf[mt][0], alf[mt][1], alf[mt][2], alf[mt][3],
                             bhf[nt][0], bhf[nt][1]);
                }
        }
        __syncthreads();
        if (kt + 2 < 32) CPA_CHUNK(kt + 2, s);
    }
#undef CPA_CHUNK

    // ---- epilogue (pairwise over n) ----
#pragma unroll
    for (int mt = 0; mt < 4; mt++) {
        int mb = row0 + warpM * 64 + mt * 16 + lq;
#pragma unroll
        for (int nt = 0; nt < 4; nt++) {
            int n0 = col0 + warpN * 32 + nt * 8 + lr * 2;
            float bi0 = __ldg(bias + n0), bi1 = __ldg(bias + n0 + 1);
#pragma unroll
            for (int rh = 0; rh < 2; rh++) {
                int m = mb + rh * 8;
                float v0 = acc[mt][nt][rh * 2 + 0] + bi0;
                float v1 = acc[mt][nt][rh * 2 + 1] + bi1;
                if (MODE == 1) {
                    *(float2*)(C + (size_t)m * 1024 + n0) = make_float2(v0, v1);
                } else {
                    int b = m >> 11;
                    int s = m & 2047;
                    if (n0 < D_MODEL) {
                        *(float2*)(g_q + (size_t)m * 1024 + n0) = make_float2(v0, v1);
                        float q0 = v0 * 0.125f, q1 = v1 * 0.125f;
                        uint32_t hh = bf2(q0, q1);
                        uint32_t ll = bf2(q0 - bf_lo_f(hh), q1 - bf_hi_f(hh));
                        size_t qo = ((size_t)(b * 16 + (n0 >> 6)) * SEQ + s) * 64 + (n0 & 63);
                        *(uint32_t*)(g_qh + qo) = hh;
                        *(uint32_t*)(g_ql + qo) = ll;
                    } else {
                        int cc = n0 - D_MODEL;
                        int which = cc >> 10;
                        cc &= 1023;
                        int hd = cc >> 6, d = cc & 63;
                        size_t so = ((size_t)(b * 16 + hd) * SEQ + s) * 64 + d;
                        *(float2*)(C + (size_t)which * KV_ELEMS + so) = make_float2(v0, v1);
                        uint32_t hp = bf2(v0, v1);
                        uint32_t lp = bf2(v0 - bf_lo_f(hp), v1 - bf_hi_f(hp));
                        if (which == 0) {
                            *(uint32_t*)(g_kh + so) = hp;
                            *(uint32_t*)(g_kl + so) = lp;
                        } else {
                            size_t vo = ((size_t)(b * 16 + hd) * 64 + d) * SEQ + s;
                            __nv_bfloat16 h0 = __float2bfloat16(v0);
                            __nv_bfloat16 h1 = __float2bfloat16(v1);
                            g_vth[vo] = h0;
                            g_vtl[vo] = __float2bfloat16(v0 - __bfloat162float(h0));
                            g_vth[vo + SEQ] = h1;
                            g_vtl[vo + SEQ] = __float2bfloat16(v1 - __bfloat162float(h1));
                        }
                    }
                }
            }
        }
    }
}

// ---------------------------------------------------------------------------
// Flash attention on mma.sync. Q fragments in registers; K/V frags via
// ldmatrix.x2. Heavy tiles scheduled first (reversed qt). 2 CTAs/SM.
// ---------------------------------------------------------------------------
#define AT_ARR 3072                        // words per KV array (4*64*12)
#define AT_STG (4 * AT_ARR)                // 12288 words per stage
#define AT_SMEM (2 * AT_STG * 4)           // 98304 B

__global__ __launch_bounds__(256, 2)
void attn_mma()
{
    extern __shared__ uint32_t sm[];
    const uint32_t smb = smem_u32(sm);

    const int tid = threadIdx.x;
    const int wid = tid >> 5;
    const int lane = tid & 31;
    const int lq = lane >> 2;
    const int lr = lane & 3;
    const int qt = (int)gridDim.x - 1 - (int)blockIdx.x;   // heavy tiles first
    const int bh = blockIdx.y;
    const int b = bh >> 4, h = bh & 15;
    const float MX = 20.0f;

    const int kv_row  = lane & 7;            // + nb*8
    const int kv_half = (lane >> 3) & 1;

    const uint4* Qh4 = (const uint4*)g_qh;
    const uint4* Ql4 = (const uint4*)g_ql;
    const uint4* Kh4 = (const uint4*)g_kh;
    const uint4* Kl4 = (const uint4*)g_kl;
    const uint4* Vh4 = (const uint4*)g_vth;
    const uint4* Vl4 = (const uint4*)g_vtl;

    // ---- stage Q tile through stage-0 SMEM -> registers, then release ----
    uint32_t qh[4][4], ql[4][4];
    {
        const size_t q0 = ((size_t)bh * SEQ + qt * 128) * 8;
#pragma unroll
        for (int i = 0; i < 4; i++) {
            int e = tid + i * 256;
            int m = e >> 3, seg = e & 7;
            uint4 vh = Qh4[q0 + m * 8 + seg];
            uint4 vl = Ql4[q0 + m * 8 + seg];
            int idx = ((seg >> 1) * 128 + m) * 12 + (seg & 1) * 4;
            sm[idx] = vh.x; sm[idx+1] = vh.y; sm[idx+2] = vh.z; sm[idx+3] = vh.w;
            sm[6144 + idx] = vl.x; sm[6144 + idx+1] = vl.y;
            sm[6144 + idx+2] = vl.z; sm[6144 + idx+3] = vl.w;
        }
        __syncthreads();
#pragma unroll
        for (int ks = 0; ks < 4; ks++) {
            int aidx = (ks * 128 + wid * 16 + lq) * 12 + lr;
            qh[ks][0] = sm[aidx];       qh[ks][1] = sm[aidx + 96];
            qh[ks][2] = sm[aidx + 4];   qh[ks][3] = sm[aidx + 100];
            ql[ks][0] = sm[6144 + aidx];     ql[ks][1] = sm[6144 + aidx + 96];
            ql[ks][2] = sm[6144 + aidx + 4]; ql[ks][3] = sm[6144 + aidx + 100];
        }
        __syncthreads();
    }

#define CPAKV(c, stg)                                                        \
    {                                                                        \
        uint32_t sb = smb + (stg) * (AT_STG * 4);                            \
        int kt0_ = (c) * 64;                                                 \
        _Pragma("unroll")                                                    \
        for (int i = 0; i < 2; i++) {                                        \
            int e = tid + i * 256;                                           \
            int m = e >> 3, seg = e & 7;                                     \
            uint32_t idx = (uint32_t)(((((seg >> 1) * 64 + m) * 12) + (seg & 1) * 4) * 4); \
            size_t ki = ((size_t)bh * SEQ + kt0_ + m) * 8 + seg;             \
            size_t vi = ((size_t)bh * 64 + m) * 256 + (kt0_ >> 3) + seg;     \
            cpa16(sb + idx,               Kh4 + ki);                         \
            cpa16(sb + AT_ARR * 4 + idx,  Kl4 + ki);                         \
            cpa16(sb + AT_ARR * 8 + idx,  Vh4 + vi);                         \
            cpa16(sb + AT_ARR * 12 + idx, Vl4 + vi);                         \
        }                                                                    \
        cpc();                                                               \
    }

    const int nch = 2 * qt + 2;
    const int gr0 = qt * 128 + wid * 16;

    CPAKV(0, 0);
    CPAKV(1, 1);

    float O[8][4];
#pragma unroll
    for (int nb = 0; nb < 8; nb++)
#pragma unroll
        for (int q = 0; q < 4; q++) O[nb][q] = 0.0f;
    float lsum0 = 0.0f, lsum1 = 0.0f;

#pragma unroll 1
    for (int c = 0; c < nch; c++) {
        const int s = c & 1;
        if (c + 1 < nch) cpw<1>(); else cpw<0>();
        __syncthreads();

        const int kt0 = c * 64;
        if (kt0 <= gr0 + 15) {
            const uint32_t kstage = smb + s * (AT_STG * 4);

            float S[8][4];
#pragma unroll
            for (int nb = 0; nb < 8; nb++)
#pragma unroll
                for (int q = 0; q < 4; q++) S[nb][q] = 0.0f;
#pragma unroll
            for (int ks = 0; ks < 4; ks++) {
#pragma unroll
                for (int nb = 0; nb < 8; nb++) {
                    uint32_t kaddr = kstage +
                        (uint32_t)(((ks * 64 + nb * 8 + kv_row) * 12 + kv_half * 4) * 4);
                    uint32_t bh0, bh1, bl0, bl1;
                    ldsm2(bh0, bh1, kaddr);
                    ldsm2(bl0, bl1, kaddr + AT_ARR * 4);
                    mma_bf16(S[nb], qh[ks][0], qh[ks][1], qh[ks][2], qh[ks][3], bh0, bh1);
                    mma_bf16(S[nb], qh[ks][0], qh[ks][1], qh[ks][2], qh[ks][3], bl0, bl1);
                    mma_bf16(S[nb], ql[ks][0], ql[ks][1], ql[ks][2], ql[ks][3], bh0, bh1);
                }
            }
            const int r0 = gr0 + lq, r1 = r0 + 8;
            float p[8][4];
#pragma unroll
            for (int nb = 0; nb < 8; nb++) {
                int c0 = kt0 + nb * 8 + 2 * lr;
                p[nb][0] = (c0     <= r0) ? __expf(S[nb][0] - MX) : 0.0f;
                p[nb][1] = (c0 + 1 <= r0) ? __expf(S[nb][1] - MX) : 0.0f;
                p[nb][2] = (c0     <= r1) ? __expf(S[nb][2] - MX) : 0.0f;
                p[nb][3] = (c0 + 1 <= r1) ? __expf(S[nb][3] - MX) : 0.0f;
                lsum0 += p[nb][0] + p[nb][1];
                lsum1 += p[nb][2] + p[nb][3];
            }
#pragma unroll
            for (int ks = 0; ks < 4; ks++) {
                uint32_t ph0 = bf2(p[2*ks][0],   p[2*ks][1]);
                uint32_t ph1 = bf2(p[2*ks][2],   p[2*ks][3]);
                uint32_t ph2 = bf2(p[2*ks+1][0], p[2*ks+1][1]);
                uint32_t ph3 = bf2(p[2*ks+1][2], p[2*ks+1][3]);
                uint32_t pl0 = bf2(p[2*ks][0] - bf_lo_f(ph0),   p[2*ks][1] - bf_hi_f(ph0));
                uint32_t pl1 = bf2(p[2*ks][2] - bf_lo_f(ph1),   p[2*ks][3] - bf_hi_f(ph1));
                uint32_t pl2 = bf2(p[2*ks+1][0] - bf_lo_f(ph2), p[2*ks+1][1] - bf_hi_f(ph2));
                uint32_t pl3 = bf2(p[2*ks+1][2] - bf_lo_f(ph3), p[2*ks+1][3] - bf_hi_f(ph3));
#pragma unroll
                for (int nb = 0; nb < 8; nb++) {
                    uint32_t vaddr = kstage + AT_ARR * 8 +
                        (uint32_t)(((ks * 64 + nb * 8 + kv_row) * 12 + kv_half * 4) * 4);
                    uint32_t vh0, vh1, vl0, vl1;
                    ldsm2(vh0, vh1, vaddr);
                    ldsm2(vl0, vl1, vaddr + AT_ARR * 4);
                    mma_bf16(O[nb], ph0, ph1, ph2, ph3, vh0, vh1);
                    mma_bf16(O[nb], pl0, pl1, pl2, pl3, vh0, vh1);
                    mma_bf16(O[nb], ph0, ph1, ph2, ph3, vl0, vl1);
                }
            }
        }
        __syncthreads();
        if (c + 2 < nch) CPAKV(c + 2, s);
    }
#undef CPAKV

    // ---- epilogue: merge memattn partials, normalize, emit ctx bf16 hi/lo ----
    lsum0 += __shfl_xor_sync(0xFFFFFFFFu, lsum0, 1);
    lsum0 += __shfl_xor_sync(0xFFFFFFFFu, lsum0, 2);
    lsum1 += __shfl_xor_sync(0xFFFFFFFFu, lsum1, 1);
    lsum1 += __shfl_xor_sync(0xFFFFFFFFu, lsum1, 2);

    const int rl0 = wid * 16 + lq, rl1 = rl0 + 8;
    const int row0g = qt * 128;
    const float inv0 = 1.0f / (lsum0 + g_msum[(size_t)bh * SEQ + row0g + rl0]);
    const float inv1 = 1.0f / (lsum1 + g_msum[(size_t)bh * SEQ + row0g + rl1]);
    const size_t c0base = ((size_t)(b * SEQ + row0g + rl0)) * D_MODEL + h * HEAD_DIM;
    const size_t c1base = ((size_t)(b * SEQ + row0g + rl1)) * D_MODEL + h * HEAD_DIM;
#pragma unroll
    for (int nb = 0; nb < 8; nb++) {
        int col = nb * 8 + 2 * lr;
        float2 m0 = *(float2*)(g_ctx + c0base + col);
        float2 m1 = *(float2*)(g_ctx + c1base + col);
        float o0x = (O[nb][0] + m0.x) * inv0;
        float o0y = (O[nb][1] + m0.y) * inv0;
        float o1x = (O[nb][2] + m1.x) * inv1;
        float o1y = (O[nb][3] + m1.y) * inv1;
        uint32_t h0 = bf2(o0x, o0y);
        uint32_t l0 = bf2(o0x - bf_lo_f(h0), o0y - bf_hi_f(h0));
        uint32_t h1 = bf2(o1x, o1y);
        uint32_t l1 = bf2(o1x - bf_lo_f(h1), o1y - bf_hi_f(h1));
        *(uint32_t*)(g_a_hi + c0base + col) = h0;
        *(uint32_t*)(g_a_lo + c0base + col) = l0;
        *(uint32_t*)(g_a_hi + c1base + col) = h1;
        *(uint32_t*)(g_a_lo + c1base + col) = l1;
    }
}

// ---------------------------------------------------------------------------
extern "C" void kernel_launch(void* const* d_in, const int* in_sizes, int n_in,
                              void* d_out, int out_size)
{
    const float* x = 0; const float* pk = 0; const float* pv = 0;
    const float* W_qkv = 0; const float* b_qkv = 0;
    const float* W_out = 0; const float* b_out = 0;
    for (int i = 0; i < n_in; i++) {
        const float* p = (const float*)d_in[i];
        switch (in_sizes[i]) {
            case 4194304:  x = p;      break;
            case 33554432: if (!pk) pk = p; else pv = p; break;
            case 3145728:  W_qkv = p;  break;
            case 3072:     b_qkv = p;  break;
            case 1048576:  W_out = p;  break;
            case 1024:     b_out = p;  break;
            default: break;
        }
    }
    if (!(x && pk && pv && W_qkv && b_qkv && W_out && b_out)) {
        if (n_in < 7) return;
        x     = (const float*)d_in[0];
        pk    = (const float*)d_in[1];
        pv    = (const float*)d_in[2];
        W_qkv = (const float*)d_in[3];
        b_qkv = (const float*)d_in[4];
        W_out = (const float*)d_in[5];
        b_out = (const float*)d_in[6];
    }

    float* out = (float*)d_out;

    static __nv_bfloat16 *s_ah = nullptr, *s_al = nullptr, *s_bh = nullptr, *s_bl = nullptr;
    if (!s_ah) {
        void* p = 0;
        cudaGetSymbolAddress(&p, g_a_hi);  s_ah = (__nv_bfloat16*)p;
        cudaGetSymbolAddress(&p, g_a_lo);  s_al = (__nv_bfloat16*)p;
        cudaGetSymbolAddress(&p, g_bt_hi); s_bh = (__nv_bfloat16*)p;
        cudaGetSymbolAddress(&p, g_bt_lo); s_bl = (__nv_bfloat16*)p;
        cudaFuncSetAttribute((const void*)hgemm_bf<0>,
                             cudaFuncAttributeMaxDynamicSharedMemorySize, HB_SMEM);
        cudaFuncSetAttribute((const void*)hgemm_bf<1>,
                             cudaFuncAttributeMaxDynamicSharedMemorySize, HB_SMEM);
        cudaFuncSetAttribute((const void*)attn_mma,
                             cudaFuncAttributeMaxDynamicSharedMemorySize, AT_SMEM);
    }

    float* kvbuf = out + OUT_ELEMS;   // [out | k | v] element layout

    // prep: split x; split+transpose W_qkv
    split_a_kernel<<<OUT_ELEMS / 1024, 256>>>((const float4*)x, (uint2*)s_ah, (uint2*)s_al);
    {
        dim3 grid(3 * D_MODEL / 32, D_MODEL / 32);
        split_wt_kernel<<<grid, dim3(32, 8)>>>(W_qkv, s_bh, s_bl, 3 * D_MODEL);
    }
    // 1) QKV GEMM (emits q/k/v + pre-split attention operands)
    {
        dim3 grid(3 * D_MODEL / 128, M_TOT / 128);
        hgemm_bf<0><<<grid, 256, HB_SMEM>>>((const uint4*)s_ah, (const uint4*)s_al,
                                            (const uint4*)s_bh, (const uint4*)s_bl,
                                            b_qkv, kvbuf);
    }
    // 2a) memory attention partials (coalesced warp-per-query)
    {
        dim3 grid(SEQ / 8, BATCH * N_HEADS);
        memattn_kernel<<<grid, 256>>>(pk, pv);
    }
    // 2b) token flash attention + merge (writes ctx bf16 hi/lo)
    {
        dim3 grid(SEQ / 128, BATCH * N_HEADS);
        attn_mma<<<grid, 256, AT_SMEM>>>();
    }
    // prep: split+transpose W_out
    {
        dim3 grid(D_MODEL / 32, D_MODEL / 32);
        split_wt_kernel<<<grid, dim3(32, 8)>>>(W_out, s_bh, s_bl, D_MODEL);
    }
    // 3) output GEMM (A = ctx hi/lo from attn epilogue)
    {
        dim3 grid(D_MODEL / 128, M_TOT / 128);
        hgemm_bf<1><<<grid, 256, HB_SMEM>>>((const uint4*)s_ah, (const uint4*)s_al,
                                            (const uint4*)s_bh, (const uint4*)s_bl,
                                            b_out, out);
    }
}

// round 16
// speedup vs baseline: 2.8244x; 1.0592x over previous
#include <cuda_runtime.h>
#include <cuda_bf16.h>
#include <cstdint>

#define D_MODEL  1024
#define N_HEADS  16
#define HEAD_DIM 64
#define BATCH    2
#define SEQ      2048
#define LMEM     8
#define M_TOT    (BATCH * SEQ)            // 4096
#define OUT_ELEMS (M_TOT * D_MODEL)       // 4194304
#define KV_ELEMS  (BATCH * N_HEADS * SEQ * HEAD_DIM)  // 4194304 each

typedef unsigned long long ull;

// scratch (no cudaMalloc). NEVER pass these directly as host-side kernel args
// (host stub address + GB300 ATS = silent host reads) — use cudaGetSymbolAddress
// or reference in device code.
__device__ float g_q[M_TOT * D_MODEL];
__device__ float g_ctx[M_TOT * D_MODEL];           // memattn macc
__device__ float g_msum[BATCH * N_HEADS * SEQ];    // memattn partial sums
__device__ float g_part[32 * 16 * 4 * 128 * 64];   // attn split-K O partials (64MB)
__device__ float g_psum[32 * 16 * 4 * 128];        // attn split-K lsum partials
__device__ __nv_bfloat16 g_a_hi[M_TOT * D_MODEL];  // GEMM A split (x, then ctx)
__device__ __nv_bfloat16 g_a_lo[M_TOT * D_MODEL];
__device__ __nv_bfloat16 g_bt_hi[3 * D_MODEL * D_MODEL];
__device__ __nv_bfloat16 g_bt_lo[3 * D_MODEL * D_MODEL];
__device__ __nv_bfloat16 g_qh[M_TOT * D_MODEL];    // q*0.125 hi/lo, [bh][s][d]
__device__ __nv_bfloat16 g_ql[M_TOT * D_MODEL];
__device__ __nv_bfloat16 g_kh[KV_ELEMS];           // [bh][s][d]
__device__ __nv_bfloat16 g_kl[KV_ELEMS];
__device__ __nv_bfloat16 g_vth[KV_ELEMS];          // [bh][d][s]
__device__ __nv_bfloat16 g_vtl[KV_ELEMS];

// attn tile table: code = qt*4 + kb, heavy tiles (8 chunks) first.
__constant__ unsigned char c_tiles[40] = {
    60,61,62,63, 56,57,58, 52,53,54, 48,49,50, 44,45,46,
    40,41, 36,37, 32,33, 28,29, 24, 20, 16, 12,
    59,42,25,8,  55,38,21,4,  51,34,17,0
};

// ---- bf16 helpers ------------------------------------------------------------
__device__ __forceinline__ uint32_t bf2(float lo, float hi) {   // low16=lo, high16=hi
    uint32_t r;
    asm("cvt.rn.bf16x2.f32 %0, %1, %2;" : "=r"(r) : "f"(hi), "f"(lo));
    return r;
}
__device__ __forceinline__ float bf_lo_f(uint32_t h) { return __uint_as_float(h << 16); }
__device__ __forceinline__ float bf_hi_f(uint32_t h) { return __uint_as_float(h & 0xFFFF0000u); }

__device__ __forceinline__ void mma_bf16(float* c,
                                         uint32_t a0, uint32_t a1, uint32_t a2, uint32_t a3,
                                         uint32_t b0, uint32_t b1) {
    asm volatile(
        "mma.sync.aligned.m16n8k16.row.col.f32.bf16.bf16.f32 "
        "{%0,%1,%2,%3}, {%4,%5,%6,%7}, {%8,%9}, {%0,%1,%2,%3};"
        : "+f"(c[0]), "+f"(c[1]), "+f"(c[2]), "+f"(c[3])
        : "r"(a0), "r"(a1), "r"(a2), "r"(a3), "r"(b0), "r"(b1));
}

// ---- ldmatrix (LDSM) ----------------------------------------------------------
__device__ __forceinline__ void ldsm4(uint32_t* r, uint32_t addr) {
    asm volatile("ldmatrix.sync.aligned.m8n8.x4.shared.b16 {%0,%1,%2,%3}, [%4];"
        : "=r"(r[0]), "=r"(r[1]), "=r"(r[2]), "=r"(r[3]) : "r"(addr));
}
__device__ __forceinline__ void ldsm2(uint32_t& r0, uint32_t& r1, uint32_t addr) {
    asm volatile("ldmatrix.sync.aligned.m8n8.x2.shared.b16 {%0,%1}, [%2];"
        : "=r"(r0), "=r"(r1) : "r"(addr));
}

// ---- cp.async -----------------------------------------------------------------
__device__ __forceinline__ uint32_t smem_u32(const void* p) {
    uint32_t a;
    asm("{ .reg .u64 t; cvta.to.shared.u64 t, %1; cvt.u32.u64 %0, t; }"
        : "=r"(a) : "l"(p));
    return a;
}
__device__ __forceinline__ void cpa16(uint32_t smaddr, const void* gptr) {
    asm volatile("cp.async.cg.shared.global [%0], [%1], 16;"
                 :: "r"(smaddr), "l"(__cvta_generic_to_global(gptr)));
}
__device__ __forceinline__ void cpc() {
    asm volatile("cp.async.commit_group;");
}
template <int N>
__device__ __forceinline__ void cpw() {
    asm volatile("cp.async.wait_group %0;" :: "n"(N));
}

// ---------------------------------------------------------------------------
// Prep kernels (proven)
// ---------------------------------------------------------------------------
__global__ __launch_bounds__(256)
void split_a_kernel(const float4* __restrict__ src,
                    uint2* __restrict__ hi, uint2* __restrict__ lo)
{
    int i = blockIdx.x * 256 + threadIdx.x;
    float4 v = src[i];
    uint32_t h01 = bf2(v.x, v.y), h23 = bf2(v.z, v.w);
    uint32_t l01 = bf2(v.x - bf_lo_f(h01), v.y - bf_hi_f(h01));
    uint32_t l23 = bf2(v.z - bf_lo_f(h23), v.w - bf_hi_f(h23));
    hi[i] = make_uint2(h01, h23);
    lo[i] = make_uint2(l01, l23);
}

__global__ __launch_bounds__(256)
void split_wt_kernel(const float* __restrict__ W,
                     __nv_bfloat16* __restrict__ hiT,
                     __nv_bfloat16* __restrict__ loT,
                     int N)
{
    __shared__ float t[32][33];
    const int tx = threadIdx.x, ty = threadIdx.y;
    const int n0 = blockIdx.x * 32, k0 = blockIdx.y * 32;
#pragma unroll
    for (int i = 0; i < 4; i++)
        t[ty + 8 * i][tx] = W[(size_t)(k0 + ty + 8 * i) * N + n0 + tx];
    __syncthreads();
#pragma unroll
    for (int i = 0; i < 4; i++) {
        int n = n0 + ty + 8 * i;
        float f = t[tx][ty + 8 * i];
        __nv_bfloat16 h = __float2bfloat16(f);
        __nv_bfloat16 l = __float2bfloat16(f - __bfloat162float(h));
        hiT[(size_t)n * 1024 + k0 + tx] = h;
        loT[(size_t)n * 1024 + k0 + tx] = l;
    }
}

// ---------------------------------------------------------------------------
// Memory attention — warp-per-query, coalesced (proven round 14).
// ---------------------------------------------------------------------------
__global__ __launch_bounds__(256)
void memattn_kernel(const float* __restrict__ pk, const float* __restrict__ pv)
{
    const int tid  = threadIdx.x;
    const int wid  = tid >> 5;
    const int lane = tid & 31;
    const int half = lane >> 4;
    const int d4   = (lane & 15) * 4;
    const int bh   = blockIdx.y;
    const int b    = bh >> 4, h = bh & 15;
    const int qrow = blockIdx.x * 8 + wid;
    const float MX = 20.0f;

    float4 q4;
    {
        const float* qp = g_q + ((size_t)(b * SEQ + qrow) * D_MODEL + h * HEAD_DIM + d4);
        q4 = *(const float4*)qp;
        q4.x *= 0.125f; q4.y *= 0.125f; q4.z *= 0.125f; q4.w *= 0.125f;
    }

    const size_t blk = ((size_t)bh * SEQ + qrow) * (LMEM * HEAD_DIM);
    const float* kp = pk + blk;
    const float* vp = pv + blk;

    float4 acc = make_float4(0.f, 0.f, 0.f, 0.f);
    float lsum = 0.0f;

#pragma unroll
    for (int p = 0; p < 4; p++) {
        const int key = 2 * p + half;
        float4 k4 = *(const float4*)(kp + key * HEAD_DIM + d4);
        float d = q4.x * k4.x + q4.y * k4.y + q4.z * k4.z + q4.w * k4.w;
        d += __shfl_xor_sync(0xFFFFFFFFu, d, 1);
        d += __shfl_xor_sync(0xFFFFFFFFu, d, 2);
        d += __shfl_xor_sync(0xFFFFFFFFu, d, 4);
        d += __shfl_xor_sync(0xFFFFFFFFu, d, 8);
        float pe = __expf(d - MX);
        lsum += pe;
        float4 v4 = *(const float4*)(vp + key * HEAD_DIM + d4);
        acc.x += pe * v4.x;
        acc.y += pe * v4.y;
        acc.z += pe * v4.z;
        acc.w += pe * v4.w;
    }
    acc.x += __shfl_xor_sync(0xFFFFFFFFu, acc.x, 16);
    acc.y += __shfl_xor_sync(0xFFFFFFFFu, acc.y, 16);
    acc.z += __shfl_xor_sync(0xFFFFFFFFu, acc.z, 16);
    acc.w += __shfl_xor_sync(0xFFFFFFFFu, acc.w, 16);
    lsum  += __shfl_xor_sync(0xFFFFFFFFu, lsum, 16);

    if (lane < 16)
        *(float4*)(g_ctx + ((size_t)(b * SEQ + qrow)) * D_MODEL + h * HEAD_DIM + d4) = acc;
    if (lane == 0)
        g_msum[(size_t)bh * SEQ + qrow] = lsum;
}

// ---------------------------------------------------------------------------
// bf16 mma.sync GEMM, hi/lo 3-term (proven round 15).
// ---------------------------------------------------------------------------
#define HG_ARR 3072
#define HG_STG (4 * HG_ARR)
#define HB_SMEM (2 * HG_STG * 4)

template <int MODE>
__global__ __launch_bounds__(256, 2)
void hgemm_bf(const uint4* __restrict__ Ah, const uint4* __restrict__ Al,
              const uint4* __restrict__ Bh, const uint4* __restrict__ Bl,
              const float* __restrict__ bias,
              float* __restrict__ C)
{
    extern __shared__ uint32_t sm[];
    const uint32_t smb = smem_u32(sm);

    const int tid   = threadIdx.x;
    const int wid   = tid >> 5;
    const int lane  = tid & 31;
    const int warpM = wid & 1;
    const int warpN = wid >> 1;
    const int row0  = blockIdx.y * 128;
    const int col0  = blockIdx.x * 128;
    const int lq    = lane >> 2;
    const int lr    = lane & 3;

    const int a_row  = warpM * 64 + (lane & 15);
    const int a_half = (lane >> 4) & 1;
    const int b_row  = warpN * 32 + (lane & 7);
    const int b_half = (lane >> 3) & 1;

    float acc[4][4][4];
#pragma unroll
    for (int a = 0; a < 4; a++)
#pragma unroll
        for (int b = 0; b < 4; b++)
#pragma unroll
            for (int c = 0; c < 4; c++) acc[a][b][c] = 0.0f;

#define CPA_CHUNK(kt, stg)                                                   \
    {                                                                        \
        uint32_t sb = smb + (stg) * (HG_STG * 4);                            \
        _Pragma("unroll")                                                    \
        for (int i = 0; i < 2; i++) {                                        \
            int e = tid + i * 256;                                           \
            int m = e >> 2, seg = e & 3;                                     \
            uint32_t idx = (uint32_t)(((((seg >> 1) * 128 + m) * 12) + (seg & 1) * 4) * 4); \
            size_t ga = (size_t)(row0 + m) * 128 + (size_t)(kt) * 4 + seg;   \
            size_t gb = (size_t)(col0 + m) * 128 + (size_t)(kt) * 4 + seg;   \
            cpa16(sb + idx,                Ah + ga);                         \
            cpa16(sb + HG_ARR * 4 + idx,   Al + ga);                         \
            cpa16(sb + HG_ARR * 8 + idx,   Bh + gb);                         \
            cpa16(sb + HG_ARR * 12 + idx,  Bl + gb);                         \
        }                                                                    \
        cpc();                                                               \
    }

    CPA_CHUNK(0, 0);
    CPA_CHUNK(1, 1);

#pragma unroll 1
    for (int kt = 0; kt < 32; kt++) {
        const int s = kt & 1;
        if (kt + 1 < 32) cpw<1>(); else cpw<0>();
        __syncthreads();

        const uint32_t sbase = smb + s * (HG_STG * 4);
#pragma unroll
        for (int ks = 0; ks < 2; ks++) {
            uint32_t ahf[4][4], alf[4][4];
#pragma unroll
            for (int mt = 0; mt < 4; mt++) {
                uint32_t aaddr = sbase +
                    (uint32_t)(((ks * 128 + a_row + mt * 16) * 12 + a_half * 4) * 4);
                ldsm4(ahf[mt], aaddr);
                ldsm4(alf[mt], aaddr + HG_ARR * 4);
            }
            uint32_t bhf[4][2], blf[4][2];
#pragma unroll
            for (int nt = 0; nt < 4; nt++) {
                uint32_t baddr = sbase + HG_ARR * 8 +
                    (uint32_t)(((ks * 128 + b_row + nt * 8) * 12 + b_half * 4) * 4);
                ldsm2(bhf[nt][0], bhf[nt][1], baddr);
                ldsm2(blf[nt][0], blf[nt][1], baddr + HG_ARR * 4);
            }
#pragma unroll
            for (int mt = 0; mt < 4; mt++)
#pragma unroll
                for (int nt = 0; nt < 4; nt++) {
                    mma_bf16(acc[mt][nt], ahf[mt][0], ahf[mt][1], ahf[mt][2], ahf[mt][3],
                             bhf[nt][0], bhf[nt][1]);
                    mma_bf16(acc[mt][nt], ahf[mt][0], ahf[mt][1], ahf[mt][2], ahf[mt][3],
                             blf[nt][0], blf[nt][1]);
                    mma_bf16(acc[mt][nt], alf[mt][0], alf[mt][1], alf[mt][2], alf[mt][3],
                             bhf[nt][0], bhf[nt][1]);
                }
        }
        __syncthreads();
        if (kt + 2 < 32) CPA_CHUNK(kt + 2, s);
    }
#undef CPA_CHUNK

#pragma unroll
    for (int mt = 0; mt < 4; mt++) {
        int mb = row0 + warpM * 64 + mt * 16 + lq;
#pragma unroll
        for (int nt = 0; nt < 4; nt++) {
            int n0 = col0 + warpN * 32 + nt * 8 + lr * 2;
            float bi0 = __ldg(bias + n0), bi1 = __ldg(bias + n0 + 1);
#pragma unroll
            for (int rh = 0; rh < 2; rh++) {
                int m = mb + rh * 8;
                float v0 = acc[mt][nt][rh * 2 + 0] + bi0;
                float v1 = acc[mt][nt][rh * 2 + 1] + bi1;
                if (MODE == 1) {
                    *(float2*)(C + (size_t)m * 1024 + n0) = make_float2(v0, v1);
                } else {
                    int b = m >> 11;
                    int s = m & 2047;
                    if (n0 < D_MODEL) {
                        *(float2*)(g_q + (size_t)m * 1024 + n0) = make_float2(v0, v1);
                        float q0 = v0 * 0.125f, q1 = v1 * 0.125f;
                        uint32_t hh = bf2(q0, q1);
                        uint32_t ll = bf2(q0 - bf_lo_f(hh), q1 - bf_hi_f(hh));
                        size_t qo = ((size_t)(b * 16 + (n0 >> 6)) * SEQ + s) * 64 + (n0 & 63);
                        *(uint32_t*)(g_qh + qo) = hh;
                        *(uint32_t*)(g_ql + qo) = ll;
                    } else {
                        int cc = n0 - D_MODEL;
                        int which = cc >> 10;
                        cc &= 1023;
                        int hd = cc >> 6, d = cc & 63;
                        size_t so = ((size_t)(b * 16 + hd) * SEQ + s) * 64 + d;
                        *(float2*)(C + (size_t)which * KV_ELEMS + so) = make_float2(v0, v1);
                        uint32_t hp = bf2(v0, v1);
                        uint32_t lp = bf2(v0 - bf_lo_f(hp), v1 - bf_hi_f(hp));
                        if (which == 0) {
                            *(uint32_t*)(g_kh + so) = hp;
                            *(uint32_t*)(g_kl + so) = lp;
                        } else {
                            size_t vo = ((size_t)(b * 16 + hd) * 64 + d) * SEQ + s;
                            __nv_bfloat16 h0 = __float2bfloat16(v0);
                            __nv_bfloat16 h1 = __float2bfloat16(v1);
                            g_vth[vo] = h0;
                            g_vtl[vo] = __float2bfloat16(v0 - __bfloat162float(h0));
                            g_vth[vo + SEQ] = h1;
                            g_vtl[vo + SEQ] = __float2bfloat16(v1 - __bfloat162float(h1));
                        }
                    }
                }
            }
        }
    }
}

// ---------------------------------------------------------------------------
// Flash attention, split-K over key-blocks of 8 chunks (512 keys).
// 40 uniform tiles per bh (table c_tiles), each writes RAW partials
// (O, lsum) to a private slot — static softmax base makes partials additive.
// ---------------------------------------------------------------------------
#define AT_ARR 3072
#define AT_STG (4 * AT_ARR)
#define AT_SMEM (2 * AT_STG * 4)

__global__ __launch_bounds__(256, 2)
void attn_mma()
{
    extern __shared__ uint32_t sm[];
    const uint32_t smb = smem_u32(sm);

    const int tid = threadIdx.x;
    const int wid = tid >> 5;
    const int lane = tid & 31;
    const int lq = lane >> 2;
    const int lr = lane & 3;
    const int code = c_tiles[blockIdx.x];
    const int qt = code >> 2;
    const int kb = code & 3;
    const int bh = blockIdx.y;
    const float MX = 20.0f;

    const int c0   = kb * 8;
    const int cnt0 = 2 * qt + 2 - c0;
    const int cnt  = cnt0 < 8 ? cnt0 : 8;
    const int cend = c0 + cnt;

    const int kv_row  = lane & 7;
    const int kv_half = (lane >> 3) & 1;

    const uint4* Qh4 = (const uint4*)g_qh;
    const uint4* Ql4 = (const uint4*)g_ql;
    const uint4* Kh4 = (const uint4*)g_kh;
    const uint4* Kl4 = (const uint4*)g_kl;
    const uint4* Vh4 = (const uint4*)g_vth;
    const uint4* Vl4 = (const uint4*)g_vtl;

    // ---- stage Q tile through stage-0 SMEM -> registers, then release ----
    uint32_t qh[4][4], ql[4][4];
    {
        const size_t q0 = ((size_t)bh * SEQ + qt * 128) * 8;
#pragma unroll
        for (int i = 0; i < 4; i++) {
            int e = tid + i * 256;
            int m = e >> 3, seg = e & 7;
            uint4 vh = Qh4[q0 + m * 8 + seg];
            uint4 vl = Ql4[q0 + m * 8 + seg];
            int idx = ((seg >> 1) * 128 + m) * 12 + (seg & 1) * 4;
            sm[idx] = vh.x; sm[idx+1] = vh.y; sm[idx+2] = vh.z; sm[idx+3] = vh.w;
            sm[6144 + idx] = vl.x; sm[6144 + idx+1] = vl.y;
            sm[6144 + idx+2] = vl.z; sm[6144 + idx+3] = vl.w;
        }
        __syncthreads();
#pragma unroll
        for (int ks = 0; ks < 4; ks++) {
            int aidx = (ks * 128 + wid * 16 + lq) * 12 + lr;
            qh[ks][0] = sm[aidx];       qh[ks][1] = sm[aidx + 96];
            qh[ks][2] = sm[aidx + 4];   qh[ks][3] = sm[aidx + 100];
            ql[ks][0] = sm[6144 + aidx];     ql[ks][1] = sm[6144 + aidx + 96];
            ql[ks][2] = sm[6144 + aidx + 4]; ql[ks][3] = sm[6144 + aidx + 100];
        }
        __syncthreads();
    }

#define CPAKV(c, stg)                                                        \
    {                                                                        \
        uint32_t sb = smb + (stg) * (AT_STG * 4);                            \
        int kt0_ = (c) * 64;                                                 \
        _Pragma("unroll")                                                    \
        for (int i = 0; i < 2; i++) {                                        \
            int e = tid + i * 256;                                           \
            int m = e >> 3, seg = e & 7;                                     \
            uint32_t idx = (uint32_t)(((((seg >> 1) * 64 + m) * 12) + (seg & 1) * 4) * 4); \
            size_t ki = ((size_t)bh * SEQ + kt0_ + m) * 8 + seg;             \
            size_t vi = ((size_t)bh * 64 + m) * 256 + (kt0_ >> 3) + seg;     \
            cpa16(sb + idx,               Kh4 + ki);                         \
            cpa16(sb + AT_ARR * 4 + idx,  Kl4 + ki);                         \
            cpa16(sb + AT_ARR * 8 + idx,  Vh4 + vi);                         \
            cpa16(sb + AT_ARR * 12 + idx, Vl4 + vi);                         \
        }                                                                    \
        cpc();                                                               \
    }

    const int gr0 = qt * 128 + wid * 16;

    CPAKV(c0, 0);
    CPAKV(c0 + 1, 1);

    float O[8][4];
#pragma unroll
    for (int nb = 0; nb < 8; nb++)
#pragma unroll
        for (int q = 0; q < 4; q++) O[nb][q] = 0.0f;
    float lsum0 = 0.0f, lsum1 = 0.0f;

#pragma unroll 1
    for (int c = c0; c < cend; c++) {
        const int s = (c - c0) & 1;
        if (c + 1 < cend) cpw<1>(); else cpw<0>();
        __syncthreads();

        const int kt0 = c * 64;
        if (kt0 <= gr0 + 15) {
            const uint32_t kstage = smb + s * (AT_STG * 4);

            float S[8][4];
#pragma unroll
            for (int nb = 0; nb < 8; nb++)
#pragma unroll
                for (int q = 0; q < 4; q++) S[nb][q] = 0.0f;
#pragma unroll
            for (int ks = 0; ks < 4; ks++) {
#pragma unroll
                for (int nb = 0; nb < 8; nb++) {
                    uint32_t kaddr = kstage +
                        (uint32_t)(((ks * 64 + nb * 8 + kv_row) * 12 + kv_half * 4) * 4);
                    uint32_t bh0, bh1, bl0, bl1;
                    ldsm2(bh0, bh1, kaddr);
                    ldsm2(bl0, bl1, kaddr + AT_ARR * 4);
                    mma_bf16(S[nb], qh[ks][0], qh[ks][1], qh[ks][2], qh[ks][3], bh0, bh1);
                    mma_bf16(S[nb], qh[ks][0], qh[ks][1], qh[ks][2], qh[ks][3], bl0, bl1);
                    mma_bf16(S[nb], ql[ks][0], ql[ks][1], ql[ks][2], ql[ks][3], bh0, bh1);
                }
            }
            const int r0 = gr0 + lq, r1 = r0 + 8;
            float p[8][4];
#pragma unroll
            for (int nb = 0; nb < 8; nb++) {
                int cc0 = kt0 + nb * 8 + 2 * lr;
                p[nb][0] = (cc0     <= r0) ? __expf(S[nb][0] - MX) : 0.0f;
                p[nb][1] = (cc0 + 1 <= r0) ? __expf(S[nb][1] - MX) : 0.0f;
                p[nb][2] = (cc0     <= r1) ? __expf(S[nb][2] - MX) : 0.0f;
                p[nb][3] = (cc0 + 1 <= r1) ? __expf(S[nb][3] - MX) : 0.0f;
                lsum0 += p[nb][0] + p[nb][1];
                lsum1 += p[nb][2] + p[nb][3];
            }
#pragma unroll
            for (int ks = 0; ks < 4; ks++) {
                uint32_t ph0 = bf2(p[2*ks][0],   p[2*ks][1]);
                uint32_t ph1 = bf2(p[2*ks][2],   p[2*ks][3]);
                uint32_t ph2 = bf2(p[2*ks+1][0], p[2*ks+1][1]);
                uint32_t ph3 = bf2(p[2*ks+1][2], p[2*ks+1][3]);
                uint32_t pl0 = bf2(p[2*ks][0] - bf_lo_f(ph0),   p[2*ks][1] - bf_hi_f(ph0));
                uint32_t pl1 = bf2(p[2*ks][2] - bf_lo_f(ph1),   p[2*ks][3] - bf_hi_f(ph1));
                uint32_t pl2 = bf2(p[2*ks+1][0] - bf_lo_f(ph2), p[2*ks+1][1] - bf_hi_f(ph2));
                uint32_t pl3 = bf2(p[2*ks+1][2] - bf_lo_f(ph3), p[2*ks+1][3] - bf_hi_f(ph3));
#pragma unroll
                for (int nb = 0; nb < 8; nb++) {
                    uint32_t vaddr = kstage + AT_ARR * 8 +
                        (uint32_t)(((ks * 64 + nb * 8 + kv_row) * 12 + kv_half * 4) * 4);
                    uint32_t vh0, vh1, vl0, vl1;
                    ldsm2(vh0, vh1, vaddr);
                    ldsm2(vl0, vl1, vaddr + AT_ARR * 4);
                    mma_bf16(O[nb], ph0, ph1, ph2, ph3, vh0, vh1);
                    mma_bf16(O[nb], pl0, pl1, pl2, pl3, vh0, vh1);
                    mma_bf16(O[nb], ph0, ph1, ph2, ph3, vl0, vl1);
                }
            }
        }
        __syncthreads();
        if (c + 2 < cend) CPAKV(c + 2, s);
    }
#undef CPAKV

    // ---- epilogue: write RAW partials to this tile's slot ----
    lsum0 += __shfl_xor_sync(0xFFFFFFFFu, lsum0, 1);
    lsum0 += __shfl_xor_sync(0xFFFFFFFFu, lsum0, 2);
    lsum1 += __shfl_xor_sync(0xFFFFFFFFu, lsum1, 1);
    lsum1 += __shfl_xor_sync(0xFFFFFFFFu, lsum1, 2);

    const int rl0 = wid * 16 + lq, rl1 = rl0 + 8;
    const int slot = (bh * 16 + qt) * 4 + kb;
    float* pb = g_part + (size_t)slot * (128 * 64);
#pragma unroll
    for (int nb = 0; nb < 8; nb++) {
        int col = nb * 8 + 2 * lr;
        *(float2*)(pb + rl0 * 64 + col) = make_float2(O[nb][0], O[nb][1]);
        *(float2*)(pb + rl1 * 64 + col) = make_float2(O[nb][2], O[nb][3]);
    }
    if (lr == 0) {
        g_psum[(size_t)slot * 128 + rl0] = lsum0;
        g_psum[(size_t)slot * 128 + rl1] = lsum1;
    }
}

// ---------------------------------------------------------------------------
// Merge: ctx = (Σ token partials + memattn macc) / (Σ psum + msum),
// emitted as bf16 hi/lo into g_a_hi/g_a_lo for hgemm<1>.
// grid (16 qt, 32 bh), 256 threads: tid>>1 = row, (tid&1)*32 = col half.
// ---------------------------------------------------------------------------
__global__ __launch_bounds__(256)
void merge_kernel()
{
    const int tid = threadIdx.x;
    const int qt  = blockIdx.x;
    const int bh  = blockIdx.y;
    const int b = bh >> 4, h = bh & 15;
    const int r   = tid >> 1;
    const int ch  = (tid & 1) * 32;
    const int nkb = (qt + 4) >> 2;           // ceil((qt+1)/4)
    const int row = qt * 128 + r;
    const int slot0 = (bh * 16 + qt) * 4;

    float den = g_msum[(size_t)bh * SEQ + row];
#pragma unroll 4
    for (int kb = 0; kb < nkb; kb++)
        den += g_psum[(size_t)(slot0 + kb) * 128 + r];
    const float inv = 1.0f / den;

    const size_t cbase = ((size_t)(b * SEQ + row)) * D_MODEL + h * HEAD_DIM + ch;
#pragma unroll
    for (int j = 0; j < 8; j++) {
        float4 m = *(const float4*)(g_ctx + cbase + j * 4);
#pragma unroll 4
        for (int kb = 0; kb < nkb; kb++) {
            const float* pb = g_part + (size_t)(slot0 + kb) * (128 * 64) + r * 64 + ch + j * 4;
            float4 p = *(const float4*)pb;
            m.x += p.x; m.y += p.y; m.z += p.z; m.w += p.w;
        }
        float o0 = m.x * inv, o1 = m.y * inv, o2 = m.z * inv, o3 = m.w * inv;
        uint32_t h01 = bf2(o0, o1), h23 = bf2(o2, o3);
        uint32_t l01 = bf2(o0 - bf_lo_f(h01), o1 - bf_hi_f(h01));
        uint32_t l23 = bf2(o2 - bf_lo_f(h23), o3 - bf_hi_f(h23));
        *(uint2*)(g_a_hi + cbase + j * 4) = make_uint2(h01, h23);
        *(uint2*)(g_a_lo + cbase + j * 4) = make_uint2(l01, l23);
    }
}

// ---------------------------------------------------------------------------
extern "C" void kernel_launch(void* const* d_in, const int* in_sizes, int n_in,
                              void* d_out, int out_size)
{
    const float* x = 0; const float* pk = 0; const float* pv = 0;
    const float* W_qkv = 0; const float* b_qkv = 0;
    const float* W_out = 0; const float* b_out = 0;
    for (int i = 0; i < n_in; i++) {
        const float* p = (const float*)d_in[i];
        switch (in_sizes[i]) {
            case 4194304:  x = p;      break;
            case 33554432: if (!pk) pk = p; else pv = p; break;
            case 3145728:  W_qkv = p;  break;
            case 3072:     b_qkv = p;  break;
            case 1048576:  W_out = p;  break;
            case 1024:     b_out = p;  break;
            default: break;
        }
    }
    if (!(x && pk && pv && W_qkv && b_qkv && W_out && b_out)) {
        if (n_in < 7) return;
        x     = (const float*)d_in[0];
        pk    = (const float*)d_in[1];
        pv    = (const float*)d_in[2];
        W_qkv = (const float*)d_in[3];
        b_qkv = (const float*)d_in[4];
        W_out = (const float*)d_in[5];
        b_out = (const float*)d_in[6];
    }

    float* out = (float*)d_out;

    static __nv_bfloat16 *s_ah = nullptr, *s_al = nullptr, *s_bh = nullptr, *s_bl = nullptr;
    if (!s_ah) {
        void* p = 0;
        cudaGetSymbolAddress(&p, g_a_hi);  s_ah = (__nv_bfloat16*)p;
        cudaGetSymbolAddress(&p, g_a_lo);  s_al = (__nv_bfloat16*)p;
        cudaGetSymbolAddress(&p, g_bt_hi); s_bh = (__nv_bfloat16*)p;
        cudaGetSymbolAddress(&p, g_bt_lo); s_bl = (__nv_bfloat16*)p;
        cudaFuncSetAttribute((const void*)hgemm_bf<0>,
                             cudaFuncAttributeMaxDynamicSharedMemorySize, HB_SMEM);
        cudaFuncSetAttribute((const void*)hgemm_bf<1>,
                             cudaFuncAttributeMaxDynamicSharedMemorySize, HB_SMEM);
        cudaFuncSetAttribute((const void*)attn_mma,
                             cudaFuncAttributeMaxDynamicSharedMemorySize, AT_SMEM);
    }

    float* kvbuf = out + OUT_ELEMS;   // [out | k | v] element layout

    // prep: split x; split+transpose W_qkv
    split_a_kernel<<<OUT_ELEMS / 1024, 256>>>((const float4*)x, (uint2*)s_ah, (uint2*)s_al);
    {
        dim3 grid(3 * D_MODEL / 32, D_MODEL / 32);
        split_wt_kernel<<<grid, dim3(32, 8)>>>(W_qkv, s_bh, s_bl, 3 * D_MODEL);
    }
    // 1) QKV GEMM (emits q/k/v + pre-split attention operands)
    {
        dim3 grid(3 * D_MODEL / 128, M_TOT / 128);
        hgemm_bf<0><<<grid, 256, HB_SMEM>>>((const uint4*)s_ah, (const uint4*)s_al,
                                            (const uint4*)s_bh, (const uint4*)s_bl,
                                            b_qkv, kvbuf);
    }
    // 2a) memory attention partials
    {
        dim3 grid(SEQ / 8, BATCH * N_HEADS);
        memattn_kernel<<<grid, 256>>>(pk, pv);
    }
    // 2b) token flash attention, split-K uniform tiles (raw partials)
    {
        dim3 grid(40, BATCH * N_HEADS);
        attn_mma<<<grid, 256, AT_SMEM>>>();
    }
    // 2c) merge partials -> ctx bf16 hi/lo
    {
        dim3 grid(16, BATCH * N_HEADS);
        merge_kernel<<<grid, 256>>>();
    }
    // prep: split+transpose W_out
    {
        dim3 grid(D_MODEL / 32, D_MODEL / 32);
        split_wt_kernel<<<grid, dim3(32, 8)>>>(W_out, s_bh, s_bl, D_MODEL);
    }
    // 3) output GEMM
    {
        dim3 grid(D_MODEL / 128, M_TOT / 128);
        hgemm_bf<1><<<grid, 256, HB_SMEM>>>((const uint4*)s_ah, (const uint4*)s_al,
                                            (const uint4*)s_bh, (const uint4*)s_bl,
                                            b_out, out);
    }
}

// round 17
// speedup vs baseline: 2.8362x; 1.0042x over previous
#include <cuda_runtime.h>
#include <cuda_bf16.h>
#include <cstdint>

#define D_MODEL  1024
#define N_HEADS  16
#define HEAD_DIM 64
#define BATCH    2
#define SEQ      2048
#define LMEM     8
#define M_TOT    (BATCH * SEQ)            // 4096
#define OUT_ELEMS (M_TOT * D_MODEL)       // 4194304
#define KV_ELEMS  (BATCH * N_HEADS * SEQ * HEAD_DIM)  // 4194304 each

typedef unsigned long long ull;

// scratch (no cudaMalloc). NEVER pass these directly as host-side kernel args
// (host stub address + GB300 ATS = silent host reads) — use cudaGetSymbolAddress
// or reference in device code.
__device__ float g_q[M_TOT * D_MODEL];
__device__ float g_ctx[M_TOT * D_MODEL];           // memattn macc
__device__ float g_msum[BATCH * N_HEADS * SEQ];    // memattn partial sums
__device__ float g_part[32 * 16 * 4 * 128 * 64];   // attn split-K O partials (64MB)
__device__ float g_psum[32 * 16 * 4 * 128];        // attn split-K lsum partials
__device__ __nv_bfloat16 g_a_hi[M_TOT * D_MODEL];  // GEMM A split (x, then ctx)
__device__ __nv_bfloat16 g_a_lo[M_TOT * D_MODEL];
__device__ __nv_bfloat16 g_bt_hi[3 * D_MODEL * D_MODEL];
__device__ __nv_bfloat16 g_bt_lo[3 * D_MODEL * D_MODEL];
__device__ __nv_bfloat16 g_bo_hi[D_MODEL * D_MODEL];   // W_out^T split (own buffer
__device__ __nv_bfloat16 g_bo_lo[D_MODEL * D_MODEL];   // so prep can overlap)
__device__ __nv_bfloat16 g_qh[M_TOT * D_MODEL];    // q*0.125 hi/lo, [bh][s][d]
__device__ __nv_bfloat16 g_ql[M_TOT * D_MODEL];
__device__ __nv_bfloat16 g_kh[KV_ELEMS];           // [bh][s][d]
__device__ __nv_bfloat16 g_kl[KV_ELEMS];
__device__ __nv_bfloat16 g_vth[KV_ELEMS];          // [bh][d][s]
__device__ __nv_bfloat16 g_vtl[KV_ELEMS];

// attn tile table: code = qt*4 + kb, heavy tiles (8 chunks) first.
__constant__ unsigned char c_tiles[40] = {
    60,61,62,63, 56,57,58, 52,53,54, 48,49,50, 44,45,46,
    40,41, 36,37, 32,33, 28,29, 24, 20, 16, 12,
    59,42,25,8,  55,38,21,4,  51,34,17,0
};

// ---- bf16 helpers ------------------------------------------------------------
__device__ __forceinline__ uint32_t bf2(float lo, float hi) {   // low16=lo, high16=hi
    uint32_t r;
    asm("cvt.rn.bf16x2.f32 %0, %1, %2;" : "=r"(r) : "f"(hi), "f"(lo));
    return r;
}
__device__ __forceinline__ float bf_lo_f(uint32_t h) { return __uint_as_float(h << 16); }
__device__ __forceinline__ float bf_hi_f(uint32_t h) { return __uint_as_float(h & 0xFFFF0000u); }

__device__ __forceinline__ void mma_bf16(float* c,
                                         uint32_t a0, uint32_t a1, uint32_t a2, uint32_t a3,
                                         uint32_t b0, uint32_t b1) {
    asm volatile(
        "mma.sync.aligned.m16n8k16.row.col.f32.bf16.bf16.f32 "
        "{%0,%1,%2,%3}, {%4,%5,%6,%7}, {%8,%9}, {%0,%1,%2,%3};"
        : "+f"(c[0]), "+f"(c[1]), "+f"(c[2]), "+f"(c[3])
        : "r"(a0), "r"(a1), "r"(a2), "r"(a3), "r"(b0), "r"(b1));
}

// ---- ldmatrix (LDSM) ----------------------------------------------------------
__device__ __forceinline__ void ldsm4(uint32_t* r, uint32_t addr) {
    asm volatile("ldmatrix.sync.aligned.m8n8.x4.shared.b16 {%0,%1,%2,%3}, [%4];"
        : "=r"(r[0]), "=r"(r[1]), "=r"(r[2]), "=r"(r[3]) : "r"(addr));
}
__device__ __forceinline__ void ldsm2(uint32_t& r0, uint32_t& r1, uint32_t addr) {
    asm volatile("ldmatrix.sync.aligned.m8n8.x2.shared.b16 {%0,%1}, [%2];"
        : "=r"(r0), "=r"(r1) : "r"(addr));
}

// ---- cp.async -----------------------------------------------------------------
__device__ __forceinline__ uint32_t smem_u32(const void* p) {
    uint32_t a;
    asm("{ .reg .u64 t; cvta.to.shared.u64 t, %1; cvt.u32.u64 %0, t; }"
        : "=r"(a) : "l"(p));
    return a;
}
__device__ __forceinline__ void cpa16(uint32_t smaddr, const void* gptr) {
    asm volatile("cp.async.cg.shared.global [%0], [%1], 16;"
                 :: "r"(smaddr), "l"(__cvta_generic_to_global(gptr)));
}
__device__ __forceinline__ void cpc() {
    asm volatile("cp.async.commit_group;");
}
template <int N>
__device__ __forceinline__ void cpw() {
    asm volatile("cp.async.wait_group %0;" :: "n"(N));
}

// ---------------------------------------------------------------------------
// Prep kernels (proven)
// ---------------------------------------------------------------------------
__global__ __launch_bounds__(256)
void split_a_kernel(const float4* __restrict__ src,
                    uint2* __restrict__ hi, uint2* __restrict__ lo)
{
    int i = blockIdx.x * 256 + threadIdx.x;
    float4 v = src[i];
    uint32_t h01 = bf2(v.x, v.y), h23 = bf2(v.z, v.w);
    uint32_t l01 = bf2(v.x - bf_lo_f(h01), v.y - bf_hi_f(h01));
    uint32_t l23 = bf2(v.z - bf_lo_f(h23), v.w - bf_hi_f(h23));
    hi[i] = make_uint2(h01, h23);
    lo[i] = make_uint2(l01, l23);
}

__global__ __launch_bounds__(256)
void split_wt_kernel(const float* __restrict__ W,
                     __nv_bfloat16* __restrict__ hiT,
                     __nv_bfloat16* __restrict__ loT,
                     int N)
{
    __shared__ float t[32][33];
    const int tx = threadIdx.x, ty = threadIdx.y;
    const int n0 = blockIdx.x * 32, k0 = blockIdx.y * 32;
#pragma unroll
    for (int i = 0; i < 4; i++)
        t[ty + 8 * i][tx] = W[(size_t)(k0 + ty + 8 * i) * N + n0 + tx];
    __syncthreads();
#pragma unroll
    for (int i = 0; i < 4; i++) {
        int n = n0 + ty + 8 * i;
        float f = t[tx][ty + 8 * i];
        __nv_bfloat16 h = __float2bfloat16(f);
        __nv_bfloat16 l = __float2bfloat16(f - __bfloat162float(h));
        hiT[(size_t)n * 1024 + k0 + tx] = h;
        loT[(size_t)n * 1024 + k0 + tx] = l;
    }
}

// ---------------------------------------------------------------------------
// Memory attention — warp-per-query, coalesced (proven round 14).
// ---------------------------------------------------------------------------
__global__ __launch_bounds__(256)
void memattn_kernel(const float* __restrict__ pk, const float* __restrict__ pv)
{
    const int tid  = threadIdx.x;
    const int wid  = tid >> 5;
    const int lane = tid & 31;
    const int half = lane >> 4;
    const int d4   = (lane & 15) * 4;
    const int bh   = blockIdx.y;
    const int b    = bh >> 4, h = bh & 15;
    const int qrow = blockIdx.x * 8 + wid;
    const float MX = 20.0f;

    float4 q4;
    {
        const float* qp = g_q + ((size_t)(b * SEQ + qrow) * D_MODEL + h * HEAD_DIM + d4);
        q4 = *(const float4*)qp;
        q4.x *= 0.125f; q4.y *= 0.125f; q4.z *= 0.125f; q4.w *= 0.125f;
    }

    const size_t blk = ((size_t)bh * SEQ + qrow) * (LMEM * HEAD_DIM);
    const float* kp = pk + blk;
    const float* vp = pv + blk;

    float4 acc = make_float4(0.f, 0.f, 0.f, 0.f);
    float lsum = 0.0f;

#pragma unroll
    for (int p = 0; p < 4; p++) {
        const int key = 2 * p + half;
        float4 k4 = *(const float4*)(kp + key * HEAD_DIM + d4);
        float d = q4.x * k4.x + q4.y * k4.y + q4.z * k4.z + q4.w * k4.w;
        d += __shfl_xor_sync(0xFFFFFFFFu, d, 1);
        d += __shfl_xor_sync(0xFFFFFFFFu, d, 2);
        d += __shfl_xor_sync(0xFFFFFFFFu, d, 4);
        d += __shfl_xor_sync(0xFFFFFFFFu, d, 8);
        float pe = __expf(d - MX);
        lsum += pe;
        float4 v4 = *(const float4*)(vp + key * HEAD_DIM + d4);
        acc.x += pe * v4.x;
        acc.y += pe * v4.y;
        acc.z += pe * v4.z;
        acc.w += pe * v4.w;
    }
    acc.x += __shfl_xor_sync(0xFFFFFFFFu, acc.x, 16);
    acc.y += __shfl_xor_sync(0xFFFFFFFFu, acc.y, 16);
    acc.z += __shfl_xor_sync(0xFFFFFFFFu, acc.z, 16);
    acc.w += __shfl_xor_sync(0xFFFFFFFFu, acc.w, 16);
    lsum  += __shfl_xor_sync(0xFFFFFFFFu, lsum, 16);

    if (lane < 16)
        *(float4*)(g_ctx + ((size_t)(b * SEQ + qrow)) * D_MODEL + h * HEAD_DIM + d4) = acc;
    if (lane == 0)
        g_msum[(size_t)bh * SEQ + qrow] = lsum;
}

// ---------------------------------------------------------------------------
// bf16 mma.sync GEMM, hi/lo 3-term (proven round 15).
// ---------------------------------------------------------------------------
#define HG_ARR 3072
#define HG_STG (4 * HG_ARR)
#define HB_SMEM (2 * HG_STG * 4)

template <int MODE>
__global__ __launch_bounds__(256, 2)
void hgemm_bf(const uint4* __restrict__ Ah, const uint4* __restrict__ Al,
              const uint4* __restrict__ Bh, const uint4* __restrict__ Bl,
              const float* __restrict__ bias,
              float* __restrict__ C)
{
    extern __shared__ uint32_t sm[];
    const uint32_t smb = smem_u32(sm);

    const int tid   = threadIdx.x;
    const int wid   = tid >> 5;
    const int lane  = tid & 31;
    const int warpM = wid & 1;
    const int warpN = wid >> 1;
    const int row0  = blockIdx.y * 128;
    const int col0  = blockIdx.x * 128;
    const int lq    = lane >> 2;
    const int lr    = lane & 3;

    const int a_row  = warpM * 64 + (lane & 15);
    const int a_half = (lane >> 4) & 1;
    const int b_row  = warpN * 32 + (lane & 7);
    const int b_half = (lane >> 3) & 1;

    float acc[4][4][4];
#pragma unroll
    for (int a = 0; a < 4; a++)
#pragma unroll
        for (int b = 0; b < 4; b++)
#pragma unroll
            for (int c = 0; c < 4; c++) acc[a][b][c] = 0.0f;

#define CPA_CHUNK(kt, stg)                                                   \
    {                                                                        \
        uint32_t sb = smb + (stg) * (HG_STG * 4);                            \
        _Pragma("unroll")                                                    \
        for (int i = 0; i < 2; i++) {                                        \
            int e = tid + i * 256;                                           \
            int m = e >> 2, seg = e & 3;                                     \
            uint32_t idx = (uint32_t)(((((seg >> 1) * 128 + m) * 12) + (seg & 1) * 4) * 4); \
            size_t ga = (size_t)(row0 + m) * 128 + (size_t)(kt) * 4 + seg;   \
            size_t gb = (size_t)(col0 + m) * 128 + (size_t)(kt) * 4 + seg;   \
            cpa16(sb + idx,                Ah + ga);                         \
            cpa16(sb + HG_ARR * 4 + idx,   Al + ga);                         \
            cpa16(sb + HG_ARR * 8 + idx,   Bh + gb);                         \
            cpa16(sb + HG_ARR * 12 + idx,  Bl + gb);                         \
        }                                                                    \
        cpc();                                                               \
    }

    CPA_CHUNK(0, 0);
    CPA_CHUNK(1, 1);

#pragma unroll 1
    for (int kt = 0; kt < 32; kt++) {
        const int s = kt & 1;
        if (kt + 1 < 32) cpw<1>(); else cpw<0>();
        __syncthreads();

        const uint32_t sbase = smb + s * (HG_STG * 4);
#pragma unroll
        for (int ks = 0; ks < 2; ks++) {
            uint32_t ahf[4][4], alf[4][4];
#pragma unroll
            for (int mt = 0; mt < 4; mt++) {
                uint32_t aaddr = sbase +
                    (uint32_t)(((ks * 128 + a_row + mt * 16) * 12 + a_half * 4) * 4);
                ldsm4(ahf[mt], aaddr);
                ldsm4(alf[mt], aaddr + HG_ARR * 4);
            }
            uint32_t bhf[4][2], blf[4][2];
#pragma unroll
            for (int nt = 0; nt < 4; nt++) {
                uint32_t baddr = sbase + HG_ARR * 8 +
                    (uint32_t)(((ks * 128 + b_row + nt * 8) * 12 + b_half * 4) * 4);
                ldsm2(bhf[nt][0], bhf[nt][1], baddr);
                ldsm2(blf[nt][0], blf[nt][1], baddr + HG_ARR * 4);
            }
#pragma unroll
            for (int mt = 0; mt < 4; mt++)
#pragma unroll
                for (int nt = 0; nt < 4; nt++) {
                    mma_bf16(acc[mt][nt], ahf[mt][0], ahf[mt][1], ahf[mt][2], ahf[mt][3],
                             bhf[nt][0], bhf[nt][1]);
                    mma_bf16(acc[mt][nt], ahf[mt][0], ahf[mt][1], ahf[mt][2], ahf[mt][3],
                             blf[nt][0], blf[nt][1]);
                    mma_bf16(acc[mt][nt], alf[mt][0], alf[mt][1], alf[mt][2], alf[mt][3],
                             bhf[nt][0], bhf[nt][1]);
                }
        }
        __syncthreads();
        if (kt + 2 < 32) CPA_CHUNK(kt + 2, s);
    }
#undef CPA_CHUNK

#pragma unroll
    for (int mt = 0; mt < 4; mt++) {
        int mb = row0 + warpM * 64 + mt * 16 + lq;
#pragma unroll
        for (int nt = 0; nt < 4; nt++) {
            int n0 = col0 + warpN * 32 + nt * 8 + lr * 2;
            float bi0 = __ldg(bias + n0), bi1 = __ldg(bias + n0 + 1);
#pragma unroll
            for (int rh = 0; rh < 2; rh++) {
                int m = mb + rh * 8;
                float v0 = acc[mt][nt][rh * 2 + 0] + bi0;
                float v1 = acc[mt][nt][rh * 2 + 1] + bi1;
                if (MODE == 1) {
                    *(float2*)(C + (size_t)m * 1024 + n0) = make_float2(v0, v1);
                } else {
                    int b = m >> 11;
                    int s = m & 2047;
                    if (n0 < D_MODEL) {
                        *(float2*)(g_q + (size_t)m * 1024 + n0) = make_float2(v0, v1);
                        float q0 = v0 * 0.125f, q1 = v1 * 0.125f;
                        uint32_t hh = bf2(q0, q1);
                        uint32_t ll = bf2(q0 - bf_lo_f(hh), q1 - bf_hi_f(hh));
                        size_t qo = ((size_t)(b * 16 + (n0 >> 6)) * SEQ + s) * 64 + (n0 & 63);
                        *(uint32_t*)(g_qh + qo) = hh;
                        *(uint32_t*)(g_ql + qo) = ll;
                    } else {
                        int cc = n0 - D_MODEL;
                        int which = cc >> 10;
                        cc &= 1023;
                        int hd = cc >> 6, d = cc & 63;
                        size_t so = ((size_t)(b * 16 + hd) * SEQ + s) * 64 + d;
                        *(float2*)(C + (size_t)which * KV_ELEMS + so) = make_float2(v0, v1);
                        uint32_t hp = bf2(v0, v1);
                        uint32_t lp = bf2(v0 - bf_lo_f(hp), v1 - bf_hi_f(hp));
                        if (which == 0) {
                            *(uint32_t*)(g_kh + so) = hp;
                            *(uint32_t*)(g_kl + so) = lp;
                        } else {
                            size_t vo = ((size_t)(b * 16 + hd) * 64 + d) * SEQ + s;
                            __nv_bfloat16 h0 = __float2bfloat16(v0);
                            __nv_bfloat16 h1 = __float2bfloat16(v1);
                            g_vth[vo] = h0;
                            g_vtl[vo] = __float2bfloat16(v0 - __bfloat162float(h0));
                            g_vth[vo + SEQ] = h1;
                            g_vtl[vo + SEQ] = __float2bfloat16(v1 - __bfloat162float(h1));
                        }
                    }
                }
            }
        }
    }
}

// ---------------------------------------------------------------------------
// Flash attention, split-K over key-blocks of 8 chunks (proven round 16).
// ---------------------------------------------------------------------------
#define AT_ARR 3072
#define AT_STG (4 * AT_ARR)
#define AT_SMEM (2 * AT_STG * 4)

__global__ __launch_bounds__(256, 2)
void attn_mma()
{
    extern __shared__ uint32_t sm[];
    const uint32_t smb = smem_u32(sm);

    const int tid = threadIdx.x;
    const int wid = tid >> 5;
    const int lane = tid & 31;
    const int lq = lane >> 2;
    const int lr = lane & 3;
    const int code = c_tiles[blockIdx.x];
    const int qt = code >> 2;
    const int kb = code & 3;
    const int bh = blockIdx.y;
    const float MX = 20.0f;

    const int c0   = kb * 8;
    const int cnt0 = 2 * qt + 2 - c0;
    const int cnt  = cnt0 < 8 ? cnt0 : 8;
    const int cend = c0 + cnt;

    const int kv_row  = lane & 7;
    const int kv_half = (lane >> 3) & 1;

    const uint4* Qh4 = (const uint4*)g_qh;
    const uint4* Ql4 = (const uint4*)g_ql;
    const uint4* Kh4 = (const uint4*)g_kh;
    const uint4* Kl4 = (const uint4*)g_kl;
    const uint4* Vh4 = (const uint4*)g_vth;
    const uint4* Vl4 = (const uint4*)g_vtl;

    uint32_t qh[4][4], ql[4][4];
    {
        const size_t q0 = ((size_t)bh * SEQ + qt * 128) * 8;
#pragma unroll
        for (int i = 0; i < 4; i++) {
            int e = tid + i * 256;
            int m = e >> 3, seg = e & 7;
            uint4 vh = Qh4[q0 + m * 8 + seg];
            uint4 vl = Ql4[q0 + m * 8 + seg];
            int idx = ((seg >> 1) * 128 + m) * 12 + (seg & 1) * 4;
            sm[idx] = vh.x; sm[idx+1] = vh.y; sm[idx+2] = vh.z; sm[idx+3] = vh.w;
            sm[6144 + idx] = vl.x; sm[6144 + idx+1] = vl.y;
            sm[6144 + idx+2] = vl.z; sm[6144 + idx+3] = vl.w;
        }
        __syncthreads();
#pragma unroll
        for (int ks = 0; ks < 4; ks++) {
            int aidx = (ks * 128 + wid * 16 + lq) * 12 + lr;
            qh[ks][0] = sm[aidx];       qh[ks][1] = sm[aidx + 96];
            qh[ks][2] = sm[aidx + 4];   qh[ks][3] = sm[aidx + 100];
            ql[ks][0] = sm[6144 + aidx];     ql[ks][1] = sm[6144 + aidx + 96];
            ql[ks][2] = sm[6144 + aidx + 4]; ql[ks][3] = sm[6144 + aidx + 100];
        }
        __syncthreads();
    }

#define CPAKV(c, stg)                                                        \
    {                                                                        \
        uint32_t sb = smb + (stg) * (AT_STG * 4);                            \
        int kt0_ = (c) * 64;                                                 \
        _Pragma("unroll")                                                    \
        for (int i = 0; i < 2; i++) {                                        \
            int e = tid + i * 256;                                           \
            int m = e >> 3, seg = e & 7;                                     \
            uint32_t idx = (uint32_t)(((((seg >> 1) * 64 + m) * 12) + (seg & 1) * 4) * 4); \
            size_t ki = ((size_t)bh * SEQ + kt0_ + m) * 8 + seg;             \
            size_t vi = ((size_t)bh * 64 + m) * 256 + (kt0_ >> 3) + seg;     \
            cpa16(sb + idx,               Kh4 + ki);                         \
            cpa16(sb + AT_ARR * 4 + idx,  Kl4 + ki);                         \
            cpa16(sb + AT_ARR * 8 + idx,  Vh4 + vi);                         \
            cpa16(sb + AT_ARR * 12 + idx, Vl4 + vi);                         \
        }                                                                    \
        cpc();                                                               \
    }

    const int gr0 = qt * 128 + wid * 16;

    CPAKV(c0, 0);
    CPAKV(c0 + 1, 1);

    float O[8][4];
#pragma unroll
    for (int nb = 0; nb < 8; nb++)
#pragma unroll
        for (int q = 0; q < 4; q++) O[nb][q] = 0.0f;
    float lsum0 = 0.0f, lsum1 = 0.0f;

#pragma unroll 1
    for (int c = c0; c < cend; c++) {
        const int s = (c - c0) & 1;
        if (c + 1 < cend) cpw<1>(); else cpw<0>();
        __syncthreads();

        const int kt0 = c * 64;
        if (kt0 <= gr0 + 15) {
            const uint32_t kstage = smb + s * (AT_STG * 4);

            float S[8][4];
#pragma unroll
            for (int nb = 0; nb < 8; nb++)
#pragma unroll
                for (int q = 0; q < 4; q++) S[nb][q] = 0.0f;
#pragma unroll
            for (int ks = 0; ks < 4; ks++) {
#pragma unroll
                for (int nb = 0; nb < 8; nb++) {
                    uint32_t kaddr = kstage +
                        (uint32_t)(((ks * 64 + nb * 8 + kv_row) * 12 + kv_half * 4) * 4);
                    uint32_t bh0, bh1, bl0, bl1;
                    ldsm2(bh0, bh1, kaddr);
                    ldsm2(bl0, bl1, kaddr + AT_ARR * 4);
                    mma_bf16(S[nb], qh[ks][0], qh[ks][1], qh[ks][2], qh[ks][3], bh0, bh1);
                    mma_bf16(S[nb], qh[ks][0], qh[ks][1], qh[ks][2], qh[ks][3], bl0, bl1);
                    mma_bf16(S[nb], ql[ks][0], ql[ks][1], ql[ks][2], ql[ks][3], bh0, bh1);
                }
            }
            const int r0 = gr0 + lq, r1 = r0 + 8;
            float p[8][4];
#pragma unroll
            for (int nb = 0; nb < 8; nb++) {
                int cc0 = kt0 + nb * 8 + 2 * lr;
                p[nb][0] = (cc0     <= r0) ? __expf(S[nb][0] - MX) : 0.0f;
                p[nb][1] = (cc0 + 1 <= r0) ? __expf(S[nb][1] - MX) : 0.0f;
                p[nb][2] = (cc0     <= r1) ? __expf(S[nb][2] - MX) : 0.0f;
                p[nb][3] = (cc0 + 1 <= r1) ? __expf(S[nb][3] - MX) : 0.0f;
                lsum0 += p[nb][0] + p[nb][1];
                lsum1 += p[nb][2] + p[nb][3];
            }
#pragma unroll
            for (int ks = 0; ks < 4; ks++) {
                uint32_t ph0 = bf2(p[2*ks][0],   p[2*ks][1]);
                uint32_t ph1 = bf2(p[2*ks][2],   p[2*ks][3]);
                uint32_t ph2 = bf2(p[2*ks+1][0], p[2*ks+1][1]);
                uint32_t ph3 = bf2(p[2*ks+1][2], p[2*ks+1][3]);
                uint32_t pl0 = bf2(p[2*ks][0] - bf_lo_f(ph0),   p[2*ks][1] - bf_hi_f(ph0));
                uint32_t pl1 = bf2(p[2*ks][2] - bf_lo_f(ph1),   p[2*ks][3] - bf_hi_f(ph1));
                uint32_t pl2 = bf2(p[2*ks+1][0] - bf_lo_f(ph2), p[2*ks+1][1] - bf_hi_f(ph2));
                uint32_t pl3 = bf2(p[2*ks+1][2] - bf_lo_f(ph3), p[2*ks+1][3] - bf_hi_f(ph3));
#pragma unroll
                for (int nb = 0; nb < 8; nb++) {
                    uint32_t vaddr = kstage + AT_ARR * 8 +
                        (uint32_t)(((ks * 64 + nb * 8 + kv_row) * 12 + kv_half * 4) * 4);
                    uint32_t vh0, vh1, vl0, vl1;
                    ldsm2(vh0, vh1, vaddr);
                    ldsm2(vl0, vl1, vaddr + AT_ARR * 4);
                    mma_bf16(O[nb], ph0, ph1, ph2, ph3, vh0, vh1);
                    mma_bf16(O[nb], pl0, pl1, pl2, pl3, vh0, vh1);
                    mma_bf16(O[nb], ph0, ph1, ph2, ph3, vl0, vl1);
                }
            }
        }
        __syncthreads();
        if (c + 2 < cend) CPAKV(c + 2, s);
    }
#undef CPAKV

    lsum0 += __shfl_xor_sync(0xFFFFFFFFu, lsum0, 1);
    lsum0 += __shfl_xor_sync(0xFFFFFFFFu, lsum0, 2);
    lsum1 += __shfl_xor_sync(0xFFFFFFFFu, lsum1, 1);
    lsum1 += __shfl_xor_sync(0xFFFFFFFFu, lsum1, 2);

    const int rl0 = wid * 16 + lq, rl1 = rl0 + 8;
    const int slot = (bh * 16 + qt) * 4 + kb;
    float* pb = g_part + (size_t)slot * (128 * 64);
#pragma unroll
    for (int nb = 0; nb < 8; nb++) {
        int col = nb * 8 + 2 * lr;
        *(float2*)(pb + rl0 * 64 + col) = make_float2(O[nb][0], O[nb][1]);
        *(float2*)(pb + rl1 * 64 + col) = make_float2(O[nb][2], O[nb][3]);
    }
    if (lr == 0) {
        g_psum[(size_t)slot * 128 + rl0] = lsum0;
        g_psum[(size_t)slot * 128 + rl1] = lsum1;
    }
}

// ---------------------------------------------------------------------------
// Merge (proven round 16).
// ---------------------------------------------------------------------------
__global__ __launch_bounds__(256)
void merge_kernel()
{
    const int tid = threadIdx.x;
    const int qt  = blockIdx.x;
    const int bh  = blockIdx.y;
    const int b = bh >> 4, h = bh & 15;
    const int r   = tid >> 1;
    const int ch  = (tid & 1) * 32;
    const int nkb = (qt + 4) >> 2;
    const int row = qt * 128 + r;
    const int slot0 = (bh * 16 + qt) * 4;

    float den = g_msum[(size_t)bh * SEQ + row];
#pragma unroll 4
    for (int kb = 0; kb < nkb; kb++)
        den += g_psum[(size_t)(slot0 + kb) * 128 + r];
    const float inv = 1.0f / den;

    const size_t cbase = ((size_t)(b * SEQ + row)) * D_MODEL + h * HEAD_DIM + ch;
#pragma unroll
    for (int j = 0; j < 8; j++) {
        float4 m = *(const float4*)(g_ctx + cbase + j * 4);
#pragma unroll 4
        for (int kb = 0; kb < nkb; kb++) {
            const float* pb = g_part + (size_t)(slot0 + kb) * (128 * 64) + r * 64 + ch + j * 4;
            float4 p = *(const float4*)pb;
            m.x += p.x; m.y += p.y; m.z += p.z; m.w += p.w;
        }
        float o0 = m.x * inv, o1 = m.y * inv, o2 = m.z * inv, o3 = m.w * inv;
        uint32_t h01 = bf2(o0, o1), h23 = bf2(o2, o3);
        uint32_t l01 = bf2(o0 - bf_lo_f(h01), o1 - bf_hi_f(h01));
        uint32_t l23 = bf2(o2 - bf_lo_f(h23), o3 - bf_hi_f(h23));
        *(uint2*)(g_a_hi + cbase + j * 4) = make_uint2(h01, h23);
        *(uint2*)(g_a_lo + cbase + j * 4) = make_uint2(l01, l23);
    }
}

// ---------------------------------------------------------------------------
extern "C" void kernel_launch(void* const* d_in, const int* in_sizes, int n_in,
                              void* d_out, int out_size)
{
    const float* x = 0; const float* pk = 0; const float* pv = 0;
    const float* W_qkv = 0; const float* b_qkv = 0;
    const float* W_out = 0; const float* b_out = 0;
    for (int i = 0; i < n_in; i++) {
        const float* p = (const float*)d_in[i];
        switch (in_sizes[i]) {
            case 4194304:  x = p;      break;
            case 33554432: if (!pk) pk = p; else pv = p; break;
            case 3145728:  W_qkv = p;  break;
            case 3072:     b_qkv = p;  break;
            case 1048576:  W_out = p;  break;
            case 1024:     b_out = p;  break;
            default: break;
        }
    }
    if (!(x && pk && pv && W_qkv && b_qkv && W_out && b_out)) {
        if (n_in < 7) return;
        x     = (const float*)d_in[0];
        pk    = (const float*)d_in[1];
        pv    = (const float*)d_in[2];
        W_qkv = (const float*)d_in[3];
        b_qkv = (const float*)d_in[4];
        W_out = (const float*)d_in[5];
        b_out = (const float*)d_in[6];
    }

    float* out = (float*)d_out;

    static __nv_bfloat16 *s_ah = 0, *s_al = 0, *s_bh = 0, *s_bl = 0, *s_oh = 0, *s_ol = 0;
    static cudaStream_t s1 = 0, s2 = 0;
    static cudaEvent_t eS = 0, e0 = 0, e1 = 0, e2 = 0;
    if (!s_ah) {
        void* p = 0;
        cudaGetSymbolAddress(&p, g_a_hi);  s_ah = (__nv_bfloat16*)p;
        cudaGetSymbolAddress(&p, g_a_lo);  s_al = (__nv_bfloat16*)p;
        cudaGetSymbolAddress(&p, g_bt_hi); s_bh = (__nv_bfloat16*)p;
        cudaGetSymbolAddress(&p, g_bt_lo); s_bl = (__nv_bfloat16*)p;
        cudaGetSymbolAddress(&p, g_bo_hi); s_oh = (__nv_bfloat16*)p;
        cudaGetSymbolAddress(&p, g_bo_lo); s_ol = (__nv_bfloat16*)p;
        cudaFuncSetAttribute((const void*)hgemm_bf<0>,
                             cudaFuncAttributeMaxDynamicSharedMemorySize, HB_SMEM);
        cudaFuncSetAttribute((const void*)hgemm_bf<1>,
                             cudaFuncAttributeMaxDynamicSharedMemorySize, HB_SMEM);
        cudaFuncSetAttribute((const void*)attn_mma,
                             cudaFuncAttributeMaxDynamicSharedMemorySize, AT_SMEM);
        cudaStreamCreateWithFlags(&s1, cudaStreamNonBlocking);
        cudaStreamCreateWithFlags(&s2, cudaStreamNonBlocking);
        cudaEventCreateWithFlags(&eS, cudaEventDisableTiming);
        cudaEventCreateWithFlags(&e0, cudaEventDisableTiming);
        cudaEventCreateWithFlags(&e1, cudaEventDisableTiming);
        cudaEventCreateWithFlags(&e2, cudaEventDisableTiming);
    }

    float* kvbuf = out + OUT_ELEMS;   // [out | k | v] element layout

    // ---- fork s2: W_out prep (independent of everything else) ----
    cudaEventRecord(eS, 0);
    cudaStreamWaitEvent(s2, eS, 0);
    {
        dim3 grid(D_MODEL / 32, D_MODEL / 32);
        split_wt_kernel<<<grid, dim3(32, 8), 0, s2>>>(W_out, s_oh, s_ol, D_MODEL);
    }
    cudaEventRecord(e2, s2);

    // ---- main: prep x + W_qkv, QKV GEMM ----
    split_a_kernel<<<OUT_ELEMS / 1024, 256>>>((const float4*)x, (uint2*)s_ah, (uint2*)s_al);
    {
        dim3 grid(3 * D_MODEL / 32, D_MODEL / 32);
        split_wt_kernel<<<grid, dim3(32, 8)>>>(W_qkv, s_bh, s_bl, 3 * D_MODEL);
    }
    {
        dim3 grid(3 * D_MODEL / 128, M_TOT / 128);
        hgemm_bf<0><<<grid, 256, HB_SMEM>>>((const uint4*)s_ah, (const uint4*)s_al,
                                            (const uint4*)s_bh, (const uint4*)s_bl,
                                            b_qkv, kvbuf);
    }
    cudaEventRecord(e0, 0);

    // ---- fork s1: memattn (overlaps attn_mma on main) ----
    cudaStreamWaitEvent(s1, e0, 0);
    {
        dim3 grid(SEQ / 8, BATCH * N_HEADS);
        memattn_kernel<<<grid, 256, 0, s1>>>(pk, pv);
    }
    cudaEventRecord(e1, s1);

    // ---- main: token flash attention (split-K) ----
    {
        dim3 grid(40, BATCH * N_HEADS);
        attn_mma<<<grid, 256, AT_SMEM>>>();
    }

    // ---- join: merge needs memattn + attn ----
    cudaStreamWaitEvent(0, e1, 0);
    {
        dim3 grid(16, BATCH * N_HEADS);
        merge_kernel<<<grid, 256>>>();
    }

    // ---- join: out GEMM needs merge + W_out prep ----
    cudaStreamWaitEvent(0, e2, 0);
    {
        dim3 grid(D_MODEL / 128, M_TOT / 128);
        hgemm_bf<1><<<grid, 256, HB_SMEM>>>((const uint4*)s_ah, (const uint4*)s_al,
                                            (const uint4*)s_oh, (const uint4*)s_ol,
                                            b_out, out);
    }
}